// round 7
// baseline (speedup 1.0000x reference)
#include <cuda_runtime.h>
#include <math.h>

// ---------------- problem constants ----------------
static const int NTOK   = 8192;   // N
static const int DMODEL = 512;    // D
static const int NHEADS = 8;
static const int DHEAD  = 64;
static const int MLAND  = 256;    // M landmarks
static const int LFOLD  = 32;     // N / M
static const int WPD    = 256;    // weight_params_dim
static const int NEDGE  = 262144; // E
static const int KCONV  = 33;
static const int QKVW   = 3 * NHEADS * DHEAD; // 1536
static const int PITERS = 6;

// ---------------- device scratch (BSS) ----------------
__device__ float g_qkv [NTOK * QKVW];
__device__ float g_ql  [NHEADS * MLAND * DHEAD];
__device__ float g_kl  [NHEADS * MLAND * DHEAD];
__device__ float g_a1  [(long)NHEADS * NTOK * MLAND];
__device__ float g_a2  [NHEADS * MLAND * MLAND];
__device__ float g_a3  [(long)NHEADS * MLAND * NTOK];
__device__ float g_z   [NHEADS * MLAND * MLAND];
__device__ float g_z2  [NHEADS * MLAND * MLAND];
__device__ float g_xz  [NHEADS * MLAND * MLAND];
__device__ float g_t1  [NHEADS * MLAND * MLAND];
__device__ float g_t2  [NHEADS * MLAND * MLAND];
__device__ float g_a3v [NHEADS * MLAND * DHEAD];
__device__ float g_w1  [(long)NHEADS * NTOK * MLAND];
__device__ float g_xh  [NTOK * DMODEL];
__device__ float g_enc [NTOK * DMODEL];
__device__ float g_val [NTOK * DMODEL];
__device__ float g_qe  [NTOK * WPD];
__device__ float g_ke  [NTOK * WPD];
__device__ float g_Araw [NTOK];
__device__ float g_alpha[NTOK];
__device__ unsigned int g_norm[2];

// ---------------- tf32 / ptx helpers ----------------
__device__ __forceinline__ unsigned f2tf(float x) {
    unsigned u;
    asm("cvt.rna.tf32.f32 %0, %1;" : "=r"(u) : "f"(x));
    return u;
}
__device__ __forceinline__ void split_u(unsigned x, unsigned& hi, unsigned& lo) {
    float f = __uint_as_float(x);
    hi = f2tf(f);
    lo = f2tf(f - __uint_as_float(hi));
}
__device__ __forceinline__ void mma8(float* c, const unsigned* a, const unsigned* b) {
    asm volatile(
        "mma.sync.aligned.m16n8k8.row.col.f32.tf32.tf32.f32 "
        "{%0,%1,%2,%3}, {%4,%5,%6,%7}, {%8,%9}, {%0,%1,%2,%3};"
        : "+f"(c[0]), "+f"(c[1]), "+f"(c[2]), "+f"(c[3])
        : "r"(a[0]), "r"(a[1]), "r"(a[2]), "r"(a[3]), "r"(b[0]), "r"(b[1]));
}
__device__ __forceinline__ void ldsm4(unsigned& r0, unsigned& r1, unsigned& r2,
                                      unsigned& r3, unsigned addr) {
    asm volatile("ldmatrix.sync.aligned.m8n8.x4.shared.b16 {%0,%1,%2,%3}, [%4];"
        : "=r"(r0), "=r"(r1), "=r"(r2), "=r"(r3) : "r"(addr));
}
__device__ __forceinline__ unsigned sptr(const void* p) {
    return (unsigned)__cvta_generic_to_shared(p);
}
#define CP16(d, s)  asm volatile("cp.async.ca.shared.global [%0], [%1], 16;" :: "r"(d), "l"(s))
#define CP4(d, s)   asm volatile("cp.async.ca.shared.global [%0], [%1], 4;"  :: "r"(d), "l"(s))
#define CPCOMMIT()  asm volatile("cp.async.commit_group;")
#define CPWAIT1()   asm volatile("cp.async.wait_group 1;")
#define CPWAIT0()   asm volatile("cp.async.wait_group 0;")

// padded physical row index: insert one 16B slot every 8 rows (bank spread)
__device__ __forceinline__ int prp(int r) { return r + (r >> 3); }

static const int SROWS = 144;  // prp(127)=142 < 144
struct StageT { float A[2][2][SROWS][4]; float B[2][2][SROWS][4]; };
static const int NSTAGE = 3;

// =====================================================================
// gemmT2: tf32x3 tensor GEMM, raw-fp32 smem + ldmatrix + cp.async,
// 3-stage pipeline with ONE barrier per k-tile.
// CTA tile 128 x BN x 16, 256 threads (8 warps 4x2), warp tile 32 x BN/2.
// C = alpha * A@op(B) + diag*I [+ addC + bias];  C2 = alpha2*(A@opB) + diag2*I.
// TB: B=[N,K]. !TB: B=[K,N]. kSplit>1: atomicAdd into pre-zeroed C.
// REQUIRES M%128==0, N%BN==0, (K/kSplit)%16==0, 16B-aligned rows.
// =====================================================================
template<bool TB, int BN>
__global__ __launch_bounds__(256, 2)
void gemmT2_k(int M, int N, int K, float alpha,
              const float* __restrict__ A, int lda, long sA,
              const float* __restrict__ B, int ldb, long sB,
              float* __restrict__ C, int ldc, long sC, int kSplit,
              float diag, float* __restrict__ C2, float alpha2, float diag2,
              const float* __restrict__ addC, const float* __restrict__ bias)
{
    constexpr int WNT = BN / 16;  // n-tiles (8 cols each) per warp
    constexpr int NP  = WNT / 2;  // ldmatrix x4 pairs
    constexpr int NB  = (BN == 128) ? 8 : 4; // NT fill elems/thread

    int bz = blockIdx.z;
    int batch = bz / kSplit, ks = bz - batch * kSplit;
    A += (long)batch * sA; B += (long)batch * sB; C += (long)batch * sC;
    if (C2)   C2   += (long)batch * sC;
    if (addC) addC += (long)batch * sC;
    const int chunk = K / kSplit;
    const int k0s = ks * chunk;
    const int T = chunk >> 4;

    const int row0 = blockIdx.y * 128;
    const int col0 = blockIdx.x * BN;
    const int tid  = threadIdx.x;
    const int lane = tid & 31, w = tid >> 5, wr = w >> 1, wc = w & 1;

    extern __shared__ __align__(16) char smraw[];
    StageT* sm = reinterpret_cast<StageT*>(smraw);
    const unsigned stageSz = (unsigned)sizeof(StageT);

    // ---- fill precompute ----
    const int ar = tid >> 1, akt = tid & 1;
    const float* aSrc = A + (long)(row0 + ar) * lda + akt * 8;
    const unsigned aD0 = sptr(&sm[0].A[akt][0][prp(ar)][0]);
    const unsigned aD1 = sptr(&sm[0].A[akt][1][prp(ar)][0]);

    const float* bSrc;
    unsigned bD0 = 0, bD1 = 0;
    unsigned bDst[8];
    if (TB) {
        int bn = tid >> 1, bkt = tid & 1;
        bSrc = B + (long)(col0 + bn) * ldb + bkt * 8;
        bD0 = sptr(&sm[0].B[bkt][0][prp(bn)][0]);
        bD1 = sptr(&sm[0].B[bkt][1][prp(bn)][0]);
    } else {
        int n  = tid & (BN - 1);
        int kb = (tid >> ((BN == 128) ? 7 : 6)) * NB;
        bSrc = B + (long)kb * ldb + col0 + n;
        #pragma unroll
        for (int j = 0; j < NB; j++) {
            int kk = kb + j;
            bDst[j] = sptr(&sm[0].B[kk >> 3][(kk >> 2) & 1][prp(n)][kk & 3]);
        }
    }

    auto fill = [&](int kAbs, int s) {
        unsigned so = s * stageSz;
        CP16(aD0 + so, aSrc + kAbs);
        CP16(aD1 + so, aSrc + kAbs + 4);
        if (TB) {
            CP16(bD0 + so, bSrc + kAbs);
            CP16(bD1 + so, bSrc + kAbs + 4);
        } else {
            #pragma unroll
            for (int j = 0; j < NB; j++)
                CP4(bDst[j] + so, bSrc + (long)(kAbs + j) * ldb);
        }
    };

    // ---- ldmatrix address precompute ----
    const int aRow = wr * 32 + (lane & 15);
    const int aKj  = lane >> 4;
    unsigned aAdr[2][2];
    #pragma unroll
    for (int kt = 0; kt < 2; kt++)
        #pragma unroll
        for (int rt = 0; rt < 2; rt++)
            aAdr[kt][rt] = sptr(&sm[0].A[kt][aKj][prp(aRow + rt * 16)][0]);

    const int bKj  = (lane >> 3) & 1;
    const int bRow = wc * (BN / 2) + ((lane & 7) | ((lane & 16) >> 1));
    unsigned bAdr[2][NP];
    #pragma unroll
    for (int kt = 0; kt < 2; kt++)
        #pragma unroll
        for (int p = 0; p < NP; p++)
            bAdr[kt][p] = sptr(&sm[0].B[kt][bKj][prp(bRow + p * 16)][0]);

    float acc[2][WNT][4];
    #pragma unroll
    for (int i = 0; i < 2; i++)
        #pragma unroll
        for (int j = 0; j < WNT; j++)
            #pragma unroll
            for (int v = 0; v < 4; v++) acc[i][j][v] = 0.f;

    auto compute = [&](int s) {
        unsigned so = s * stageSz;
        #pragma unroll
        for (int kt = 0; kt < 2; kt++) {
            unsigned ah[2][4], al[2][4];
            #pragma unroll
            for (int rt = 0; rt < 2; rt++) {
                unsigned r0, r1, r2, r3;
                ldsm4(r0, r1, r2, r3, aAdr[kt][rt] + so);
                split_u(r0, ah[rt][0], al[rt][0]);
                split_u(r1, ah[rt][1], al[rt][1]);
                split_u(r2, ah[rt][2], al[rt][2]);
                split_u(r3, ah[rt][3], al[rt][3]);
            }
            #pragma unroll
            for (int p = 0; p < NP; p++) {
                unsigned r0, r1, r2, r3;
                ldsm4(r0, r1, r2, r3, bAdr[kt][p] + so);
                unsigned bh0[2], bl0[2], bh1[2], bl1[2];
                split_u(r0, bh0[0], bl0[0]);
                split_u(r1, bh0[1], bl0[1]);
                split_u(r2, bh1[0], bl1[0]);
                split_u(r3, bh1[1], bl1[1]);
                #pragma unroll
                for (int rt = 0; rt < 2; rt++) {
                    mma8(acc[rt][2 * p],     ah[rt], bh0);
                    mma8(acc[rt][2 * p],     al[rt], bh0);
                    mma8(acc[rt][2 * p],     ah[rt], bl0);
                    mma8(acc[rt][2 * p + 1], ah[rt], bh1);
                    mma8(acc[rt][2 * p + 1], al[rt], bh1);
                    mma8(acc[rt][2 * p + 1], ah[rt], bl1);
                }
            }
        }
    };

    // ---- 3-stage pipelined mainloop, one barrier per tile ----
    fill(k0s, 0);
    CPCOMMIT();
    if (T > 1) { fill(k0s + 16, 1); CPCOMMIT(); }
    for (int t = 0; t < T; t++) {
        if (t + 1 < T) CPWAIT1(); else CPWAIT0();
        __syncthreads();
        if (t + 2 < T) {
            fill(k0s + (t + 2) * 16, (t + 2) % NSTAGE);
            CPCOMMIT();
        }
        compute(t % NSTAGE);
    }

    // ---- epilogue ----
    const int g = lane >> 2, tg = lane & 3;
    #pragma unroll
    for (int rt = 0; rt < 2; rt++) {
        #pragma unroll
        for (int n2 = 0; n2 < WNT; n2++) {
            int gr = row0 + wr * 32 + rt * 16 + g;
            int gc = col0 + wc * (BN / 2) + n2 * 8 + tg * 2;
            float* c = acc[rt][n2];
            long i0 = (long)gr * ldc + gc;
            long i1 = i0 + 8 * (long)ldc;
            float v00 = alpha * c[0], v01 = alpha * c[1];
            float v10 = alpha * c[2], v11 = alpha * c[3];
            if (diag != 0.f) {
                if (gr == gc)     v00 += diag;
                if (gr == gc + 1) v01 += diag;
                if (gr + 8 == gc)     v10 += diag;
                if (gr + 8 == gc + 1) v11 += diag;
            }
            if (addC) {
                v00 += addC[i0]; v01 += addC[i0 + 1];
                v10 += addC[i1]; v11 += addC[i1 + 1];
            }
            if (bias) {
                v00 += bias[gc]; v01 += bias[gc + 1];
                v10 += bias[gc]; v11 += bias[gc + 1];
            }
            if (kSplit > 1) {
                atomicAdd(&C[i0], v00); atomicAdd(&C[i0 + 1], v01);
                atomicAdd(&C[i1], v10); atomicAdd(&C[i1 + 1], v11);
            } else {
                C[i0] = v00; C[i0 + 1] = v01;
                C[i1] = v10; C[i1 + 1] = v11;
            }
            if (C2) {
                float w00 = alpha2 * c[0], w01 = alpha2 * c[1];
                float w10 = alpha2 * c[2], w11 = alpha2 * c[3];
                if (gr == gc)     w00 += diag2;
                if (gr == gc + 1) w01 += diag2;
                if (gr + 8 == gc)     w10 += diag2;
                if (gr + 8 == gc + 1) w11 += diag2;
                C2[i0] = w00; C2[i0 + 1] = w01;
                C2[i1] = w10; C2[i1 + 1] = w11;
            }
        }
    }
}

static const int GT_SMEM = NSTAGE * (int)sizeof(StageT);  // 55296 B

static void gemmTC(bool tb, int M, int N, int K, float alpha,
                   const float* A, int lda, long sA,
                   const float* B, int ldb, long sB,
                   float* C, int ldc, long sC, int batch,
                   float diag = 0.f, float* C2 = nullptr,
                   float alpha2 = 0.f, float diag2 = 0.f,
                   const float* addC = nullptr, const float* bias = nullptr)
{
    dim3 g(N / 128, M / 128, batch);
    if (tb) {
        cudaFuncSetAttribute(gemmT2_k<true, 128>,
            cudaFuncAttributeMaxDynamicSharedMemorySize, GT_SMEM);
        gemmT2_k<true, 128><<<g, 256, GT_SMEM>>>(M, N, K, alpha, A, lda, sA,
            B, ldb, sB, C, ldc, sC, 1, diag, C2, alpha2, diag2, addC, bias);
    } else {
        cudaFuncSetAttribute(gemmT2_k<false, 128>,
            cudaFuncAttributeMaxDynamicSharedMemorySize, GT_SMEM);
        gemmT2_k<false, 128><<<g, 256, GT_SMEM>>>(M, N, K, alpha, A, lda, sA,
            B, ldb, sB, C, ldc, sC, 1, diag, C2, alpha2, diag2, addC, bias);
    }
}

static void gemmT64(int M, int K, float alpha,
                    const float* A, int lda, long sA,
                    const float* B, int ldb, long sB,
                    float* C, int ldc, long sC, int batch, int kSplit)
{
    dim3 g(1, M / 128, batch * kSplit);
    cudaFuncSetAttribute(gemmT2_k<false, 64>,
        cudaFuncAttributeMaxDynamicSharedMemorySize, GT_SMEM);
    gemmT2_k<false, 64><<<g, 256, GT_SMEM>>>(M, 64, K, alpha, A, lda, sA,
        B, ldb, sB, C, ldc, sC, kSplit, 0.f, nullptr, 0.f, 0.f, nullptr, nullptr);
}

// ---------------- small kernels ----------------
__global__ void zeros_k(float* a3v, float* Araw, unsigned int* norm)
{
    long i = (long)blockIdx.x * 256 + threadIdx.x;
    if (i < NHEADS * MLAND * DHEAD) a3v[i] = 0.f;
    if (i < NTOK) Araw[i] = 0.f;
    if (i < 2) norm[i] = 0u;
}

__global__ void landmarks_k(const float* __restrict__ qkv,
                            float* __restrict__ ql, float* __restrict__ kl)
{
    int idx = blockIdx.x * blockDim.x + threadIdx.x;
    if (idx >= NHEADS * MLAND * DHEAD) return;
    int d = idx & 63; int j = (idx >> 6) & 255; int h = idx >> 14;
    const float* qp = qkv + (long)(j * LFOLD) * QKVW + h * DHEAD + d;
    const float* kp = qp + NHEADS * DHEAD;
    float sq = 0.f, sk = 0.f;
    #pragma unroll 4
    for (int t = 0; t < LFOLD; t++) {
        sq += qp[(long)t * QKVW];
        sk += kp[(long)t * QKVW];
    }
    ql[idx] = sq * (1.f / LFOLD);
    kl[idx] = sk * (1.f / LFOLD);
}

__global__ __launch_bounds__(256)
void softmax256_k(float* __restrict__ X)
{
    float* x = X + (long)blockIdx.x * 256;
    int tid = threadIdx.x;
    __shared__ float sm[8];
    float v = x[tid];
    float m = v;
    #pragma unroll
    for (int o = 16; o; o >>= 1) m = fmaxf(m, __shfl_xor_sync(0xffffffffu, m, o));
    if ((tid & 31) == 0) sm[tid >> 5] = m;
    __syncthreads();
    m = sm[0];
    #pragma unroll
    for (int i = 1; i < 8; i++) m = fmaxf(m, sm[i]);
    float e = __expf(v - m);
    float s = e;
    #pragma unroll
    for (int o = 16; o; o >>= 1) s += __shfl_xor_sync(0xffffffffu, s, o);
    __syncthreads();
    if ((tid & 31) == 0) sm[tid >> 5] = s;
    __syncthreads();
    s = sm[0];
    #pragma unroll
    for (int i = 1; i < 8; i++) s += sm[i];
    x[tid] = e * (1.f / s);
}

__global__ __launch_bounds__(1024)
void softmax8192_k(float* __restrict__ X)
{
    float* x = X + (long)blockIdx.x * 8192;
    int tid = threadIdx.x;
    __shared__ float sm[32];
    float4 v0 = *(const float4*)(x + tid * 8);
    float4 v1 = *(const float4*)(x + tid * 8 + 4);
    float m = fmaxf(fmaxf(fmaxf(v0.x, v0.y), fmaxf(v0.z, v0.w)),
                    fmaxf(fmaxf(v1.x, v1.y), fmaxf(v1.z, v1.w)));
    #pragma unroll
    for (int o = 16; o; o >>= 1) m = fmaxf(m, __shfl_xor_sync(0xffffffffu, m, o));
    if ((tid & 31) == 0) sm[tid >> 5] = m;
    __syncthreads();
    m = sm[0];
    #pragma unroll
    for (int i = 1; i < 32; i++) m = fmaxf(m, sm[i]);
    float e0 = __expf(v0.x - m), e1 = __expf(v0.y - m);
    float e2 = __expf(v0.z - m), e3 = __expf(v0.w - m);
    float e4 = __expf(v1.x - m), e5 = __expf(v1.y - m);
    float e6 = __expf(v1.z - m), e7 = __expf(v1.w - m);
    float s = ((e0 + e1) + (e2 + e3)) + ((e4 + e5) + (e6 + e7));
    #pragma unroll
    for (int o = 16; o; o >>= 1) s += __shfl_xor_sync(0xffffffffu, s, o);
    __syncthreads();
    if ((tid & 31) == 0) sm[tid >> 5] = s;
    __syncthreads();
    s = sm[0];
    #pragma unroll
    for (int i = 1; i < 32; i++) s += sm[i];
    float inv = 1.f / s;
    *(float4*)(x + tid * 8)     = make_float4(e0 * inv, e1 * inv, e2 * inv, e3 * inv);
    *(float4*)(x + tid * 8 + 4) = make_float4(e4 * inv, e5 * inv, e6 * inv, e7 * inv);
}

__global__ void a2norm_k(const float* __restrict__ a2, unsigned int* norm)
{
    int h = blockIdx.x; int t = threadIdx.x;
    const float* x = a2 + (long)h * MLAND * MLAND;
    float rs = 0.f, cs = 0.f;
    for (int j = 0; j < MLAND; j++) {
        rs += fabsf(x[t * MLAND + j]);
        cs += fabsf(x[j * MLAND + t]);
    }
    __shared__ float s1[8], s2[8];
    for (int o = 16; o; o >>= 1) {
        rs = fmaxf(rs, __shfl_xor_sync(0xffffffffu, rs, o));
        cs = fmaxf(cs, __shfl_xor_sync(0xffffffffu, cs, o));
    }
    if ((t & 31) == 0) { s1[t >> 5] = rs; s2[t >> 5] = cs; }
    __syncthreads();
    if (t == 0) {
        rs = s1[0]; cs = s2[0];
        for (int w = 1; w < 8; w++) { rs = fmaxf(rs, s1[w]); cs = fmaxf(cs, s2[w]); }
        atomicMax(&norm[0], __float_as_uint(rs));
        atomicMax(&norm[1], __float_as_uint(cs));
    }
}

__global__ void zinit_k(const float* __restrict__ a2, float* __restrict__ z,
                        const unsigned int* __restrict__ norm)
{
    long idx = (long)blockIdx.x * 256 + threadIdx.x;
    if (idx >= (long)NHEADS * MLAND * MLAND) return;
    float inv = 1.f / (__uint_as_float(norm[0]) * __uint_as_float(norm[1]));
    int j = idx & 255; int i = (idx >> 8) & 255; long h = idx >> 16;
    z[idx] = a2[h * 65536 + (long)j * 256 + i] * inv;
}

// sliding-window depthwise conv over sequence dim, 8 rows per thread
__global__ __launch_bounds__(256)
void convadd2_k(const float* __restrict__ qkv,
                const float* __restrict__ rker,
                float* __restrict__ xh)
{
    __shared__ float skr[NHEADS * KCONV];
    for (int i = threadIdx.x; i < NHEADS * KCONV; i += 256) skr[i] = rker[i];
    __syncthreads();

    int idx = blockIdx.x * 256 + threadIdx.x;   // 512 cols x 1024 row-groups
    int col = idx & 511;
    int ng  = idx >> 9;
    if (ng >= NTOK / 8) return;
    long n0 = (long)ng * 8;
    const float* kr = skr + (col >> 6) * KCONV;
    const float* v = qkv + 2 * NHEADS * DHEAD + col;

    float win[40];
    #pragma unroll
    for (int j = 0; j < 40; j++) {
        long r = n0 - 16 + j;
        win[j] = (r >= 0 && r < NTOK) ? v[r * QKVW] : 0.f;
    }
    #pragma unroll
    for (int i = 0; i < 8; i++) {
        float s = 0.f;
        #pragma unroll
        for (int t = 0; t < KCONV; t++) s += kr[t] * win[i + t];
        xh[(n0 + i) * DMODEL + col] += s;
    }
}

__global__ void edge_k(const float* __restrict__ qe, const float* __restrict__ ke,
                       const int* __restrict__ rows, const int* __restrict__ cols,
                       const float* __restrict__ vals, float* __restrict__ Araw)
{
    int e = blockIdx.x * (blockDim.x >> 5) + (threadIdx.x >> 5);
    int lane = threadIdx.x & 31;
    if (e >= NEDGE) return;
    int r = rows[e], c = cols[e];
    const float4* qr = (const float4*)(qe + (long)r * WPD);
    const float4* kc = (const float4*)(ke + (long)c * WPD);
    float s = 0.f;
    #pragma unroll
    for (int i = lane; i < WPD / 4; i += 32) {
        float4 a = qr[i], b = kc[i];
        s += a.x * b.x + a.y * b.y + a.z * b.z + a.w * b.w;
    }
    for (int o = 16; o; o >>= 1) s += __shfl_xor_sync(0xffffffffu, s, o);
    if (lane == 0) atomicAdd(&Araw[r], s * 0.0625f * vals[e]);
}

__global__ void softmax_all_k(const float* __restrict__ A, float* __restrict__ alpha, int n)
{
    __shared__ float sm[32];
    int tid = threadIdx.x; // 1024
    float m = -1e30f;
    for (int i = tid; i < n; i += 1024) m = fmaxf(m, A[i]);
    for (int o = 16; o; o >>= 1) m = fmaxf(m, __shfl_xor_sync(0xffffffffu, m, o));
    if ((tid & 31) == 0) sm[tid >> 5] = m;
    __syncthreads();
    if (tid == 0) { float bm = sm[0]; for (int w = 1; w < 32; w++) bm = fmaxf(bm, sm[w]); sm[0] = bm; }
    __syncthreads();
    m = sm[0];
    __syncthreads();
    float s = 0.f;
    for (int i = tid; i < n; i += 1024) s += __expf(A[i] - m);
    for (int o = 16; o; o >>= 1) s += __shfl_xor_sync(0xffffffffu, s, o);
    if ((tid & 31) == 0) sm[tid >> 5] = s;
    __syncthreads();
    if (tid == 0) { float bs = 0.f; for (int w = 0; w < 32; w++) bs += sm[w]; sm[0] = bs; }
    __syncthreads();
    float inv = 1.f / sm[0];
    for (int i = tid; i < n; i += 1024) alpha[i] = __expf(A[i] - m) * inv;
}

__global__ void final_k(const float* __restrict__ val, const float* __restrict__ wvb,
                        const float* __restrict__ alpha, const float* __restrict__ enc,
                        const float* __restrict__ Araw, float* __restrict__ out)
{
    long idx = (long)blockIdx.x * 256 + threadIdx.x;
    long total = (long)NTOK * DMODEL;
    if (idx < total) {
        int col = idx & 511; long n = idx >> 9;
        float v = val[idx] + wvb[col];
        float xl = alpha[n] * v;
        float w = 1.f / (1.f + __expf(xl)); // sigmoid(-xl)
        float sq = w * w;
        float e = enc[idx];
        out[idx] = xl * 2.f * sq + 2.f * e * (1.f - sq);
    }
    if (idx < NTOK) out[total + idx] = Araw[idx];
}

// ---------------- driver ----------------
extern "C" void kernel_launch(void* const* d_in, const int* in_sizes, int n_in,
                              void* d_out, int out_size)
{
    const float* dense  = (const float*)d_in[0];
    const int*   arows  = (const int*)  d_in[1];
    const int*   acols  = (const int*)  d_in[2];
    const float* avals  = (const float*)d_in[3];
    const float* wq     = (const float*)d_in[4];
    const float* wk     = (const float*)d_in[5];
    const float* w_qkv  = (const float*)d_in[6];
    const float* w_out  = (const float*)d_in[7];
    const float* b_out  = (const float*)d_in[8];
    const float* rker   = (const float*)d_in[9];
    const float* wv_w   = (const float*)d_in[10];
    const float* wv_b   = (const float*)d_in[11];
    float* out = (float*)d_out;

    float *qkv, *ql, *kl, *a1, *a2, *a3, *z, *z2, *xz, *t1, *t2, *a3v, *w1;
    float *xh, *enc, *val, *qe, *ke, *Araw, *alpha;
    unsigned int* norm;
    cudaGetSymbolAddress((void**)&qkv, g_qkv);
    cudaGetSymbolAddress((void**)&ql,  g_ql);
    cudaGetSymbolAddress((void**)&kl,  g_kl);
    cudaGetSymbolAddress((void**)&a1,  g_a1);
    cudaGetSymbolAddress((void**)&a2,  g_a2);
    cudaGetSymbolAddress((void**)&a3,  g_a3);
    cudaGetSymbolAddress((void**)&z,   g_z);
    cudaGetSymbolAddress((void**)&z2,  g_z2);
    cudaGetSymbolAddress((void**)&xz,  g_xz);
    cudaGetSymbolAddress((void**)&t1,  g_t1);
    cudaGetSymbolAddress((void**)&t2,  g_t2);
    cudaGetSymbolAddress((void**)&a3v, g_a3v);
    cudaGetSymbolAddress((void**)&w1,  g_w1);
    cudaGetSymbolAddress((void**)&xh,  g_xh);
    cudaGetSymbolAddress((void**)&enc, g_enc);
    cudaGetSymbolAddress((void**)&val, g_val);
    cudaGetSymbolAddress((void**)&qe,  g_qe);
    cudaGetSymbolAddress((void**)&ke,  g_ke);
    cudaGetSymbolAddress((void**)&Araw, g_Araw);
    cudaGetSymbolAddress((void**)&alpha, g_alpha);
    cudaGetSymbolAddress((void**)&norm, g_norm);

    const float qscale = 0.125f; // DIM_HEAD^-0.5
    const long  smm    = (long)MLAND * MLAND;

    // 0. zero scratch (a3v accum, Araw accum, norm)
    zeros_k<<<(NHEADS * MLAND * DHEAD + 255) / 256, 256>>>(a3v, Araw, norm);

    // 1. qkv = dense @ w_qkv^T  [8192,1536]
    gemmTC(true, NTOK, QKVW, DMODEL, 1.f, dense, DMODEL, 0, w_qkv, DMODEL, 0,
           qkv, QKVW, 0, 1);

    // 2. landmarks
    landmarks_k<<<(NHEADS * MLAND * DHEAD + 255) / 256, 256>>>(qkv, ql, kl);

    // 3. a1 = softmax(scale * q @ k_l^T)   [h,8192,256]
    gemmTC(true, NTOK, MLAND, DHEAD, qscale,
           qkv, QKVW, DHEAD, kl, DHEAD, (long)MLAND * DHEAD,
           a1, MLAND, (long)NTOK * MLAND, NHEADS);
    softmax256_k<<<NHEADS * NTOK, 256>>>(a1);

    // 4. a2 = softmax(scale * q_l @ k_l^T) [h,256,256]
    gemmTC(true, MLAND, MLAND, DHEAD, qscale,
           ql, DHEAD, (long)MLAND * DHEAD, kl, DHEAD, (long)MLAND * DHEAD,
           a2, MLAND, smm, NHEADS);
    softmax256_k<<<NHEADS * MLAND, 256>>>(a2);

    // 5. pinv init
    a2norm_k<<<NHEADS, 256>>>(a2, norm);
    zinit_k<<<(int)((NHEADS * smm + 255) / 256), 256>>>(a2, z, norm);

    // 6. pinv iterations (tensor path, fused diag epilogues)
    float* zin = z; float* zout = z2;
    for (int it = 0; it < PITERS; it++) {
        // xz = a2@zin ; t1 = 7I - xz
        gemmTC(false, MLAND, MLAND, MLAND, 1.f, a2, MLAND, smm, zin, MLAND, smm,
               xz, MLAND, smm, NHEADS, 0.f, t1, -1.f, 7.f);
        // t2 = 15I - xz@t1
        gemmTC(false, MLAND, MLAND, MLAND, -1.f, xz, MLAND, smm, t1, MLAND, smm,
               t2, MLAND, smm, NHEADS, 15.f);
        // t1 = 13I - xz@t2
        gemmTC(false, MLAND, MLAND, MLAND, -1.f, xz, MLAND, smm, t2, MLAND, smm,
               t1, MLAND, smm, NHEADS, 13.f);
        // zout = 0.25 * zin@t1
        gemmTC(false, MLAND, MLAND, MLAND, 0.25f, zin, MLAND, smm, t1, MLAND, smm,
               zout, MLAND, smm, NHEADS);
        float* tmp = zin; zin = zout; zout = tmp;
    }
    float* zfin = zin;

    // 7. a3 = softmax(scale * q_l @ k^T)  [h,256,8192]
    gemmTC(true, MLAND, NTOK, DHEAD, qscale,
           ql, DHEAD, (long)MLAND * DHEAD,
           qkv + NHEADS * DHEAD, QKVW, DHEAD,
           a3, NTOK, (long)MLAND * NTOK, NHEADS);
    softmax8192_k<<<NHEADS * MLAND, 1024>>>(a3);

    // 8. a3v = a3 @ v  [h,256,64]  (split-K 16, atomic; pre-zeroed)
    gemmT64(MLAND, NTOK, 1.f,
            a3, NTOK, (long)MLAND * NTOK,
            qkv + 2 * NHEADS * DHEAD, QKVW, DHEAD,
            a3v, DHEAD, (long)MLAND * DHEAD, NHEADS, 16);

    // 9. w1 = a1 @ zfin  [h,8192,256]
    gemmTC(false, NTOK, MLAND, MLAND, 1.f,
           a1, MLAND, (long)NTOK * MLAND, zfin, MLAND, smm,
           w1, MLAND, (long)NTOK * MLAND, NHEADS);

    // 10. xh[n, h*64:+64] = w1 @ a3v
    gemmT64(NTOK, MLAND, 1.f,
            w1, MLAND, (long)NTOK * MLAND,
            a3v, DHEAD, (long)MLAND * DHEAD,
            xh, DMODEL, DHEAD, NHEADS, 1);

    // 11. residual depthwise conv on v, added into xh
    convadd2_k<<<(NTOK / 8) * DMODEL / 256, 256>>>(qkv, rker, xh);

    // 12. enc = xh @ w_out^T + b_out + dense  (fused epilogue)
    gemmTC(true, NTOK, DMODEL, DMODEL, 1.f, xh, DMODEL, 0, w_out, DMODEL, 0,
           enc, DMODEL, 0, 1, 0.f, nullptr, 0.f, 0.f, dense, b_out);

    // 13. qe = enc @ wq ; ke = enc @ wk
    gemmTC(false, NTOK, WPD, DMODEL, 1.f, enc, DMODEL, 0, wq, WPD, 0, qe, WPD, 0, 1);
    gemmTC(false, NTOK, WPD, DMODEL, 1.f, enc, DMODEL, 0, wk, WPD, 0, ke, WPD, 0, 1);

    // 14. edge scores -> segment sum (Araw pre-zeroed)
    edge_k<<<(NEDGE + 7) / 8, 256>>>(qe, ke, arows, acols, avals, Araw);

    // 15. alpha = softmax(A_raw) over all N
    softmax_all_k<<<1, 1024>>>(Araw, alpha, NTOK);

    // 16. value = dense @ wv_w^T
    gemmTC(true, NTOK, DMODEL, DMODEL, 1.f, dense, DMODEL, 0, wv_w, DMODEL, 0,
           val, DMODEL, 0, 1);

    // 17. final gated blend + A_raw copy
    final_k<<<(int)(((long)NTOK * DMODEL + 255) / 256), 256>>>(val, wv_b, alpha, enc, Araw, out);
}

// round 8
// speedup vs baseline: 1.1918x; 1.1918x over previous
#include <cuda_runtime.h>
#include <math.h>

// ---------------- problem constants ----------------
static const int NTOK   = 8192;   // N
static const int DMODEL = 512;    // D
static const int NHEADS = 8;
static const int DHEAD  = 64;
static const int MLAND  = 256;    // M landmarks
static const int LFOLD  = 32;     // N / M
static const int WPD    = 256;    // weight_params_dim
static const int NEDGE  = 262144; // E
static const int KCONV  = 33;
static const int QKVW   = 3 * NHEADS * DHEAD; // 1536
static const int PITERS = 6;

// ---------------- device scratch (BSS) ----------------
__device__ float g_qkv [NTOK * QKVW];
__device__ float g_ql  [NHEADS * MLAND * DHEAD];
__device__ float g_kl  [NHEADS * MLAND * DHEAD];
__device__ float g_a1  [(long)NHEADS * NTOK * MLAND];
__device__ float g_a2  [NHEADS * MLAND * MLAND];
__device__ float g_a3  [(long)NHEADS * MLAND * NTOK];
__device__ float g_z   [NHEADS * MLAND * MLAND];
__device__ float g_z2  [NHEADS * MLAND * MLAND];
__device__ float g_xz  [NHEADS * MLAND * MLAND];
__device__ float g_t1  [NHEADS * MLAND * MLAND];
__device__ float g_t2  [NHEADS * MLAND * MLAND];
__device__ float g_a3v [NHEADS * MLAND * DHEAD];
__device__ float g_w1  [(long)NHEADS * NTOK * MLAND];
__device__ float g_xh  [NTOK * DMODEL];
__device__ float g_enc [NTOK * DMODEL];
__device__ float g_val [NTOK * DMODEL];
__device__ float g_qe  [NTOK * WPD];
__device__ float g_ke  [NTOK * WPD];
__device__ float g_Araw [NTOK];
__device__ float g_alpha[NTOK];
__device__ unsigned int g_norm[2];

// ---------------- tf32 / ptx helpers ----------------
__device__ __forceinline__ unsigned f2tf(float x) {
    unsigned u;
    asm("cvt.rna.tf32.f32 %0, %1;" : "=r"(u) : "f"(x));
    return u;
}
__device__ __forceinline__ void split_u(unsigned x, unsigned& hi, unsigned& lo) {
    float f = __uint_as_float(x);
    hi = f2tf(f);
    lo = f2tf(f - __uint_as_float(hi));
}
__device__ __forceinline__ void mma8(float* c, const unsigned* a, const unsigned* b) {
    asm volatile(
        "mma.sync.aligned.m16n8k8.row.col.f32.tf32.tf32.f32 "
        "{%0,%1,%2,%3}, {%4,%5,%6,%7}, {%8,%9}, {%0,%1,%2,%3};"
        : "+f"(c[0]), "+f"(c[1]), "+f"(c[2]), "+f"(c[3])
        : "r"(a[0]), "r"(a[1]), "r"(a[2]), "r"(a[3]), "r"(b[0]), "r"(b[1]));
}
__device__ __forceinline__ void ldsm4(unsigned& r0, unsigned& r1, unsigned& r2,
                                      unsigned& r3, unsigned addr) {
    asm volatile("ldmatrix.sync.aligned.m8n8.x4.shared.b16 {%0,%1,%2,%3}, [%4];"
        : "=r"(r0), "=r"(r1), "=r"(r2), "=r"(r3) : "r"(addr));
}
__device__ __forceinline__ unsigned sptr(const void* p) {
    return (unsigned)__cvta_generic_to_shared(p);
}
#define CP16(d, s)  asm volatile("cp.async.ca.shared.global [%0], [%1], 16;" :: "r"(d), "l"(s))
#define CP4(d, s)   asm volatile("cp.async.ca.shared.global [%0], [%1], 4;"  :: "r"(d), "l"(s))
#define CPCOMMIT()  asm volatile("cp.async.commit_group;")
#define CPWAIT1()   asm volatile("cp.async.wait_group 1;")
#define CPWAIT0()   asm volatile("cp.async.wait_group 0;")

// padded physical row index: insert one 16B slot every 8 rows (bank spread)
__device__ __forceinline__ int prp(int r) { return r + (r >> 3); }

static const int SROWS = 144;  // prp(127)=142 < 144
struct StageT { float A[2][2][SROWS][4]; float B[2][2][SROWS][4]; };
static const int NSTAGE = 3;

// =====================================================================
// gemmT2: tf32x3 tensor GEMM, raw-fp32 smem + ldmatrix + cp.async,
// 3-stage pipeline with ONE barrier per k-tile.
// CTA tile 128 x BN x 16, 256 threads (8 warps 4x2), warp tile 32 x BN/2.
// C = alpha * A@op(B) [+ addC + bias];  TB: B=[N,K]. !TB: B=[K,N].
// kSplit>1: atomicAdd into pre-zeroed C.
// REQUIRES M%128==0, N%BN==0, (K/kSplit)%16==0, 16B-aligned rows.
// =====================================================================
template<bool TB, int BN>
__global__ __launch_bounds__(256, 2)
void gemmT2_k(int M, int N, int K, float alpha,
              const float* __restrict__ A, int lda, long sA,
              const float* __restrict__ B, int ldb, long sB,
              float* __restrict__ C, int ldc, long sC, int kSplit,
              const float* __restrict__ addC, const float* __restrict__ bias)
{
    constexpr int WNT = BN / 16;  // n-tiles (8 cols each) per warp
    constexpr int NP  = WNT / 2;  // ldmatrix x4 pairs
    constexpr int NB  = (BN == 128) ? 8 : 4; // NT fill elems/thread

    int bz = blockIdx.z;
    int batch = bz / kSplit, ks = bz - batch * kSplit;
    A += (long)batch * sA; B += (long)batch * sB; C += (long)batch * sC;
    if (addC) addC += (long)batch * sC;
    const int chunk = K / kSplit;
    const int k0s = ks * chunk;
    const int T = chunk >> 4;

    const int row0 = blockIdx.y * 128;
    const int col0 = blockIdx.x * BN;
    const int tid  = threadIdx.x;
    const int lane = tid & 31, w = tid >> 5, wr = w >> 1, wc = w & 1;

    extern __shared__ __align__(16) char smraw[];
    StageT* sm = reinterpret_cast<StageT*>(smraw);
    const unsigned stageSz = (unsigned)sizeof(StageT);

    // ---- fill precompute ----
    const int ar = tid >> 1, akt = tid & 1;
    const float* aSrc = A + (long)(row0 + ar) * lda + akt * 8;
    const unsigned aD0 = sptr(&sm[0].A[akt][0][prp(ar)][0]);
    const unsigned aD1 = sptr(&sm[0].A[akt][1][prp(ar)][0]);

    const float* bSrc;
    unsigned bD0 = 0, bD1 = 0;
    unsigned bDst[8];
    if (TB) {
        int bn = tid >> 1, bkt = tid & 1;
        bSrc = B + (long)(col0 + bn) * ldb + bkt * 8;
        bD0 = sptr(&sm[0].B[bkt][0][prp(bn)][0]);
        bD1 = sptr(&sm[0].B[bkt][1][prp(bn)][0]);
    } else {
        int n  = tid & (BN - 1);
        int kb = (tid >> ((BN == 128) ? 7 : 6)) * NB;
        bSrc = B + (long)kb * ldb + col0 + n;
        #pragma unroll
        for (int j = 0; j < NB; j++) {
            int kk = kb + j;
            bDst[j] = sptr(&sm[0].B[kk >> 3][(kk >> 2) & 1][prp(n)][kk & 3]);
        }
    }

    auto fill = [&](int kAbs, int s) {
        unsigned so = s * stageSz;
        CP16(aD0 + so, aSrc + kAbs);
        CP16(aD1 + so, aSrc + kAbs + 4);
        if (TB) {
            CP16(bD0 + so, bSrc + kAbs);
            CP16(bD1 + so, bSrc + kAbs + 4);
        } else {
            #pragma unroll
            for (int j = 0; j < NB; j++)
                CP4(bDst[j] + so, bSrc + (long)(kAbs + j) * ldb);
        }
    };

    // ---- ldmatrix address precompute ----
    const int aRow = wr * 32 + (lane & 15);
    const int aKj  = lane >> 4;
    unsigned aAdr[2][2];
    #pragma unroll
    for (int kt = 0; kt < 2; kt++)
        #pragma unroll
        for (int rt = 0; rt < 2; rt++)
            aAdr[kt][rt] = sptr(&sm[0].A[kt][aKj][prp(aRow + rt * 16)][0]);

    const int bKj  = (lane >> 3) & 1;
    const int bRow = wc * (BN / 2) + ((lane & 7) | ((lane & 16) >> 1));
    unsigned bAdr[2][NP];
    #pragma unroll
    for (int kt = 0; kt < 2; kt++)
        #pragma unroll
        for (int p = 0; p < NP; p++)
            bAdr[kt][p] = sptr(&sm[0].B[kt][bKj][prp(bRow + p * 16)][0]);

    float acc[2][WNT][4];
    #pragma unroll
    for (int i = 0; i < 2; i++)
        #pragma unroll
        for (int j = 0; j < WNT; j++)
            #pragma unroll
            for (int v = 0; v < 4; v++) acc[i][j][v] = 0.f;

    auto compute = [&](int s) {
        unsigned so = s * stageSz;
        #pragma unroll
        for (int kt = 0; kt < 2; kt++) {
            unsigned ah[2][4], al[2][4];
            #pragma unroll
            for (int rt = 0; rt < 2; rt++) {
                unsigned r0, r1, r2, r3;
                ldsm4(r0, r1, r2, r3, aAdr[kt][rt] + so);
                split_u(r0, ah[rt][0], al[rt][0]);
                split_u(r1, ah[rt][1], al[rt][1]);
                split_u(r2, ah[rt][2], al[rt][2]);
                split_u(r3, ah[rt][3], al[rt][3]);
            }
            #pragma unroll
            for (int p = 0; p < NP; p++) {
                unsigned r0, r1, r2, r3;
                ldsm4(r0, r1, r2, r3, bAdr[kt][p] + so);
                unsigned bh0[2], bl0[2], bh1[2], bl1[2];
                split_u(r0, bh0[0], bl0[0]);
                split_u(r1, bh0[1], bl0[1]);
                split_u(r2, bh1[0], bl1[0]);
                split_u(r3, bh1[1], bl1[1]);
                #pragma unroll
                for (int rt = 0; rt < 2; rt++) {
                    mma8(acc[rt][2 * p],     ah[rt], bh0);
                    mma8(acc[rt][2 * p],     al[rt], bh0);
                    mma8(acc[rt][2 * p],     ah[rt], bl0);
                    mma8(acc[rt][2 * p + 1], ah[rt], bh1);
                    mma8(acc[rt][2 * p + 1], al[rt], bh1);
                    mma8(acc[rt][2 * p + 1], ah[rt], bl1);
                }
            }
        }
    };

    // ---- 3-stage pipelined mainloop, one barrier per tile ----
    fill(k0s, 0);
    CPCOMMIT();
    if (T > 1) { fill(k0s + 16, 1); CPCOMMIT(); }
    for (int t = 0; t < T; t++) {
        if (t + 1 < T) CPWAIT1(); else CPWAIT0();
        __syncthreads();
        if (t + 2 < T) {
            fill(k0s + (t + 2) * 16, (t + 2) % NSTAGE);
            CPCOMMIT();
        }
        compute(t % NSTAGE);
    }

    // ---- epilogue ----
    const int g = lane >> 2, tg = lane & 3;
    #pragma unroll
    for (int rt = 0; rt < 2; rt++) {
        #pragma unroll
        for (int n2 = 0; n2 < WNT; n2++) {
            int gr = row0 + wr * 32 + rt * 16 + g;
            int gc = col0 + wc * (BN / 2) + n2 * 8 + tg * 2;
            float* c = acc[rt][n2];
            long i0 = (long)gr * ldc + gc;
            long i1 = i0 + 8 * (long)ldc;
            float v00 = alpha * c[0], v01 = alpha * c[1];
            float v10 = alpha * c[2], v11 = alpha * c[3];
            if (addC) {
                v00 += addC[i0]; v01 += addC[i0 + 1];
                v10 += addC[i1]; v11 += addC[i1 + 1];
            }
            if (bias) {
                v00 += bias[gc]; v01 += bias[gc + 1];
                v10 += bias[gc]; v11 += bias[gc + 1];
            }
            if (kSplit > 1) {
                atomicAdd(&C[i0], v00); atomicAdd(&C[i0 + 1], v01);
                atomicAdd(&C[i1], v10); atomicAdd(&C[i1 + 1], v11);
            } else {
                C[i0] = v00; C[i0 + 1] = v01;
                C[i1] = v10; C[i1 + 1] = v11;
            }
        }
    }
}

static const int GT_SMEM = NSTAGE * (int)sizeof(StageT);  // 55296 B

static void gemmTC(bool tb, int M, int N, int K, float alpha,
                   const float* A, int lda, long sA,
                   const float* B, int ldb, long sB,
                   float* C, int ldc, long sC, int batch,
                   const float* addC = nullptr, const float* bias = nullptr)
{
    dim3 g(N / 128, M / 128, batch);
    if (tb) {
        cudaFuncSetAttribute(gemmT2_k<true, 128>,
            cudaFuncAttributeMaxDynamicSharedMemorySize, GT_SMEM);
        gemmT2_k<true, 128><<<g, 256, GT_SMEM>>>(M, N, K, alpha, A, lda, sA,
            B, ldb, sB, C, ldc, sC, 1, addC, bias);
    } else {
        cudaFuncSetAttribute(gemmT2_k<false, 128>,
            cudaFuncAttributeMaxDynamicSharedMemorySize, GT_SMEM);
        gemmT2_k<false, 128><<<g, 256, GT_SMEM>>>(M, N, K, alpha, A, lda, sA,
            B, ldb, sB, C, ldc, sC, 1, addC, bias);
    }
}

static void gemmT64(int M, int K, float alpha,
                    const float* A, int lda, long sA,
                    const float* B, int ldb, long sB,
                    float* C, int ldc, long sC, int batch, int kSplit)
{
    dim3 g(1, M / 128, batch * kSplit);
    cudaFuncSetAttribute(gemmT2_k<false, 64>,
        cudaFuncAttributeMaxDynamicSharedMemorySize, GT_SMEM);
    gemmT2_k<false, 64><<<g, 256, GT_SMEM>>>(M, 64, K, alpha, A, lda, sA,
        B, ldb, sB, C, ldc, sC, kSplit, nullptr, nullptr);
}

// =====================================================================
// gemm64ep: fp32 SIMT 256x256x256 batched GEMM (pinv), NT, 64x64 tile,
// fused epilogue:  C = alpha*(A@B) + diag*I,  optional C2 likewise.
// (measured-good in R6; 128 CTAs/launch)
// =====================================================================
__global__ __launch_bounds__(256)
void gemm64ep_k(float alpha, float diag,
                const float* __restrict__ A, const float* __restrict__ B,
                float* __restrict__ C,
                float alpha2, float diag2, float* __restrict__ C2)
{
    const long sb = (long)MLAND * MLAND;
    A += blockIdx.z * sb;
    B += blockIdx.z * sb;
    C += blockIdx.z * sb;
    if (C2) C2 += blockIdx.z * sb;

    __shared__ float As[64 * 17];
    __shared__ float Bs[16 * 64];

    int tid = threadIdx.x;
    int row0 = blockIdx.y * 64;
    int col0 = blockIdx.x * 64;
    int tx = tid & 15, ty = tid >> 4;

    float acc[4][4] = {};

    for (int kk = 0; kk < 256; kk += 16) {
        #pragma unroll
        for (int i = 0; i < 4; i++) {
            int e = tid + i * 256;
            int r = e >> 4, c = e & 15;
            As[r * 17 + c] = A[(long)(row0 + r) * 256 + kk + c];
        }
        #pragma unroll
        for (int i = 0; i < 4; i++) {
            int e = tid + i * 256;
            int c = e >> 6, n = e & 63;
            Bs[c * 64 + n] = B[(long)(kk + c) * 256 + col0 + n];
        }
        __syncthreads();
        #pragma unroll
        for (int c = 0; c < 16; c++) {
            float a[4], b[4];
            #pragma unroll
            for (int i = 0; i < 4; i++) a[i] = As[(ty * 4 + i) * 17 + c];
            #pragma unroll
            for (int j = 0; j < 4; j++) b[j] = Bs[c * 64 + tx * 4 + j];
            #pragma unroll
            for (int i = 0; i < 4; i++)
                #pragma unroll
                for (int j = 0; j < 4; j++)
                    acc[i][j] = fmaf(a[i], b[j], acc[i][j]);
        }
        __syncthreads();
    }
    #pragma unroll
    for (int i = 0; i < 4; i++) {
        int gr = row0 + ty * 4 + i;
        #pragma unroll
        for (int j = 0; j < 4; j++) {
            int gc = col0 + tx * 4 + j;
            float d = (gr == gc) ? 1.f : 0.f;
            C[(long)gr * 256 + gc] = alpha * acc[i][j] + diag * d;
            if (C2) C2[(long)gr * 256 + gc] = alpha2 * acc[i][j] + diag2 * d;
        }
    }
}

// ---------------- small kernels ----------------
__global__ void zeros_k(float* a3v, float* Araw, unsigned int* norm)
{
    long i = (long)blockIdx.x * 256 + threadIdx.x;
    if (i < NHEADS * MLAND * DHEAD) a3v[i] = 0.f;
    if (i < NTOK) Araw[i] = 0.f;
    if (i < 2) norm[i] = 0u;
}

__global__ void landmarks_k(const float* __restrict__ qkv,
                            float* __restrict__ ql, float* __restrict__ kl)
{
    int idx = blockIdx.x * blockDim.x + threadIdx.x;
    if (idx >= NHEADS * MLAND * DHEAD) return;
    int d = idx & 63; int j = (idx >> 6) & 255; int h = idx >> 14;
    const float* qp = qkv + (long)(j * LFOLD) * QKVW + h * DHEAD + d;
    const float* kp = qp + NHEADS * DHEAD;
    float sq = 0.f, sk = 0.f;
    #pragma unroll 4
    for (int t = 0; t < LFOLD; t++) {
        sq += qp[(long)t * QKVW];
        sk += kp[(long)t * QKVW];
    }
    ql[idx] = sq * (1.f / LFOLD);
    kl[idx] = sk * (1.f / LFOLD);
}

__global__ __launch_bounds__(256)
void softmax256_k(float* __restrict__ X)
{
    float* x = X + (long)blockIdx.x * 256;
    int tid = threadIdx.x;
    __shared__ float sm[8];
    float v = x[tid];
    float m = v;
    #pragma unroll
    for (int o = 16; o; o >>= 1) m = fmaxf(m, __shfl_xor_sync(0xffffffffu, m, o));
    if ((tid & 31) == 0) sm[tid >> 5] = m;
    __syncthreads();
    m = sm[0];
    #pragma unroll
    for (int i = 1; i < 8; i++) m = fmaxf(m, sm[i]);
    float e = __expf(v - m);
    float s = e;
    #pragma unroll
    for (int o = 16; o; o >>= 1) s += __shfl_xor_sync(0xffffffffu, s, o);
    __syncthreads();
    if ((tid & 31) == 0) sm[tid >> 5] = s;
    __syncthreads();
    s = sm[0];
    #pragma unroll
    for (int i = 1; i < 8; i++) s += sm[i];
    x[tid] = e * (1.f / s);
}

__global__ __launch_bounds__(1024)
void softmax8192_k(float* __restrict__ X)
{
    float* x = X + (long)blockIdx.x * 8192;
    int tid = threadIdx.x;
    __shared__ float sm[32];
    float4 v0 = *(const float4*)(x + tid * 8);
    float4 v1 = *(const float4*)(x + tid * 8 + 4);
    float m = fmaxf(fmaxf(fmaxf(v0.x, v0.y), fmaxf(v0.z, v0.w)),
                    fmaxf(fmaxf(v1.x, v1.y), fmaxf(v1.z, v1.w)));
    #pragma unroll
    for (int o = 16; o; o >>= 1) m = fmaxf(m, __shfl_xor_sync(0xffffffffu, m, o));
    if ((tid & 31) == 0) sm[tid >> 5] = m;
    __syncthreads();
    m = sm[0];
    #pragma unroll
    for (int i = 1; i < 32; i++) m = fmaxf(m, sm[i]);
    float e0 = __expf(v0.x - m), e1 = __expf(v0.y - m);
    float e2 = __expf(v0.z - m), e3 = __expf(v0.w - m);
    float e4 = __expf(v1.x - m), e5 = __expf(v1.y - m);
    float e6 = __expf(v1.z - m), e7 = __expf(v1.w - m);
    float s = ((e0 + e1) + (e2 + e3)) + ((e4 + e5) + (e6 + e7));
    #pragma unroll
    for (int o = 16; o; o >>= 1) s += __shfl_xor_sync(0xffffffffu, s, o);
    __syncthreads();
    if ((tid & 31) == 0) sm[tid >> 5] = s;
    __syncthreads();
    s = sm[0];
    #pragma unroll
    for (int i = 1; i < 32; i++) s += sm[i];
    float inv = 1.f / s;
    *(float4*)(x + tid * 8)     = make_float4(e0 * inv, e1 * inv, e2 * inv, e3 * inv);
    *(float4*)(x + tid * 8 + 4) = make_float4(e4 * inv, e5 * inv, e6 * inv, e7 * inv);
}

__global__ void a2norm_k(const float* __restrict__ a2, unsigned int* norm)
{
    int h = blockIdx.x; int t = threadIdx.x;
    const float* x = a2 + (long)h * MLAND * MLAND;
    float rs = 0.f, cs = 0.f;
    for (int j = 0; j < MLAND; j++) {
        rs += fabsf(x[t * MLAND + j]);
        cs += fabsf(x[j * MLAND + t]);
    }
    __shared__ float s1[8], s2[8];
    for (int o = 16; o; o >>= 1) {
        rs = fmaxf(rs, __shfl_xor_sync(0xffffffffu, rs, o));
        cs = fmaxf(cs, __shfl_xor_sync(0xffffffffu, cs, o));
    }
    if ((t & 31) == 0) { s1[t >> 5] = rs; s2[t >> 5] = cs; }
    __syncthreads();
    if (t == 0) {
        rs = s1[0]; cs = s2[0];
        for (int w = 1; w < 8; w++) { rs = fmaxf(rs, s1[w]); cs = fmaxf(cs, s2[w]); }
        atomicMax(&norm[0], __float_as_uint(rs));
        atomicMax(&norm[1], __float_as_uint(cs));
    }
}

__global__ void zinit_k(const float* __restrict__ a2, float* __restrict__ z,
                        const unsigned int* __restrict__ norm)
{
    long idx = (long)blockIdx.x * 256 + threadIdx.x;
    if (idx >= (long)NHEADS * MLAND * MLAND) return;
    float inv = 1.f / (__uint_as_float(norm[0]) * __uint_as_float(norm[1]));
    int j = idx & 255; int i = (idx >> 8) & 255; long h = idx >> 16;
    z[idx] = a2[h * 65536 + (long)j * 256 + i] * inv;
}

// sliding-window depthwise conv over sequence dim, 8 rows per thread
__global__ __launch_bounds__(256)
void convadd2_k(const float* __restrict__ qkv,
                const float* __restrict__ rker,
                float* __restrict__ xh)
{
    __shared__ float skr[NHEADS * KCONV];
    for (int i = threadIdx.x; i < NHEADS * KCONV; i += 256) skr[i] = rker[i];
    __syncthreads();

    int idx = blockIdx.x * 256 + threadIdx.x;   // 512 cols x 1024 row-groups
    int col = idx & 511;
    int ng  = idx >> 9;
    if (ng >= NTOK / 8) return;
    long n0 = (long)ng * 8;
    const float* kr = skr + (col >> 6) * KCONV;
    const float* v = qkv + 2 * NHEADS * DHEAD + col;

    float win[40];
    #pragma unroll
    for (int j = 0; j < 40; j++) {
        long r = n0 - 16 + j;
        win[j] = (r >= 0 && r < NTOK) ? v[r * QKVW] : 0.f;
    }
    #pragma unroll
    for (int i = 0; i < 8; i++) {
        float s = 0.f;
        #pragma unroll
        for (int t = 0; t < KCONV; t++) s += kr[t] * win[i + t];
        xh[(n0 + i) * DMODEL + col] += s;
    }
}

__global__ void edge_k(const float* __restrict__ qe, const float* __restrict__ ke,
                       const int* __restrict__ rows, const int* __restrict__ cols,
                       const float* __restrict__ vals, float* __restrict__ Araw)
{
    int e = blockIdx.x * (blockDim.x >> 5) + (threadIdx.x >> 5);
    int lane = threadIdx.x & 31;
    if (e >= NEDGE) return;
    int r = rows[e], c = cols[e];
    const float4* qr = (const float4*)(qe + (long)r * WPD);
    const float4* kc = (const float4*)(ke + (long)c * WPD);
    float s = 0.f;
    #pragma unroll
    for (int i = lane; i < WPD / 4; i += 32) {
        float4 a = qr[i], b = kc[i];
        s += a.x * b.x + a.y * b.y + a.z * b.z + a.w * b.w;
    }
    for (int o = 16; o; o >>= 1) s += __shfl_xor_sync(0xffffffffu, s, o);
    if (lane == 0) atomicAdd(&Araw[r], s * 0.0625f * vals[e]);
}

__global__ void softmax_all_k(const float* __restrict__ A, float* __restrict__ alpha, int n)
{
    __shared__ float sm[32];
    int tid = threadIdx.x; // 1024
    float m = -1e30f;
    for (int i = tid; i < n; i += 1024) m = fmaxf(m, A[i]);
    for (int o = 16; o; o >>= 1) m = fmaxf(m, __shfl_xor_sync(0xffffffffu, m, o));
    if ((tid & 31) == 0) sm[tid >> 5] = m;
    __syncthreads();
    if (tid == 0) { float bm = sm[0]; for (int w = 1; w < 32; w++) bm = fmaxf(bm, sm[w]); sm[0] = bm; }
    __syncthreads();
    m = sm[0];
    __syncthreads();
    float s = 0.f;
    for (int i = tid; i < n; i += 1024) s += __expf(A[i] - m);
    for (int o = 16; o; o >>= 1) s += __shfl_xor_sync(0xffffffffu, s, o);
    if ((tid & 31) == 0) sm[tid >> 5] = s;
    __syncthreads();
    if (tid == 0) { float bs = 0.f; for (int w = 0; w < 32; w++) bs += sm[w]; sm[0] = bs; }
    __syncthreads();
    float inv = 1.f / sm[0];
    for (int i = tid; i < n; i += 1024) alpha[i] = __expf(A[i] - m) * inv;
}

__global__ void final_k(const float* __restrict__ val, const float* __restrict__ wvb,
                        const float* __restrict__ alpha, const float* __restrict__ enc,
                        const float* __restrict__ Araw, float* __restrict__ out)
{
    long idx = (long)blockIdx.x * 256 + threadIdx.x;
    long total = (long)NTOK * DMODEL;
    if (idx < total) {
        int col = idx & 511; long n = idx >> 9;
        float v = val[idx] + wvb[col];
        float xl = alpha[n] * v;
        float w = 1.f / (1.f + __expf(xl)); // sigmoid(-xl)
        float sq = w * w;
        float e = enc[idx];
        out[idx] = xl * 2.f * sq + 2.f * e * (1.f - sq);
    }
    if (idx < NTOK) out[total + idx] = Araw[idx];
}

// ---------------- driver ----------------
extern "C" void kernel_launch(void* const* d_in, const int* in_sizes, int n_in,
                              void* d_out, int out_size)
{
    const float* dense  = (const float*)d_in[0];
    const int*   arows  = (const int*)  d_in[1];
    const int*   acols  = (const int*)  d_in[2];
    const float* avals  = (const float*)d_in[3];
    const float* wq     = (const float*)d_in[4];
    const float* wk     = (const float*)d_in[5];
    const float* w_qkv  = (const float*)d_in[6];
    const float* w_out  = (const float*)d_in[7];
    const float* b_out  = (const float*)d_in[8];
    const float* rker   = (const float*)d_in[9];
    const float* wv_w   = (const float*)d_in[10];
    const float* wv_b   = (const float*)d_in[11];
    float* out = (float*)d_out;

    float *qkv, *ql, *kl, *a1, *a2, *a3, *z, *z2, *xz, *t1, *t2, *a3v, *w1;
    float *xh, *enc, *val, *qe, *ke, *Araw, *alpha;
    unsigned int* norm;
    cudaGetSymbolAddress((void**)&qkv, g_qkv);
    cudaGetSymbolAddress((void**)&ql,  g_ql);
    cudaGetSymbolAddress((void**)&kl,  g_kl);
    cudaGetSymbolAddress((void**)&a1,  g_a1);
    cudaGetSymbolAddress((void**)&a2,  g_a2);
    cudaGetSymbolAddress((void**)&a3,  g_a3);
    cudaGetSymbolAddress((void**)&z,   g_z);
    cudaGetSymbolAddress((void**)&z2,  g_z2);
    cudaGetSymbolAddress((void**)&xz,  g_xz);
    cudaGetSymbolAddress((void**)&t1,  g_t1);
    cudaGetSymbolAddress((void**)&t2,  g_t2);
    cudaGetSymbolAddress((void**)&a3v, g_a3v);
    cudaGetSymbolAddress((void**)&w1,  g_w1);
    cudaGetSymbolAddress((void**)&xh,  g_xh);
    cudaGetSymbolAddress((void**)&enc, g_enc);
    cudaGetSymbolAddress((void**)&val, g_val);
    cudaGetSymbolAddress((void**)&qe,  g_qe);
    cudaGetSymbolAddress((void**)&ke,  g_ke);
    cudaGetSymbolAddress((void**)&Araw, g_Araw);
    cudaGetSymbolAddress((void**)&alpha, g_alpha);
    cudaGetSymbolAddress((void**)&norm, g_norm);

    const float qscale = 0.125f; // DIM_HEAD^-0.5
    const long  smm    = (long)MLAND * MLAND;

    // 0. zero scratch (a3v accum, Araw accum, norm)
    zeros_k<<<(NHEADS * MLAND * DHEAD + 255) / 256, 256>>>(a3v, Araw, norm);

    // 1. qkv = dense @ w_qkv^T  [8192,1536]
    gemmTC(true, NTOK, QKVW, DMODEL, 1.f, dense, DMODEL, 0, w_qkv, DMODEL, 0,
           qkv, QKVW, 0, 1);

    // 2. landmarks
    landmarks_k<<<(NHEADS * MLAND * DHEAD + 255) / 256, 256>>>(qkv, ql, kl);

    // 3. a1 = softmax(scale * q @ k_l^T)   [h,8192,256]
    gemmTC(true, NTOK, MLAND, DHEAD, qscale,
           qkv, QKVW, DHEAD, kl, DHEAD, (long)MLAND * DHEAD,
           a1, MLAND, (long)NTOK * MLAND, NHEADS);
    softmax256_k<<<NHEADS * NTOK, 256>>>(a1);

    // 4. a2 = softmax(scale * q_l @ k_l^T) [h,256,256]
    gemmTC(true, MLAND, MLAND, DHEAD, qscale,
           ql, DHEAD, (long)MLAND * DHEAD, kl, DHEAD, (long)MLAND * DHEAD,
           a2, MLAND, smm, NHEADS);
    softmax256_k<<<NHEADS * MLAND, 256>>>(a2);

    // 5. pinv init
    a2norm_k<<<NHEADS, 256>>>(a2, norm);
    zinit_k<<<(int)((NHEADS * smm + 255) / 256), 256>>>(a2, z, norm);

    // 6. pinv iterations (fp32 SIMT, fused epilogues — measured best)
    float* zin = z; float* zout = z2;
    dim3 gp(4, 4, NHEADS);
    for (int it = 0; it < PITERS; it++) {
        gemm64ep_k<<<gp, 256>>>(1.f, 0.f, a2, zin, xz, -1.f, 7.f, t1);      // xz, 7I-xz
        gemm64ep_k<<<gp, 256>>>(-1.f, 15.f, xz, t1, t2, 0.f, 0.f, nullptr); // 15I - xz@t1
        gemm64ep_k<<<gp, 256>>>(-1.f, 13.f, xz, t2, t1, 0.f, 0.f, nullptr); // 13I - xz@t2
        gemm64ep_k<<<gp, 256>>>(0.25f, 0.f, zin, t1, zout, 0.f, 0.f, nullptr);
        float* tmp = zin; zin = zout; zout = tmp;
    }
    float* zfin = zin;

    // 7. a3 = softmax(scale * q_l @ k^T)  [h,256,8192]
    gemmTC(true, MLAND, NTOK, DHEAD, qscale,
           ql, DHEAD, (long)MLAND * DHEAD,
           qkv + NHEADS * DHEAD, QKVW, DHEAD,
           a3, NTOK, (long)MLAND * NTOK, NHEADS);
    softmax8192_k<<<NHEADS * MLAND, 1024>>>(a3);

    // 8. a3v = a3 @ v  [h,256,64]  (split-K 16, atomic; pre-zeroed)
    gemmT64(MLAND, NTOK, 1.f,
            a3, NTOK, (long)MLAND * NTOK,
            qkv + 2 * NHEADS * DHEAD, QKVW, DHEAD,
            a3v, DHEAD, (long)MLAND * DHEAD, NHEADS, 16);

    // 9. w1 = a1 @ zfin  [h,8192,256]
    gemmTC(false, NTOK, MLAND, MLAND, 1.f,
           a1, MLAND, (long)NTOK * MLAND, zfin, MLAND, smm,
           w1, MLAND, (long)NTOK * MLAND, NHEADS);

    // 10. xh[n, h*64:+64] = w1 @ a3v
    gemmT64(NTOK, MLAND, 1.f,
            w1, MLAND, (long)NTOK * MLAND,
            a3v, DHEAD, (long)MLAND * DHEAD,
            xh, DMODEL, DHEAD, NHEADS, 1);

    // 11. residual depthwise conv on v, added into xh
    convadd2_k<<<(NTOK / 8) * DMODEL / 256, 256>>>(qkv, rker, xh);

    // 12. enc = xh @ w_out^T + b_out + dense  (fused epilogue)
    gemmTC(true, NTOK, DMODEL, DMODEL, 1.f, xh, DMODEL, 0, w_out, DMODEL, 0,
           enc, DMODEL, 0, 1, dense, b_out);

    // 13. qe = enc @ wq ; ke = enc @ wk
    gemmTC(false, NTOK, WPD, DMODEL, 1.f, enc, DMODEL, 0, wq, WPD, 0, qe, WPD, 0, 1);
    gemmTC(false, NTOK, WPD, DMODEL, 1.f, enc, DMODEL, 0, wk, WPD, 0, ke, WPD, 0, 1);

    // 14. edge scores -> segment sum (Araw pre-zeroed)
    edge_k<<<(NEDGE + 7) / 8, 256>>>(qe, ke, arows, acols, avals, Araw);

    // 15. alpha = softmax(A_raw) over all N
    softmax_all_k<<<1, 1024>>>(Araw, alpha, NTOK);

    // 16. value = dense @ wv_w^T
    gemmTC(true, NTOK, DMODEL, DMODEL, 1.f, dense, DMODEL, 0, wv_w, DMODEL, 0,
           val, DMODEL, 0, 1);

    // 17. final gated blend + A_raw copy
    final_k<<<(int)(((long)NTOK * DMODEL + 255) / 256), 256>>>(val, wv_b, alpha, enc, Araw, out);
}

// round 10
// speedup vs baseline: 1.3322x; 1.1178x over previous
#include <cuda_runtime.h>
#include <math.h>

// ---------------- problem constants ----------------
static const int NTOK   = 8192;   // N
static const int DMODEL = 512;    // D
static const int NHEADS = 8;
static const int DHEAD  = 64;
static const int MLAND  = 256;    // M landmarks
static const int LFOLD  = 32;     // N / M
static const int WPD    = 256;    // weight_params_dim
static const int NEDGE  = 262144; // E
static const int KCONV  = 33;
static const int QKVW   = 3 * NHEADS * DHEAD; // 1536
static const int PITERS = 6;

// ---------------- device scratch (BSS) ----------------
__device__ float g_qkv [NTOK * QKVW];
__device__ float g_ql  [NHEADS * MLAND * DHEAD];
__device__ float g_kl  [NHEADS * MLAND * DHEAD];
__device__ float g_a1  [(long)NHEADS * NTOK * MLAND];
__device__ float g_a2  [NHEADS * MLAND * MLAND];
__device__ float g_a3  [(long)NHEADS * MLAND * NTOK];
__device__ float g_z   [NHEADS * MLAND * MLAND];
__device__ float g_z2  [NHEADS * MLAND * MLAND];
__device__ float g_xz  [NHEADS * MLAND * MLAND];
__device__ float g_t1  [NHEADS * MLAND * MLAND];
__device__ float g_t2  [NHEADS * MLAND * MLAND];
__device__ float g_a3v [NHEADS * MLAND * DHEAD];
__device__ float g_zv  [NHEADS * MLAND * DHEAD];
__device__ float g_xh  [NTOK * DMODEL];
__device__ float g_enc [NTOK * DMODEL];
__device__ float g_val [NTOK * DMODEL];
__device__ float g_qe  [NTOK * WPD];
__device__ float g_ke  [NTOK * WPD];
__device__ float g_Araw [NTOK];
__device__ float g_alpha[NTOK];
__device__ unsigned int g_norm[2];

// ---------------- tf32 / ptx helpers ----------------
__device__ __forceinline__ unsigned f2tf(float x) {
    unsigned u;
    asm("cvt.rna.tf32.f32 %0, %1;" : "=r"(u) : "f"(x));
    return u;
}
__device__ __forceinline__ void split_u(unsigned x, unsigned& hi, unsigned& lo) {
    float f = __uint_as_float(x);
    hi = f2tf(f);
    lo = f2tf(f - __uint_as_float(hi));
}
__device__ __forceinline__ void mma8(float* c, const unsigned* a, const unsigned* b) {
    asm volatile(
        "mma.sync.aligned.m16n8k8.row.col.f32.tf32.tf32.f32 "
        "{%0,%1,%2,%3}, {%4,%5,%6,%7}, {%8,%9}, {%0,%1,%2,%3};"
        : "+f"(c[0]), "+f"(c[1]), "+f"(c[2]), "+f"(c[3])
        : "r"(a[0]), "r"(a[1]), "r"(a[2]), "r"(a[3]), "r"(b[0]), "r"(b[1]));
}
__device__ __forceinline__ void ldsm4(unsigned& r0, unsigned& r1, unsigned& r2,
                                      unsigned& r3, unsigned addr) {
    asm volatile("ldmatrix.sync.aligned.m8n8.x4.shared.b16 {%0,%1,%2,%3}, [%4];"
        : "=r"(r0), "=r"(r1), "=r"(r2), "=r"(r3) : "r"(addr));
}
__device__ __forceinline__ unsigned sptr(const void* p) {
    return (unsigned)__cvta_generic_to_shared(p);
}
#define CP16(d, s)  asm volatile("cp.async.ca.shared.global [%0], [%1], 16;" :: "r"(d), "l"(s))
#define CP4(d, s)   asm volatile("cp.async.ca.shared.global [%0], [%1], 4;"  :: "r"(d), "l"(s))
#define CPCOMMIT()  asm volatile("cp.async.commit_group;")
#define CPWAIT1()   asm volatile("cp.async.wait_group 1;")
#define CPWAIT0()   asm volatile("cp.async.wait_group 0;")

// padded physical row index: insert one 16B slot every 8 rows (bank spread)
__device__ __forceinline__ int prp(int r) { return r + (r >> 3); }

static const int SROWS = 144;  // prp(127)=142 < 144
struct StageT { float A[2][2][SROWS][4]; float B[2][2][SROWS][4]; };
static const int NSTAGE = 3;

// =====================================================================
// gemmT2: tf32x3 tensor GEMM, raw-fp32 smem + ldmatrix + cp.async,
// 3-stage pipeline with ONE barrier per k-tile.
// CTA tile 128 x BN x 16, 256 threads (8 warps 4x2), warp tile 32 x BN/2.
// C = alpha * A@op(B) [+ addC + bias];  TB: B=[N,K]. !TB: B=[K,N].
// kSplit>1: atomicAdd into pre-zeroed C.
// REQUIRES M%128==0, N%BN==0, (K/kSplit)%16==0, 16B-aligned rows.
// =====================================================================
template<bool TB, int BN>
__global__ __launch_bounds__(256, 2)
void gemmT2_k(int M, int N, int K, float alpha,
              const float* __restrict__ A, int lda, long sA,
              const float* __restrict__ B, int ldb, long sB,
              float* __restrict__ C, int ldc, long sC, int kSplit,
              const float* __restrict__ addC, const float* __restrict__ bias)
{
    constexpr int WNT = BN / 16;  // n-tiles (8 cols each) per warp
    constexpr int NP  = WNT / 2;  // ldmatrix x4 pairs
    constexpr int NB  = (BN == 128) ? 8 : 4; // NT fill elems/thread

    int bz = blockIdx.z;
    int batch = bz / kSplit, ks = bz - batch * kSplit;
    A += (long)batch * sA; B += (long)batch * sB; C += (long)batch * sC;
    if (addC) addC += (long)batch * sC;
    const int chunk = K / kSplit;
    const int k0s = ks * chunk;
    const int T = chunk >> 4;

    const int row0 = blockIdx.y * 128;
    const int col0 = blockIdx.x * BN;
    const int tid  = threadIdx.x;
    const int lane = tid & 31, w = tid >> 5, wr = w >> 1, wc = w & 1;

    extern __shared__ __align__(16) char smraw[];
    StageT* sm = reinterpret_cast<StageT*>(smraw);
    const unsigned stageSz = (unsigned)sizeof(StageT);

    // ---- fill precompute ----
    const int ar = tid >> 1, akt = tid & 1;
    const float* aSrc = A + (long)(row0 + ar) * lda + akt * 8;
    const unsigned aD0 = sptr(&sm[0].A[akt][0][prp(ar)][0]);
    const unsigned aD1 = sptr(&sm[0].A[akt][1][prp(ar)][0]);

    const float* bSrc;
    unsigned bD0 = 0, bD1 = 0;
    unsigned bDst[8];
    if (TB) {
        int bn = tid >> 1, bkt = tid & 1;
        bSrc = B + (long)(col0 + bn) * ldb + bkt * 8;
        bD0 = sptr(&sm[0].B[bkt][0][prp(bn)][0]);
        bD1 = sptr(&sm[0].B[bkt][1][prp(bn)][0]);
    } else {
        int n  = tid & (BN - 1);
        int kb = (tid >> ((BN == 128) ? 7 : 6)) * NB;
        bSrc = B + (long)kb * ldb + col0 + n;
        #pragma unroll
        for (int j = 0; j < NB; j++) {
            int kk = kb + j;
            bDst[j] = sptr(&sm[0].B[kk >> 3][(kk >> 2) & 1][prp(n)][kk & 3]);
        }
    }

    auto fill = [&](int kAbs, int s) {
        unsigned so = s * stageSz;
        CP16(aD0 + so, aSrc + kAbs);
        CP16(aD1 + so, aSrc + kAbs + 4);
        if (TB) {
            CP16(bD0 + so, bSrc + kAbs);
            CP16(bD1 + so, bSrc + kAbs + 4);
        } else {
            #pragma unroll
            for (int j = 0; j < NB; j++)
                CP4(bDst[j] + so, bSrc + (long)(kAbs + j) * ldb);
        }
    };

    // ---- ldmatrix address precompute ----
    const int aRow = wr * 32 + (lane & 15);
    const int aKj  = lane >> 4;
    unsigned aAdr[2][2];
    #pragma unroll
    for (int kt = 0; kt < 2; kt++)
        #pragma unroll
        for (int rt = 0; rt < 2; rt++)
            aAdr[kt][rt] = sptr(&sm[0].A[kt][aKj][prp(aRow + rt * 16)][0]);

    const int bKj  = (lane >> 3) & 1;
    const int bRow = wc * (BN / 2) + ((lane & 7) | ((lane & 16) >> 1));
    unsigned bAdr[2][NP];
    #pragma unroll
    for (int kt = 0; kt < 2; kt++)
        #pragma unroll
        for (int p = 0; p < NP; p++)
            bAdr[kt][p] = sptr(&sm[0].B[kt][bKj][prp(bRow + p * 16)][0]);

    float acc[2][WNT][4];
    #pragma unroll
    for (int i = 0; i < 2; i++)
        #pragma unroll
        for (int j = 0; j < WNT; j++)
            #pragma unroll
            for (int v = 0; v < 4; v++) acc[i][j][v] = 0.f;

    auto compute = [&](int s) {
        unsigned so = s * stageSz;
        #pragma unroll
        for (int kt = 0; kt < 2; kt++) {
            unsigned ah[2][4], al[2][4];
            #pragma unroll
            for (int rt = 0; rt < 2; rt++) {
                unsigned r0, r1, r2, r3;
                ldsm4(r0, r1, r2, r3, aAdr[kt][rt] + so);
                split_u(r0, ah[rt][0], al[rt][0]);
                split_u(r1, ah[rt][1], al[rt][1]);
                split_u(r2, ah[rt][2], al[rt][2]);
                split_u(r3, ah[rt][3], al[rt][3]);
            }
            #pragma unroll
            for (int p = 0; p < NP; p++) {
                unsigned r0, r1, r2, r3;
                ldsm4(r0, r1, r2, r3, bAdr[kt][p] + so);
                unsigned bh0[2], bl0[2], bh1[2], bl1[2];
                split_u(r0, bh0[0], bl0[0]);
                split_u(r1, bh0[1], bl0[1]);
                split_u(r2, bh1[0], bl1[0]);
                split_u(r3, bh1[1], bl1[1]);
                #pragma unroll
                for (int rt = 0; rt < 2; rt++) {
                    mma8(acc[rt][2 * p],     ah[rt], bh0);
                    mma8(acc[rt][2 * p],     al[rt], bh0);
                    mma8(acc[rt][2 * p],     ah[rt], bl0);
                    mma8(acc[rt][2 * p + 1], ah[rt], bh1);
                    mma8(acc[rt][2 * p + 1], al[rt], bh1);
                    mma8(acc[rt][2 * p + 1], ah[rt], bl1);
                }
            }
        }
    };

    // ---- 3-stage pipelined mainloop, one barrier per tile ----
    fill(k0s, 0);
    CPCOMMIT();
    if (T > 1) { fill(k0s + 16, 1); CPCOMMIT(); }
    for (int t = 0; t < T; t++) {
        if (t + 1 < T) CPWAIT1(); else CPWAIT0();
        __syncthreads();
        if (t + 2 < T) {
            fill(k0s + (t + 2) * 16, (t + 2) % NSTAGE);
            CPCOMMIT();
        }
        compute(t % NSTAGE);
    }

    // ---- epilogue ----
    const int g = lane >> 2, tg = lane & 3;
    #pragma unroll
    for (int rt = 0; rt < 2; rt++) {
        #pragma unroll
        for (int n2 = 0; n2 < WNT; n2++) {
            int gr = row0 + wr * 32 + rt * 16 + g;
            int gc = col0 + wc * (BN / 2) + n2 * 8 + tg * 2;
            float* c = acc[rt][n2];
            long i0 = (long)gr * ldc + gc;
            long i1 = i0 + 8 * (long)ldc;
            float v00 = alpha * c[0], v01 = alpha * c[1];
            float v10 = alpha * c[2], v11 = alpha * c[3];
            if (addC) {
                v00 += addC[i0]; v01 += addC[i0 + 1];
                v10 += addC[i1]; v11 += addC[i1 + 1];
            }
            if (bias) {
                v00 += bias[gc]; v01 += bias[gc + 1];
                v10 += bias[gc]; v11 += bias[gc + 1];
            }
            if (kSplit > 1) {
                atomicAdd(&C[i0], v00); atomicAdd(&C[i0 + 1], v01);
                atomicAdd(&C[i1], v10); atomicAdd(&C[i1 + 1], v11);
            } else {
                C[i0] = v00; C[i0 + 1] = v01;
                C[i1] = v10; C[i1 + 1] = v11;
            }
        }
    }
}

static const int GT_SMEM = NSTAGE * (int)sizeof(StageT);  // 55296 B

static void gemmTC(bool tb, int M, int N, int K, float alpha,
                   const float* A, int lda, long sA,
                   const float* B, int ldb, long sB,
                   float* C, int ldc, long sC, int batch,
                   const float* addC = nullptr, const float* bias = nullptr)
{
    dim3 g(N / 128, M / 128, batch);
    if (tb) {
        cudaFuncSetAttribute(gemmT2_k<true, 128>,
            cudaFuncAttributeMaxDynamicSharedMemorySize, GT_SMEM);
        gemmT2_k<true, 128><<<g, 256, GT_SMEM>>>(M, N, K, alpha, A, lda, sA,
            B, ldb, sB, C, ldc, sC, 1, addC, bias);
    } else {
        cudaFuncSetAttribute(gemmT2_k<false, 128>,
            cudaFuncAttributeMaxDynamicSharedMemorySize, GT_SMEM);
        gemmT2_k<false, 128><<<g, 256, GT_SMEM>>>(M, N, K, alpha, A, lda, sA,
            B, ldb, sB, C, ldc, sC, 1, addC, bias);
    }
}

static void gemmT64(int M, int K, float alpha,
                    const float* A, int lda, long sA,
                    const float* B, int ldb, long sB,
                    float* C, int ldc, long sC, int batch, int kSplit)
{
    dim3 g(1, M / 128, batch * kSplit);
    cudaFuncSetAttribute(gemmT2_k<false, 64>,
        cudaFuncAttributeMaxDynamicSharedMemorySize, GT_SMEM);
    gemmT2_k<false, 64><<<g, 256, GT_SMEM>>>(M, 64, K, alpha, A, lda, sA,
        B, ldb, sB, C, ldc, sC, kSplit, nullptr, nullptr);
}

// =====================================================================
// gemm64ep: fp32 SIMT 256x256x256 batched GEMM (pinv), NT, 64x64 tile,
// fused epilogue:  C = alpha*(A@B) + diag*I,  optional C2 likewise.
// =====================================================================
__global__ __launch_bounds__(256)
void gemm64ep_k(float alpha, float diag,
                const float* __restrict__ A, const float* __restrict__ B,
                float* __restrict__ C,
                float alpha2, float diag2, float* __restrict__ C2)
{
    const long sb = (long)MLAND * MLAND;
    A += blockIdx.z * sb;
    B += blockIdx.z * sb;
    C += blockIdx.z * sb;
    if (C2) C2 += blockIdx.z * sb;

    __shared__ float As[64 * 17];
    __shared__ float Bs[16 * 64];

    int tid = threadIdx.x;
    int row0 = blockIdx.y * 64;
    int col0 = blockIdx.x * 64;
    int tx = tid & 15, ty = tid >> 4;

    float acc[4][4] = {};

    for (int kk = 0; kk < 256; kk += 16) {
        #pragma unroll
        for (int i = 0; i < 4; i++) {
            int e = tid + i * 256;
            int r = e >> 4, c = e & 15;
            As[r * 17 + c] = A[(long)(row0 + r) * 256 + kk + c];
        }
        #pragma unroll
        for (int i = 0; i < 4; i++) {
            int e = tid + i * 256;
            int c = e >> 6, n = e & 63;
            Bs[c * 64 + n] = B[(long)(kk + c) * 256 + col0 + n];
        }
        __syncthreads();
        #pragma unroll
        for (int c = 0; c < 16; c++) {
            float a[4], b[4];
            #pragma unroll
            for (int i = 0; i < 4; i++) a[i] = As[(ty * 4 + i) * 17 + c];
            #pragma unroll
            for (int j = 0; j < 4; j++) b[j] = Bs[c * 64 + tx * 4 + j];
            #pragma unroll
            for (int i = 0; i < 4; i++)
                #pragma unroll
                for (int j = 0; j < 4; j++)
                    acc[i][j] = fmaf(a[i], b[j], acc[i][j]);
        }
        __syncthreads();
    }
    #pragma unroll
    for (int i = 0; i < 4; i++) {
        int gr = row0 + ty * 4 + i;
        #pragma unroll
        for (int j = 0; j < 4; j++) {
            int gc = col0 + tx * 4 + j;
            float d = (gr == gc) ? 1.f : 0.f;
            C[(long)gr * 256 + gc] = alpha * acc[i][j] + diag * d;
            if (C2) C2[(long)gr * 256 + gc] = alpha2 * acc[i][j] + diag2 * d;
        }
    }
}

// ---------------- small kernels ----------------
__global__ void zeros_k(float* a3v, float* Araw, unsigned int* norm)
{
    long i = (long)blockIdx.x * 256 + threadIdx.x;
    if (i < NHEADS * MLAND * DHEAD) a3v[i] = 0.f;
    if (i < NTOK) Araw[i] = 0.f;
    if (i < 2) norm[i] = 0u;
}

__global__ void landmarks_k(const float* __restrict__ qkv,
                            float* __restrict__ ql, float* __restrict__ kl)
{
    int idx = blockIdx.x * blockDim.x + threadIdx.x;
    if (idx >= NHEADS * MLAND * DHEAD) return;
    int d = idx & 63; int j = (idx >> 6) & 255; int h = idx >> 14;
    const float* qp = qkv + (long)(j * LFOLD) * QKVW + h * DHEAD + d;
    const float* kp = qp + NHEADS * DHEAD;
    float sq = 0.f, sk = 0.f;
    #pragma unroll 4
    for (int t = 0; t < LFOLD; t++) {
        sq += qp[(long)t * QKVW];
        sk += kp[(long)t * QKVW];
    }
    ql[idx] = sq * (1.f / LFOLD);
    kl[idx] = sk * (1.f / LFOLD);
}

__global__ __launch_bounds__(256)
void softmax256_k(float* __restrict__ X)
{
    float* x = X + (long)blockIdx.x * 256;
    int tid = threadIdx.x;
    __shared__ float sm[8];
    float v = x[tid];
    float m = v;
    #pragma unroll
    for (int o = 16; o; o >>= 1) m = fmaxf(m, __shfl_xor_sync(0xffffffffu, m, o));
    if ((tid & 31) == 0) sm[tid >> 5] = m;
    __syncthreads();
    m = sm[0];
    #pragma unroll
    for (int i = 1; i < 8; i++) m = fmaxf(m, sm[i]);
    float e = __expf(v - m);
    float s = e;
    #pragma unroll
    for (int o = 16; o; o >>= 1) s += __shfl_xor_sync(0xffffffffu, s, o);
    __syncthreads();
    if ((tid & 31) == 0) sm[tid >> 5] = s;
    __syncthreads();
    s = sm[0];
    #pragma unroll
    for (int i = 1; i < 8; i++) s += sm[i];
    x[tid] = e * (1.f / s);
}

__global__ __launch_bounds__(1024)
void softmax8192_k(float* __restrict__ X)
{
    float* x = X + (long)blockIdx.x * 8192;
    int tid = threadIdx.x;
    __shared__ float sm[32];
    float4 v0 = *(const float4*)(x + tid * 8);
    float4 v1 = *(const float4*)(x + tid * 8 + 4);
    float m = fmaxf(fmaxf(fmaxf(v0.x, v0.y), fmaxf(v0.z, v0.w)),
                    fmaxf(fmaxf(v1.x, v1.y), fmaxf(v1.z, v1.w)));
    #pragma unroll
    for (int o = 16; o; o >>= 1) m = fmaxf(m, __shfl_xor_sync(0xffffffffu, m, o));
    if ((tid & 31) == 0) sm[tid >> 5] = m;
    __syncthreads();
    m = sm[0];
    #pragma unroll
    for (int i = 1; i < 32; i++) m = fmaxf(m, sm[i]);
    float e0 = __expf(v0.x - m), e1 = __expf(v0.y - m);
    float e2 = __expf(v0.z - m), e3 = __expf(v0.w - m);
    float e4 = __expf(v1.x - m), e5 = __expf(v1.y - m);
    float e6 = __expf(v1.z - m), e7 = __expf(v1.w - m);
    float s = ((e0 + e1) + (e2 + e3)) + ((e4 + e5) + (e6 + e7));
    #pragma unroll
    for (int o = 16; o; o >>= 1) s += __shfl_xor_sync(0xffffffffu, s, o);
    __syncthreads();
    if ((tid & 31) == 0) sm[tid >> 5] = s;
    __syncthreads();
    s = sm[0];
    #pragma unroll
    for (int i = 1; i < 32; i++) s += sm[i];
    float inv = 1.f / s;
    *(float4*)(x + tid * 8)     = make_float4(e0 * inv, e1 * inv, e2 * inv, e3 * inv);
    *(float4*)(x + tid * 8 + 4) = make_float4(e4 * inv, e5 * inv, e6 * inv, e7 * inv);
}

__global__ void a2norm_k(const float* __restrict__ a2, unsigned int* norm)
{
    int h = blockIdx.x; int t = threadIdx.x;
    const float* x = a2 + (long)h * MLAND * MLAND;
    float rs = 0.f, cs = 0.f;
    for (int j = 0; j < MLAND; j++) {
        rs += fabsf(x[t * MLAND + j]);
        cs += fabsf(x[j * MLAND + t]);
    }
    __shared__ float s1[8], s2[8];
    for (int o = 16; o; o >>= 1) {
        rs = fmaxf(rs, __shfl_xor_sync(0xffffffffu, rs, o));
        cs = fmaxf(cs, __shfl_xor_sync(0xffffffffu, cs, o));
    }
    if ((t & 31) == 0) { s1[t >> 5] = rs; s2[t >> 5] = cs; }
    __syncthreads();
    if (t == 0) {
        rs = s1[0]; cs = s2[0];
        for (int w = 1; w < 8; w++) { rs = fmaxf(rs, s1[w]); cs = fmaxf(cs, s2[w]); }
        atomicMax(&norm[0], __float_as_uint(rs));
        atomicMax(&norm[1], __float_as_uint(cs));
    }
}

__global__ void zinit_k(const float* __restrict__ a2, float* __restrict__ z,
                        const unsigned int* __restrict__ norm)
{
    long idx = (long)blockIdx.x * 256 + threadIdx.x;
    if (idx >= (long)NHEADS * MLAND * MLAND) return;
    float inv = 1.f / (__uint_as_float(norm[0]) * __uint_as_float(norm[1]));
    int j = idx & 255; int i = (idx >> 8) & 255; long h = idx >> 16;
    z[idx] = a2[h * 65536 + (long)j * 256 + i] * inv;
}

// sliding-window depthwise conv over sequence dim, 8 rows per thread
__global__ __launch_bounds__(256)
void convadd2_k(const float* __restrict__ qkv,
                const float* __restrict__ rker,
                float* __restrict__ xh)
{
    __shared__ float skr[NHEADS * KCONV];
    for (int i = threadIdx.x; i < NHEADS * KCONV; i += 256) skr[i] = rker[i];
    __syncthreads();

    int idx = blockIdx.x * 256 + threadIdx.x;   // 512 cols x 1024 row-groups
    int col = idx & 511;
    int ng  = idx >> 9;
    if (ng >= NTOK / 8) return;
    long n0 = (long)ng * 8;
    const float* kr = skr + (col >> 6) * KCONV;
    const float* v = qkv + 2 * NHEADS * DHEAD + col;

    float win[40];
    #pragma unroll
    for (int j = 0; j < 40; j++) {
        long r = n0 - 16 + j;
        win[j] = (r >= 0 && r < NTOK) ? v[r * QKVW] : 0.f;
    }
    #pragma unroll
    for (int i = 0; i < 8; i++) {
        float s = 0.f;
        #pragma unroll
        for (int t = 0; t < KCONV; t++) s += kr[t] * win[i + t];
        xh[(n0 + i) * DMODEL + col] += s;
    }
}

__global__ void edge_k(const float* __restrict__ qe, const float* __restrict__ ke,
                       const int* __restrict__ rows, const int* __restrict__ cols,
                       const float* __restrict__ vals, float* __restrict__ Araw)
{
    int e = blockIdx.x * (blockDim.x >> 5) + (threadIdx.x >> 5);
    int lane = threadIdx.x & 31;
    if (e >= NEDGE) return;
    int r = rows[e], c = cols[e];
    const float4* qr = (const float4*)(qe + (long)r * WPD);
    const float4* kc = (const float4*)(ke + (long)c * WPD);
    float s = 0.f;
    #pragma unroll
    for (int i = lane; i < WPD / 4; i += 32) {
        float4 a = qr[i], b = kc[i];
        s += a.x * b.x + a.y * b.y + a.z * b.z + a.w * b.w;
    }
    for (int o = 16; o; o >>= 1) s += __shfl_xor_sync(0xffffffffu, s, o);
    if (lane == 0) atomicAdd(&Araw[r], s * 0.0625f * vals[e]);
}

__global__ void softmax_all_k(const float* __restrict__ A, float* __restrict__ alpha, int n)
{
    __shared__ float sm[32];
    int tid = threadIdx.x; // 1024
    float m = -1e30f;
    for (int i = tid; i < n; i += 1024) m = fmaxf(m, A[i]);
    for (int o = 16; o; o >>= 1) m = fmaxf(m, __shfl_xor_sync(0xffffffffu, m, o));
    if ((tid & 31) == 0) sm[tid >> 5] = m;
    __syncthreads();
    if (tid == 0) { float bm = sm[0]; for (int w = 1; w < 32; w++) bm = fmaxf(bm, sm[w]); sm[0] = bm; }
    __syncthreads();
    m = sm[0];
    __syncthreads();
    float s = 0.f;
    for (int i = tid; i < n; i += 1024) s += __expf(A[i] - m);
    for (int o = 16; o; o >>= 1) s += __shfl_xor_sync(0xffffffffu, s, o);
    if ((tid & 31) == 0) sm[tid >> 5] = s;
    __syncthreads();
    if (tid == 0) { float bs = 0.f; for (int w = 0; w < 32; w++) bs += sm[w]; sm[0] = bs; }
    __syncthreads();
    float inv = 1.f / sm[0];
    for (int i = tid; i < n; i += 1024) alpha[i] = __expf(A[i] - m) * inv;
}

__global__ void final_k(const float* __restrict__ val, const float* __restrict__ wvb,
                        const float* __restrict__ alpha, const float* __restrict__ enc,
                        const float* __restrict__ Araw, float* __restrict__ out)
{
    long idx = (long)blockIdx.x * 256 + threadIdx.x;
    long total = (long)NTOK * DMODEL;
    if (idx < total) {
        int col = idx & 511; long n = idx >> 9;
        float v = val[idx] + wvb[col];
        float xl = alpha[n] * v;
        float w = 1.f / (1.f + __expf(xl)); // sigmoid(-xl)
        float sq = w * w;
        float e = enc[idx];
        out[idx] = xl * 2.f * sq + 2.f * e * (1.f - sq);
    }
    if (idx < NTOK) out[total + idx] = Araw[idx];
}

// ---------------- driver ----------------
extern "C" void kernel_launch(void* const* d_in, const int* in_sizes, int n_in,
                              void* d_out, int out_size)
{
    const float* dense  = (const float*)d_in[0];
    const int*   arows  = (const int*)  d_in[1];
    const int*   acols  = (const int*)  d_in[2];
    const float* avals  = (const float*)d_in[3];
    const float* wq     = (const float*)d_in[4];
    const float* wk     = (const float*)d_in[5];
    const float* w_qkv  = (const float*)d_in[6];
    const float* w_out  = (const float*)d_in[7];
    const float* b_out  = (const float*)d_in[8];
    const float* rker   = (const float*)d_in[9];
    const float* wv_w   = (const float*)d_in[10];
    const float* wv_b   = (const float*)d_in[11];
    float* out = (float*)d_out;

    float *qkv, *ql, *kl, *a1, *a2, *a3, *z, *z2, *xz, *t1, *t2, *a3v, *zv;
    float *xh, *enc, *val, *qe, *ke, *Araw, *alpha;
    unsigned int* norm;
    cudaGetSymbolAddress((void**)&qkv, g_qkv);
    cudaGetSymbolAddress((void**)&ql,  g_ql);
    cudaGetSymbolAddress((void**)&kl,  g_kl);
    cudaGetSymbolAddress((void**)&a1,  g_a1);
    cudaGetSymbolAddress((void**)&a2,  g_a2);
    cudaGetSymbolAddress((void**)&a3,  g_a3);
    cudaGetSymbolAddress((void**)&z,   g_z);
    cudaGetSymbolAddress((void**)&z2,  g_z2);
    cudaGetSymbolAddress((void**)&xz,  g_xz);
    cudaGetSymbolAddress((void**)&t1,  g_t1);
    cudaGetSymbolAddress((void**)&t2,  g_t2);
    cudaGetSymbolAddress((void**)&a3v, g_a3v);
    cudaGetSymbolAddress((void**)&zv,  g_zv);
    cudaGetSymbolAddress((void**)&xh,  g_xh);
    cudaGetSymbolAddress((void**)&enc, g_enc);
    cudaGetSymbolAddress((void**)&val, g_val);
    cudaGetSymbolAddress((void**)&qe,  g_qe);
    cudaGetSymbolAddress((void**)&ke,  g_ke);
    cudaGetSymbolAddress((void**)&Araw, g_Araw);
    cudaGetSymbolAddress((void**)&alpha, g_alpha);
    cudaGetSymbolAddress((void**)&norm, g_norm);

    const float qscale = 0.125f; // DIM_HEAD^-0.5
    const long  smm    = (long)MLAND * MLAND;

    // 0. zero scratch (a3v accum, Araw accum, norm)
    zeros_k<<<(NHEADS * MLAND * DHEAD + 255) / 256, 256>>>(a3v, Araw, norm);

    // 1. qkv = dense @ w_qkv^T  [8192,1536]
    gemmTC(true, NTOK, QKVW, DMODEL, 1.f, dense, DMODEL, 0, w_qkv, DMODEL, 0,
           qkv, QKVW, 0, 1);

    // 2. landmarks
    landmarks_k<<<(NHEADS * MLAND * DHEAD + 255) / 256, 256>>>(qkv, ql, kl);

    // 3. a1 = softmax(scale * q @ k_l^T)   [h,8192,256]
    gemmTC(true, NTOK, MLAND, DHEAD, qscale,
           qkv, QKVW, DHEAD, kl, DHEAD, (long)MLAND * DHEAD,
           a1, MLAND, (long)NTOK * MLAND, NHEADS);
    softmax256_k<<<NHEADS * NTOK, 256>>>(a1);

    // 4. a2 = softmax(scale * q_l @ k_l^T) [h,256,256]
    gemmTC(true, MLAND, MLAND, DHEAD, qscale,
           ql, DHEAD, (long)MLAND * DHEAD, kl, DHEAD, (long)MLAND * DHEAD,
           a2, MLAND, smm, NHEADS);
    softmax256_k<<<NHEADS * MLAND, 256>>>(a2);

    // 5. pinv init
    a2norm_k<<<NHEADS, 256>>>(a2, norm);
    zinit_k<<<(int)((NHEADS * smm + 255) / 256), 256>>>(a2, z, norm);

    // 6. pinv iterations (fp32 SIMT, fused epilogues — measured best)
    float* zin = z; float* zout = z2;
    dim3 gp(4, 4, NHEADS);
    for (int it = 0; it < PITERS; it++) {
        gemm64ep_k<<<gp, 256>>>(1.f, 0.f, a2, zin, xz, -1.f, 7.f, t1);      // xz, 7I-xz
        gemm64ep_k<<<gp, 256>>>(-1.f, 15.f, xz, t1, t2, 0.f, 0.f, nullptr); // 15I - xz@t1
        gemm64ep_k<<<gp, 256>>>(-1.f, 13.f, xz, t2, t1, 0.f, 0.f, nullptr); // 13I - xz@t2
        gemm64ep_k<<<gp, 256>>>(0.25f, 0.f, zin, t1, zout, 0.f, 0.f, nullptr);
        float* tmp = zin; zin = zout; zout = tmp;
    }
    float* zfin = zin;

    // 7. a3 = softmax(scale * q_l @ k^T)  [h,256,8192]
    gemmTC(true, MLAND, NTOK, DHEAD, qscale,
           ql, DHEAD, (long)MLAND * DHEAD,
           qkv + NHEADS * DHEAD, QKVW, DHEAD,
           a3, NTOK, (long)MLAND * NTOK, NHEADS);
    softmax8192_k<<<NHEADS * MLAND, 1024>>>(a3);

    // 8. a3v = a3 @ v  [h,256,64]  (split-K 16, atomic; pre-zeroed)
    gemmT64(MLAND, NTOK, 1.f,
            a3, NTOK, (long)MLAND * NTOK,
            qkv + 2 * NHEADS * DHEAD, QKVW, DHEAD,
            a3v, DHEAD, (long)MLAND * DHEAD, NHEADS, 16);

    // 9. zv = zfin @ a3v  [h,256,64]   (associativity: tiny inner product)
    gemmT64(MLAND, MLAND, 1.f,
            zfin, MLAND, smm,
            a3v, DHEAD, (long)MLAND * DHEAD,
            zv, DHEAD, (long)MLAND * DHEAD, NHEADS, 1);

    // 10. xh[n, h*64:+64] = a1 @ zv    (replaces w1 = a1@zfin; w1@a3v)
    gemmT64(NTOK, MLAND, 1.f,
            a1, MLAND, (long)NTOK * MLAND,
            zv, DHEAD, (long)MLAND * DHEAD,
            xh, DMODEL, DHEAD, NHEADS, 1);

    // 11. residual depthwise conv on v, added into xh
    convadd2_k<<<(NTOK / 8) * DMODEL / 256, 256>>>(qkv, rker, xh);

    // 12. enc = xh @ w_out^T + b_out + dense  (fused epilogue)
    gemmTC(true, NTOK, DMODEL, DMODEL, 1.f, xh, DMODEL, 0, w_out, DMODEL, 0,
           enc, DMODEL, 0, 1, dense, b_out);

    // 13. qe = enc @ wq ; ke = enc @ wk
    gemmTC(false, NTOK, WPD, DMODEL, 1.f, enc, DMODEL, 0, wq, WPD, 0, qe, WPD, 0, 1);
    gemmTC(false, NTOK, WPD, DMODEL, 1.f, enc, DMODEL, 0, wk, WPD, 0, ke, WPD, 0, 1);

    // 14. edge scores -> segment sum (Araw pre-zeroed)
    edge_k<<<(NEDGE + 7) / 8, 256>>>(qe, ke, arows, acols, avals, Araw);

    // 15. alpha = softmax(A_raw) over all N
    softmax_all_k<<<1, 1024>>>(Araw, alpha, NTOK);

    // 16. value = dense @ wv_w^T
    gemmTC(true, NTOK, DMODEL, DMODEL, 1.f, dense, DMODEL, 0, wv_w, DMODEL, 0,
           val, DMODEL, 0, 1);

    // 17. final gated blend + A_raw copy
    final_k<<<(int)(((long)NTOK * DMODEL + 255) / 256), 256>>>(val, wv_b, alpha, enc, Araw, out);
}

// round 11
// speedup vs baseline: 1.5966x; 1.1985x over previous
#include <cuda_runtime.h>
#include <cuda_fp16.h>
#include <math.h>

// ---------------- problem constants ----------------
static const int NTOK   = 8192;   // N
static const int DMODEL = 512;    // D
static const int NHEADS = 8;
static const int DHEAD  = 64;
static const int MLAND  = 256;    // M landmarks
static const int LFOLD  = 32;     // N / M
static const int WPD    = 256;    // weight_params_dim
static const int NEDGE  = 262144; // E
static const int KCONV  = 33;
static const int QKVW   = 3 * NHEADS * DHEAD; // 1536
static const int PITERS = 6;

// ---------------- device scratch (BSS) ----------------
__device__ float g_qkv [NTOK * QKVW];
__device__ float g_ql  [NHEADS * MLAND * DHEAD];
__device__ float g_kl  [NHEADS * MLAND * DHEAD];
__device__ float g_a1  [(long)NHEADS * NTOK * MLAND];
__device__ float g_a2  [NHEADS * MLAND * MLAND];
__device__ float g_a3  [(long)NHEADS * MLAND * NTOK];
__device__ float g_z   [NHEADS * MLAND * MLAND];
__device__ float g_z2  [NHEADS * MLAND * MLAND];
__device__ float g_xz  [NHEADS * MLAND * MLAND];
__device__ float g_t1  [NHEADS * MLAND * MLAND];
__device__ float g_t2  [NHEADS * MLAND * MLAND];
__device__ float g_a3v [NHEADS * MLAND * DHEAD];
__device__ float g_zv  [NHEADS * MLAND * DHEAD];
__device__ float g_xh  [NTOK * DMODEL];
__device__ float g_enc [NTOK * DMODEL];
__device__ float g_val [NTOK * DMODEL];
__device__ float g_qe  [NTOK * WPD];
__device__ float g_ke  [NTOK * WPD];
__device__ float g_wqT [WPD * DMODEL];
__device__ float g_wkT [WPD * DMODEL];
__device__ float g_Araw [NTOK];
__device__ float g_alpha[NTOK];
__device__ unsigned int g_norm[2];

// ---------------- ptx helpers ----------------
__device__ __forceinline__ unsigned sptr(const void* p) {
    return (unsigned)__cvta_generic_to_shared(p);
}
__device__ __forceinline__ void ldsm4(unsigned& r0, unsigned& r1, unsigned& r2,
                                      unsigned& r3, unsigned addr) {
    asm volatile("ldmatrix.sync.aligned.m8n8.x4.shared.b16 {%0,%1,%2,%3}, [%4];"
        : "=r"(r0), "=r"(r1), "=r"(r2), "=r"(r3) : "r"(addr));
}
__device__ __forceinline__ void mma16(float* c, const unsigned* a, const unsigned* b) {
    asm volatile(
        "mma.sync.aligned.m16n8k16.row.col.f32.f16.f16.f32 "
        "{%0,%1,%2,%3}, {%4,%5,%6,%7}, {%8,%9}, {%0,%1,%2,%3};"
        : "+f"(c[0]), "+f"(c[1]), "+f"(c[2]), "+f"(c[3])
        : "r"(a[0]), "r"(a[1]), "r"(a[2]), "r"(a[3]), "r"(b[0]), "r"(b[1]));
}

// split 8 fp32 -> 8 f16 hi-plane + 8 f16 residual-plane (packed uint4 each)
__device__ __forceinline__ void packsplit8(const float4& v0, const float4& v1,
                                           uint4& h, uint4& r)
{
    float v[8];
    *(float4*)v       = v0;
    *(float4*)(v + 4) = v1;
    unsigned hh[4], rr[4];
    #pragma unroll
    for (int i = 0; i < 4; i++) {
        __half2 p = __floats2half2_rn(v[2 * i], v[2 * i + 1]);
        hh[i] = *(unsigned*)&p;
        float lo = __half2float(__low2half(p));
        float hi = __half2float(__high2half(p));
        __half2 q = __floats2half2_rn(v[2 * i] - lo, v[2 * i + 1] - hi);
        rr[i] = *(unsigned*)&q;
    }
    h = make_uint4(hh[0], hh[1], hh[2], hh[3]);
    r = make_uint4(rr[0], rr[1], rr[2], rr[3]);
}

// =====================================================================
// gemmH: fp16x2 tensor GEMM (h/r split, 3 passes of m16n8k16).
// C = alpha * A[M,K] @ B^T (+addC +bias).  B stored [N,K] (TB form).
// CTA tile 128x128xK16-chunks, 256 threads (8 warps 4x2), warp 32x64.
// REQUIRES M%128==0, N%128==0, K%16==0, 16B-aligned rows.
// smem: 4 planes (Ah Ar Bh Br), each 128 rows x 48B (32B data + pad).
// =====================================================================
static const int HROWB = 48;                 // bytes per row (16 halves + pad)
static const int HPLANE = 128 * HROWB;       // 6144 B
__global__ __launch_bounds__(256, 2)
void gemmH_k(int M, int N, int K, float alpha,
             const float* __restrict__ A, int lda, long sA,
             const float* __restrict__ B, int ldb, long sB,
             float* __restrict__ C, int ldc, long sC,
             const float* __restrict__ addC, const float* __restrict__ bias)
{
    __shared__ __align__(16) char smem[4 * HPLANE];  // Ah Ar Bh Br

    A += (long)blockIdx.z * sA;
    B += (long)blockIdx.z * sB;
    C += (long)blockIdx.z * sC;
    if (addC) addC += (long)blockIdx.z * sC;

    const int row0 = blockIdx.y * 128;
    const int col0 = blockIdx.x * 128;
    const int tid  = threadIdx.x;
    const int lane = tid & 31, w = tid >> 5, wr = w >> 1, wc = w & 1;

    // ---- staging assignment: row sr, k-half ci (8 elems) ----
    const int sr = tid >> 1, ci = tid & 1;
    const float* aSrc = A + (long)(row0 + sr) * lda + ci * 8;
    const float* bSrc = B + (long)(col0 + sr) * ldb + ci * 8;
    char* Ah = smem;
    char* Bh = smem + 2 * HPLANE;
    const unsigned stAh = sptr(Ah + sr * HROWB + ci * 16);
    const unsigned stBh = sptr(Bh + sr * HROWB + ci * 16);

    // ---- ldmatrix addresses ----
    // A: lanes 0-15 -> rows base+(lane&15) @k-chunk0; 16-31 same rows @chunk1
    unsigned aLd[2];
    #pragma unroll
    for (int rt = 0; rt < 2; rt++) {
        int rrow = wr * 32 + rt * 16 + (lane & 15);
        aLd[rt] = sptr(Ah + rrow * HROWB + (lane >> 4) * 16);
    }
    // B: n = base + (lane&7) + 8*(lane>=16); chunk = (lane>>3)&1
    unsigned bLd[4];
    #pragma unroll
    for (int p = 0; p < 4; p++) {
        int n = wc * 64 + p * 16 + (lane & 7) + ((lane & 16) >> 1);
        bLd[p] = sptr(Bh + n * HROWB + ((lane >> 3) & 1) * 16);
    }

    float acc[2][8][4];
    #pragma unroll
    for (int i = 0; i < 2; i++)
        #pragma unroll
        for (int j = 0; j < 8; j++)
            #pragma unroll
            for (int v = 0; v < 4; v++) acc[i][j][v] = 0.f;

    const int CH = K >> 4;
    float4 pa0, pa1, pb0, pb1;
    pa0 = *(const float4*)(aSrc);
    pa1 = *(const float4*)(aSrc + 4);
    pb0 = *(const float4*)(bSrc);
    pb1 = *(const float4*)(bSrc + 4);

    for (int c = 0; c < CH; c++) {
        __syncthreads();   // previous compute done; smem writable
        {
            uint4 h, r;
            packsplit8(pa0, pa1, h, r);
            *(uint4*)(Ah + sr * HROWB + ci * 16)          = h;
            *(uint4*)(Ah + HPLANE + sr * HROWB + ci * 16) = r;
            packsplit8(pb0, pb1, h, r);
            *(uint4*)(Bh + sr * HROWB + ci * 16)          = h;
            *(uint4*)(Bh + HPLANE + sr * HROWB + ci * 16) = r;
        }
        if (c + 1 < CH) {
            pa0 = *(const float4*)(aSrc + (c + 1) * 16);
            pa1 = *(const float4*)(aSrc + (c + 1) * 16 + 4);
            pb0 = *(const float4*)(bSrc + (c + 1) * 16);
            pb1 = *(const float4*)(bSrc + (c + 1) * 16 + 4);
        }
        __syncthreads();
        // ---- compute one k16 step ----
        unsigned ah[2][4], ar[2][4];
        #pragma unroll
        for (int rt = 0; rt < 2; rt++) {
            ldsm4(ah[rt][0], ah[rt][1], ah[rt][2], ah[rt][3], aLd[rt]);
            ldsm4(ar[rt][0], ar[rt][1], ar[rt][2], ar[rt][3], aLd[rt] + HPLANE);
        }
        #pragma unroll
        for (int p = 0; p < 4; p++) {
            unsigned bh[4], br[4];
            ldsm4(bh[0], bh[1], bh[2], bh[3], bLd[p]);
            ldsm4(br[0], br[1], br[2], br[3], bLd[p] + HPLANE);
            #pragma unroll
            for (int rt = 0; rt < 2; rt++) {
                mma16(acc[rt][2 * p],     ah[rt], bh);      // h·h
                mma16(acc[rt][2 * p],     ah[rt], br);      // h·r
                mma16(acc[rt][2 * p],     ar[rt], bh);      // r·h
                mma16(acc[rt][2 * p + 1], ah[rt], bh + 2);
                mma16(acc[rt][2 * p + 1], ah[rt], br + 2);
                mma16(acc[rt][2 * p + 1], ar[rt], bh + 2);
            }
        }
    }

    // ---- epilogue (same fragment layout as m16n8k8) ----
    const int g = lane >> 2, tg = lane & 3;
    #pragma unroll
    for (int rt = 0; rt < 2; rt++) {
        #pragma unroll
        for (int n2 = 0; n2 < 8; n2++) {
            int gr = row0 + wr * 32 + rt * 16 + g;
            int gc = col0 + wc * 64 + n2 * 8 + tg * 2;
            float* c = acc[rt][n2];
            long i0 = (long)gr * ldc + gc;
            long i1 = i0 + 8 * (long)ldc;
            float v00 = alpha * c[0], v01 = alpha * c[1];
            float v10 = alpha * c[2], v11 = alpha * c[3];
            if (addC) {
                v00 += addC[i0]; v01 += addC[i0 + 1];
                v10 += addC[i1]; v11 += addC[i1 + 1];
            }
            if (bias) {
                v00 += bias[gc]; v01 += bias[gc + 1];
                v10 += bias[gc]; v11 += bias[gc + 1];
            }
            C[i0] = v00; C[i0 + 1] = v01;
            C[i1] = v10; C[i1 + 1] = v11;
        }
    }
}

static void gemmH(int M, int N, int K, float alpha,
                  const float* A, int lda, long sA,
                  const float* B, int ldb, long sB,
                  float* C, int ldc, long sC, int batch,
                  const float* addC = nullptr, const float* bias = nullptr)
{
    dim3 g(N / 128, M / 128, batch);
    gemmH_k<<<g, 256>>>(M, N, K, alpha, A, lda, sA, B, ldb, sB,
                        C, ldc, sC, addC, bias);
}

// =====================================================================
// tf32x3 mma.sync 128x64 kernel (N=64 GEMMs: a3v split-K, zv, xh)
// =====================================================================
__device__ __forceinline__ unsigned f2tf(float x) {
    unsigned u;
    asm("cvt.rna.tf32.f32 %0, %1;" : "=r"(u) : "f"(x));
    return u;
}
__device__ __forceinline__ void split_u(unsigned x, unsigned& hi, unsigned& lo) {
    float f = __uint_as_float(x);
    hi = f2tf(f);
    lo = f2tf(f - __uint_as_float(hi));
}
__device__ __forceinline__ void mma8(float* c, const unsigned* a, const unsigned* b) {
    asm volatile(
        "mma.sync.aligned.m16n8k8.row.col.f32.tf32.tf32.f32 "
        "{%0,%1,%2,%3}, {%4,%5,%6,%7}, {%8,%9}, {%0,%1,%2,%3};"
        : "+f"(c[0]), "+f"(c[1]), "+f"(c[2]), "+f"(c[3])
        : "r"(a[0]), "r"(a[1]), "r"(a[2]), "r"(a[3]), "r"(b[0]), "r"(b[1]));
}
#define CP16(d, s)  asm volatile("cp.async.ca.shared.global [%0], [%1], 16;" :: "r"(d), "l"(s))
#define CP4(d, s)   asm volatile("cp.async.ca.shared.global [%0], [%1], 4;"  :: "r"(d), "l"(s))
#define CPCOMMIT()  asm volatile("cp.async.commit_group;")
#define CPWAIT1()   asm volatile("cp.async.wait_group 1;")
#define CPWAIT0()   asm volatile("cp.async.wait_group 0;")
__device__ __forceinline__ int prp(int r) { return r + (r >> 3); }
static const int SROWS = 144;
struct StageT { float A[2][2][SROWS][4]; float B[2][2][SROWS][4]; };
static const int NSTAGE = 3;

__global__ __launch_bounds__(256, 2)
void gemmT64_k(int M, int K, float alpha,
               const float* __restrict__ A, int lda, long sA,
               const float* __restrict__ B, int ldb, long sB,
               float* __restrict__ C, int ldc, long sC, int kSplit)
{
    constexpr int BN = 64, WNT = 4, NP = 2, NB = 4;
    int bz = blockIdx.z;
    int batch = bz / kSplit, ks = bz - batch * kSplit;
    A += (long)batch * sA; B += (long)batch * sB; C += (long)batch * sC;
    const int chunk = K / kSplit;
    const int k0s = ks * chunk;
    const int T = chunk >> 4;

    const int row0 = blockIdx.y * 128;
    const int tid = threadIdx.x;
    const int lane = tid & 31, w = tid >> 5, wr = w >> 1, wc = w & 1;

    extern __shared__ __align__(16) char smraw[];
    StageT* sm = reinterpret_cast<StageT*>(smraw);
    const unsigned stageSz = (unsigned)sizeof(StageT);

    const int ar = tid >> 1, akt = tid & 1;
    const float* aSrc = A + (long)(row0 + ar) * lda + akt * 8;
    const unsigned aD0 = sptr(&sm[0].A[akt][0][prp(ar)][0]);
    const unsigned aD1 = sptr(&sm[0].A[akt][1][prp(ar)][0]);

    int n = tid & (BN - 1);
    int kb = (tid >> 6) * NB;
    const float* bSrc = B + (long)kb * ldb + n;
    unsigned bDst[NB];
    #pragma unroll
    for (int j = 0; j < NB; j++) {
        int kk = kb + j;
        bDst[j] = sptr(&sm[0].B[kk >> 3][(kk >> 2) & 1][prp(n)][kk & 3]);
    }

    auto fill = [&](int kAbs, int s) {
        unsigned so = s * stageSz;
        CP16(aD0 + so, aSrc + kAbs);
        CP16(aD1 + so, aSrc + kAbs + 4);
        #pragma unroll
        for (int j = 0; j < NB; j++)
            CP4(bDst[j] + so, bSrc + (long)(kAbs + j) * ldb);
    };

    const int aRow = wr * 32 + (lane & 15);
    const int aKj = lane >> 4;
    unsigned aAdr[2][2];
    #pragma unroll
    for (int kt = 0; kt < 2; kt++)
        #pragma unroll
        for (int rt = 0; rt < 2; rt++)
            aAdr[kt][rt] = sptr(&sm[0].A[kt][aKj][prp(aRow + rt * 16)][0]);
    const int bKj = (lane >> 3) & 1;
    const int bRow = wc * 32 + ((lane & 7) | ((lane & 16) >> 1));
    unsigned bAdr[2][NP];
    #pragma unroll
    for (int kt = 0; kt < 2; kt++)
        #pragma unroll
        for (int p = 0; p < NP; p++)
            bAdr[kt][p] = sptr(&sm[0].B[kt][bKj][prp(bRow + p * 16)][0]);

    float acc[2][WNT][4];
    #pragma unroll
    for (int i = 0; i < 2; i++)
        #pragma unroll
        for (int j = 0; j < WNT; j++)
            #pragma unroll
            for (int v = 0; v < 4; v++) acc[i][j][v] = 0.f;

    auto compute = [&](int s) {
        unsigned so = s * stageSz;
        #pragma unroll
        for (int kt = 0; kt < 2; kt++) {
            unsigned ah[2][4], al[2][4];
            #pragma unroll
            for (int rt = 0; rt < 2; rt++) {
                unsigned r0, r1, r2, r3;
                ldsm4(r0, r1, r2, r3, aAdr[kt][rt] + so);
                split_u(r0, ah[rt][0], al[rt][0]);
                split_u(r1, ah[rt][1], al[rt][1]);
                split_u(r2, ah[rt][2], al[rt][2]);
                split_u(r3, ah[rt][3], al[rt][3]);
            }
            #pragma unroll
            for (int p = 0; p < NP; p++) {
                unsigned r0, r1, r2, r3;
                ldsm4(r0, r1, r2, r3, bAdr[kt][p] + so);
                unsigned bh0[2], bl0[2], bh1[2], bl1[2];
                split_u(r0, bh0[0], bl0[0]);
                split_u(r1, bh0[1], bl0[1]);
                split_u(r2, bh1[0], bl1[0]);
                split_u(r3, bh1[1], bl1[1]);
                #pragma unroll
                for (int rt = 0; rt < 2; rt++) {
                    mma8(acc[rt][2 * p],     ah[rt], bh0);
                    mma8(acc[rt][2 * p],     al[rt], bh0);
                    mma8(acc[rt][2 * p],     ah[rt], bl0);
                    mma8(acc[rt][2 * p + 1], ah[rt], bh1);
                    mma8(acc[rt][2 * p + 1], al[rt], bh1);
                    mma8(acc[rt][2 * p + 1], ah[rt], bl1);
                }
            }
        }
    };

    fill(k0s, 0);
    CPCOMMIT();
    if (T > 1) { fill(k0s + 16, 1); CPCOMMIT(); }
    for (int t = 0; t < T; t++) {
        if (t + 1 < T) CPWAIT1(); else CPWAIT0();
        __syncthreads();
        if (t + 2 < T) { fill(k0s + (t + 2) * 16, (t + 2) % NSTAGE); CPCOMMIT(); }
        compute(t % NSTAGE);
    }

    const int g = lane >> 2, tg = lane & 3;
    #pragma unroll
    for (int rt = 0; rt < 2; rt++) {
        #pragma unroll
        for (int n2 = 0; n2 < WNT; n2++) {
            int gr = row0 + wr * 32 + rt * 16 + g;
            int gc = wc * 32 + n2 * 8 + tg * 2;
            float* c = acc[rt][n2];
            float* p0 = C + (long)gr * ldc + gc;
            float* p1 = p0 + 8 * (long)ldc;
            if (kSplit > 1) {
                atomicAdd(p0 + 0, alpha * c[0]); atomicAdd(p0 + 1, alpha * c[1]);
                atomicAdd(p1 + 0, alpha * c[2]); atomicAdd(p1 + 1, alpha * c[3]);
            } else {
                p0[0] = alpha * c[0]; p0[1] = alpha * c[1];
                p1[0] = alpha * c[2]; p1[1] = alpha * c[3];
            }
        }
    }
}
static const int GT_SMEM = NSTAGE * (int)sizeof(StageT);

static void gemmT64(int M, int K, float alpha,
                    const float* A, int lda, long sA,
                    const float* B, int ldb, long sB,
                    float* C, int ldc, long sC, int batch, int kSplit)
{
    dim3 g(1, M / 128, batch * kSplit);
    cudaFuncSetAttribute(gemmT64_k, cudaFuncAttributeMaxDynamicSharedMemorySize, GT_SMEM);
    gemmT64_k<<<g, 256, GT_SMEM>>>(M, K, alpha, A, lda, sA, B, ldb, sB,
                                   C, ldc, sC, kSplit);
}

// =====================================================================
// gemm64ep: fp32 SIMT pinv GEMM (measured best for 256x256 batch)
// =====================================================================
__global__ __launch_bounds__(256)
void gemm64ep_k(float alpha, float diag,
                const float* __restrict__ A, const float* __restrict__ B,
                float* __restrict__ C,
                float alpha2, float diag2, float* __restrict__ C2)
{
    const long sb = (long)MLAND * MLAND;
    A += blockIdx.z * sb; B += blockIdx.z * sb; C += blockIdx.z * sb;
    if (C2) C2 += blockIdx.z * sb;
    __shared__ float As[64 * 17];
    __shared__ float Bs[16 * 64];
    int tid = threadIdx.x;
    int row0 = blockIdx.y * 64, col0 = blockIdx.x * 64;
    int tx = tid & 15, ty = tid >> 4;
    float acc[4][4] = {};
    for (int kk = 0; kk < 256; kk += 16) {
        #pragma unroll
        for (int i = 0; i < 4; i++) {
            int e = tid + i * 256;
            int r = e >> 4, c = e & 15;
            As[r * 17 + c] = A[(long)(row0 + r) * 256 + kk + c];
        }
        #pragma unroll
        for (int i = 0; i < 4; i++) {
            int e = tid + i * 256;
            int c = e >> 6, n = e & 63;
            Bs[c * 64 + n] = B[(long)(kk + c) * 256 + col0 + n];
        }
        __syncthreads();
        #pragma unroll
        for (int c = 0; c < 16; c++) {
            float a[4], b[4];
            #pragma unroll
            for (int i = 0; i < 4; i++) a[i] = As[(ty * 4 + i) * 17 + c];
            #pragma unroll
            for (int j = 0; j < 4; j++) b[j] = Bs[c * 64 + tx * 4 + j];
            #pragma unroll
            for (int i = 0; i < 4; i++)
                #pragma unroll
                for (int j = 0; j < 4; j++)
                    acc[i][j] = fmaf(a[i], b[j], acc[i][j]);
        }
        __syncthreads();
    }
    #pragma unroll
    for (int i = 0; i < 4; i++) {
        int gr = row0 + ty * 4 + i;
        #pragma unroll
        for (int j = 0; j < 4; j++) {
            int gc = col0 + tx * 4 + j;
            float d = (gr == gc) ? 1.f : 0.f;
            C[(long)gr * 256 + gc] = alpha * acc[i][j] + diag * d;
            if (C2) C2[(long)gr * 256 + gc] = alpha2 * acc[i][j] + diag2 * d;
        }
    }
}

// ---------------- small kernels ----------------
__global__ void transpose_k(const float* __restrict__ S, float* __restrict__ D,
                            int R, int C)
{
    __shared__ float t[32][33];
    int r0 = blockIdx.y * 32, c0 = blockIdx.x * 32;
    int x = threadIdx.x, y0 = threadIdx.y;
    #pragma unroll
    for (int i = y0; i < 32; i += 8)
        t[i][x] = S[(long)(r0 + i) * C + c0 + x];
    __syncthreads();
    #pragma unroll
    for (int i = y0; i < 32; i += 8)
        D[(long)(c0 + i) * R + r0 + x] = t[x][i];
}

__global__ void zeros_k(float* a3v, float* Araw, unsigned int* norm)
{
    long i = (long)blockIdx.x * 256 + threadIdx.x;
    if (i < NHEADS * MLAND * DHEAD) a3v[i] = 0.f;
    if (i < NTOK) Araw[i] = 0.f;
    if (i < 2) norm[i] = 0u;
}

__global__ void landmarks_k(const float* __restrict__ qkv,
                            float* __restrict__ ql, float* __restrict__ kl)
{
    int idx = blockIdx.x * blockDim.x + threadIdx.x;
    if (idx >= NHEADS * MLAND * DHEAD) return;
    int d = idx & 63; int j = (idx >> 6) & 255; int h = idx >> 14;
    const float* qp = qkv + (long)(j * LFOLD) * QKVW + h * DHEAD + d;
    const float* kp = qp + NHEADS * DHEAD;
    float sq = 0.f, sk = 0.f;
    #pragma unroll 4
    for (int t = 0; t < LFOLD; t++) {
        sq += qp[(long)t * QKVW];
        sk += kp[(long)t * QKVW];
    }
    ql[idx] = sq * (1.f / LFOLD);
    kl[idx] = sk * (1.f / LFOLD);
}

__global__ __launch_bounds__(256)
void softmax256_k(float* __restrict__ X)
{
    float* x = X + (long)blockIdx.x * 256;
    int tid = threadIdx.x;
    __shared__ float sm[8];
    float v = x[tid];
    float m = v;
    #pragma unroll
    for (int o = 16; o; o >>= 1) m = fmaxf(m, __shfl_xor_sync(0xffffffffu, m, o));
    if ((tid & 31) == 0) sm[tid >> 5] = m;
    __syncthreads();
    m = sm[0];
    #pragma unroll
    for (int i = 1; i < 8; i++) m = fmaxf(m, sm[i]);
    float e = __expf(v - m);
    float s = e;
    #pragma unroll
    for (int o = 16; o; o >>= 1) s += __shfl_xor_sync(0xffffffffu, s, o);
    __syncthreads();
    if ((tid & 31) == 0) sm[tid >> 5] = s;
    __syncthreads();
    s = sm[0];
    #pragma unroll
    for (int i = 1; i < 8; i++) s += sm[i];
    x[tid] = e * (1.f / s);
}

__global__ __launch_bounds__(1024)
void softmax8192_k(float* __restrict__ X)
{
    float* x = X + (long)blockIdx.x * 8192;
    int tid = threadIdx.x;
    __shared__ float sm[32];
    float4 v0 = *(const float4*)(x + tid * 8);
    float4 v1 = *(const float4*)(x + tid * 8 + 4);
    float m = fmaxf(fmaxf(fmaxf(v0.x, v0.y), fmaxf(v0.z, v0.w)),
                    fmaxf(fmaxf(v1.x, v1.y), fmaxf(v1.z, v1.w)));
    #pragma unroll
    for (int o = 16; o; o >>= 1) m = fmaxf(m, __shfl_xor_sync(0xffffffffu, m, o));
    if ((tid & 31) == 0) sm[tid >> 5] = m;
    __syncthreads();
    m = sm[0];
    #pragma unroll
    for (int i = 1; i < 32; i++) m = fmaxf(m, sm[i]);
    float e0 = __expf(v0.x - m), e1 = __expf(v0.y - m);
    float e2 = __expf(v0.z - m), e3 = __expf(v0.w - m);
    float e4 = __expf(v1.x - m), e5 = __expf(v1.y - m);
    float e6 = __expf(v1.z - m), e7 = __expf(v1.w - m);
    float s = ((e0 + e1) + (e2 + e3)) + ((e4 + e5) + (e6 + e7));
    #pragma unroll
    for (int o = 16; o; o >>= 1) s += __shfl_xor_sync(0xffffffffu, s, o);
    __syncthreads();
    if ((tid & 31) == 0) sm[tid >> 5] = s;
    __syncthreads();
    s = sm[0];
    #pragma unroll
    for (int i = 1; i < 32; i++) s += sm[i];
    float inv = 1.f / s;
    *(float4*)(x + tid * 8)     = make_float4(e0 * inv, e1 * inv, e2 * inv, e3 * inv);
    *(float4*)(x + tid * 8 + 4) = make_float4(e4 * inv, e5 * inv, e6 * inv, e7 * inv);
}

__global__ void a2norm_k(const float* __restrict__ a2, unsigned int* norm)
{
    int h = blockIdx.x; int t = threadIdx.x;
    const float* x = a2 + (long)h * MLAND * MLAND;
    float rs = 0.f, cs = 0.f;
    for (int j = 0; j < MLAND; j++) {
        rs += fabsf(x[t * MLAND + j]);
        cs += fabsf(x[j * MLAND + t]);
    }
    __shared__ float s1[8], s2[8];
    for (int o = 16; o; o >>= 1) {
        rs = fmaxf(rs, __shfl_xor_sync(0xffffffffu, rs, o));
        cs = fmaxf(cs, __shfl_xor_sync(0xffffffffu, cs, o));
    }
    if ((t & 31) == 0) { s1[t >> 5] = rs; s2[t >> 5] = cs; }
    __syncthreads();
    if (t == 0) {
        rs = s1[0]; cs = s2[0];
        for (int w = 1; w < 8; w++) { rs = fmaxf(rs, s1[w]); cs = fmaxf(cs, s2[w]); }
        atomicMax(&norm[0], __float_as_uint(rs));
        atomicMax(&norm[1], __float_as_uint(cs));
    }
}

__global__ void zinit_k(const float* __restrict__ a2, float* __restrict__ z,
                        const unsigned int* __restrict__ norm)
{
    long idx = (long)blockIdx.x * 256 + threadIdx.x;
    if (idx >= (long)NHEADS * MLAND * MLAND) return;
    float inv = 1.f / (__uint_as_float(norm[0]) * __uint_as_float(norm[1]));
    int j = idx & 255; int i = (idx >> 8) & 255; long h = idx >> 16;
    z[idx] = a2[h * 65536 + (long)j * 256 + i] * inv;
}

__global__ __launch_bounds__(256)
void convadd2_k(const float* __restrict__ qkv,
                const float* __restrict__ rker,
                float* __restrict__ xh)
{
    __shared__ float skr[NHEADS * KCONV];
    for (int i = threadIdx.x; i < NHEADS * KCONV; i += 256) skr[i] = rker[i];
    __syncthreads();
    int idx = blockIdx.x * 256 + threadIdx.x;
    int col = idx & 511;
    int ng = idx >> 9;
    if (ng >= NTOK / 8) return;
    long n0 = (long)ng * 8;
    const float* kr = skr + (col >> 6) * KCONV;
    const float* v = qkv + 2 * NHEADS * DHEAD + col;
    float win[40];
    #pragma unroll
    for (int j = 0; j < 40; j++) {
        long r = n0 - 16 + j;
        win[j] = (r >= 0 && r < NTOK) ? v[r * QKVW] : 0.f;
    }
    #pragma unroll
    for (int i = 0; i < 8; i++) {
        float s = 0.f;
        #pragma unroll
        for (int t = 0; t < KCONV; t++) s += kr[t] * win[i + t];
        xh[(n0 + i) * DMODEL + col] += s;
    }
}

__global__ void edge_k(const float* __restrict__ qe, const float* __restrict__ ke,
                       const int* __restrict__ rows, const int* __restrict__ cols,
                       const float* __restrict__ vals, float* __restrict__ Araw)
{
    int e = blockIdx.x * (blockDim.x >> 5) + (threadIdx.x >> 5);
    int lane = threadIdx.x & 31;
    if (e >= NEDGE) return;
    int r = rows[e], c = cols[e];
    const float4* qr = (const float4*)(qe + (long)r * WPD);
    const float4* kc = (const float4*)(ke + (long)c * WPD);
    float s = 0.f;
    #pragma unroll
    for (int i = lane; i < WPD / 4; i += 32) {
        float4 a = qr[i], b = kc[i];
        s += a.x * b.x + a.y * b.y + a.z * b.z + a.w * b.w;
    }
    for (int o = 16; o; o >>= 1) s += __shfl_xor_sync(0xffffffffu, s, o);
    if (lane == 0) atomicAdd(&Araw[r], s * 0.0625f * vals[e]);
}

__global__ void softmax_all_k(const float* __restrict__ A, float* __restrict__ alpha, int n)
{
    __shared__ float sm[32];
    int tid = threadIdx.x;
    float m = -1e30f;
    for (int i = tid; i < n; i += 1024) m = fmaxf(m, A[i]);
    for (int o = 16; o; o >>= 1) m = fmaxf(m, __shfl_xor_sync(0xffffffffu, m, o));
    if ((tid & 31) == 0) sm[tid >> 5] = m;
    __syncthreads();
    if (tid == 0) { float bm = sm[0]; for (int w = 1; w < 32; w++) bm = fmaxf(bm, sm[w]); sm[0] = bm; }
    __syncthreads();
    m = sm[0];
    __syncthreads();
    float s = 0.f;
    for (int i = tid; i < n; i += 1024) s += __expf(A[i] - m);
    for (int o = 16; o; o >>= 1) s += __shfl_xor_sync(0xffffffffu, s, o);
    if ((tid & 31) == 0) sm[tid >> 5] = s;
    __syncthreads();
    if (tid == 0) { float bs = 0.f; for (int w = 0; w < 32; w++) bs += sm[w]; sm[0] = bs; }
    __syncthreads();
    float inv = 1.f / sm[0];
    for (int i = tid; i < n; i += 1024) alpha[i] = __expf(A[i] - m) * inv;
}

__global__ void final_k(const float* __restrict__ val, const float* __restrict__ wvb,
                        const float* __restrict__ alpha, const float* __restrict__ enc,
                        const float* __restrict__ Araw, float* __restrict__ out)
{
    long idx = (long)blockIdx.x * 256 + threadIdx.x;
    long total = (long)NTOK * DMODEL;
    if (idx < total) {
        int col = idx & 511; long n = idx >> 9;
        float v = val[idx] + wvb[col];
        float xl = alpha[n] * v;
        float w = 1.f / (1.f + __expf(xl));
        float sq = w * w;
        float e = enc[idx];
        out[idx] = xl * 2.f * sq + 2.f * e * (1.f - sq);
    }
    if (idx < NTOK) out[total + idx] = Araw[idx];
}

// ---------------- driver ----------------
extern "C" void kernel_launch(void* const* d_in, const int* in_sizes, int n_in,
                              void* d_out, int out_size)
{
    const float* dense  = (const float*)d_in[0];
    const int*   arows  = (const int*)  d_in[1];
    const int*   acols  = (const int*)  d_in[2];
    const float* avals  = (const float*)d_in[3];
    const float* wq     = (const float*)d_in[4];
    const float* wk     = (const float*)d_in[5];
    const float* w_qkv  = (const float*)d_in[6];
    const float* w_out  = (const float*)d_in[7];
    const float* b_out  = (const float*)d_in[8];
    const float* rker   = (const float*)d_in[9];
    const float* wv_w   = (const float*)d_in[10];
    const float* wv_b   = (const float*)d_in[11];
    float* out = (float*)d_out;

    float *qkv, *ql, *kl, *a1, *a2, *a3, *z, *z2, *xz, *t1, *t2, *a3v, *zv;
    float *xh, *enc, *val, *qe, *ke, *wqT, *wkT, *Araw, *alpha;
    unsigned int* norm;
    cudaGetSymbolAddress((void**)&qkv, g_qkv);
    cudaGetSymbolAddress((void**)&ql,  g_ql);
    cudaGetSymbolAddress((void**)&kl,  g_kl);
    cudaGetSymbolAddress((void**)&a1,  g_a1);
    cudaGetSymbolAddress((void**)&a2,  g_a2);
    cudaGetSymbolAddress((void**)&a3,  g_a3);
    cudaGetSymbolAddress((void**)&z,   g_z);
    cudaGetSymbolAddress((void**)&z2,  g_z2);
    cudaGetSymbolAddress((void**)&xz,  g_xz);
    cudaGetSymbolAddress((void**)&t1,  g_t1);
    cudaGetSymbolAddress((void**)&t2,  g_t2);
    cudaGetSymbolAddress((void**)&a3v, g_a3v);
    cudaGetSymbolAddress((void**)&zv,  g_zv);
    cudaGetSymbolAddress((void**)&xh,  g_xh);
    cudaGetSymbolAddress((void**)&enc, g_enc);
    cudaGetSymbolAddress((void**)&val, g_val);
    cudaGetSymbolAddress((void**)&qe,  g_qe);
    cudaGetSymbolAddress((void**)&ke,  g_ke);
    cudaGetSymbolAddress((void**)&wqT, g_wqT);
    cudaGetSymbolAddress((void**)&wkT, g_wkT);
    cudaGetSymbolAddress((void**)&Araw, g_Araw);
    cudaGetSymbolAddress((void**)&alpha, g_alpha);
    cudaGetSymbolAddress((void**)&norm, g_norm);

    const float qscale = 0.125f;
    const long  smm    = (long)MLAND * MLAND;

    // 0. zero scratch + weight transposes (wq,wk -> [WPD, DMODEL])
    zeros_k<<<(NHEADS * MLAND * DHEAD + 255) / 256, 256>>>(a3v, Araw, norm);
    {
        dim3 b(32, 8);
        transpose_k<<<dim3(WPD / 32, DMODEL / 32), b>>>(wq, wqT, DMODEL, WPD);
        transpose_k<<<dim3(WPD / 32, DMODEL / 32), b>>>(wk, wkT, DMODEL, WPD);
    }

    // 1. qkv = dense @ w_qkv^T  [8192,1536]
    gemmH(NTOK, QKVW, DMODEL, 1.f, dense, DMODEL, 0, w_qkv, DMODEL, 0,
          qkv, QKVW, 0, 1);

    // 2. landmarks
    landmarks_k<<<(NHEADS * MLAND * DHEAD + 255) / 256, 256>>>(qkv, ql, kl);

    // 3. a1 = softmax(scale * q @ k_l^T)   [h,8192,256]
    gemmH(NTOK, MLAND, DHEAD, qscale,
          qkv, QKVW, DHEAD, kl, DHEAD, (long)MLAND * DHEAD,
          a1, MLAND, (long)NTOK * MLAND, NHEADS);
    softmax256_k<<<NHEADS * NTOK, 256>>>(a1);

    // 4. a2 = softmax(scale * q_l @ k_l^T) [h,256,256]
    gemmH(MLAND, MLAND, DHEAD, qscale,
          ql, DHEAD, (long)MLAND * DHEAD, kl, DHEAD, (long)MLAND * DHEAD,
          a2, MLAND, smm, NHEADS);
    softmax256_k<<<NHEADS * MLAND, 256>>>(a2);

    // 5. pinv init
    a2norm_k<<<NHEADS, 256>>>(a2, norm);
    zinit_k<<<(int)((NHEADS * smm + 255) / 256), 256>>>(a2, z, norm);

    // 6. pinv iterations (fp32 SIMT — measured best)
    float* zin = z; float* zout = z2;
    dim3 gp(4, 4, NHEADS);
    for (int it = 0; it < PITERS; it++) {
        gemm64ep_k<<<gp, 256>>>(1.f, 0.f, a2, zin, xz, -1.f, 7.f, t1);
        gemm64ep_k<<<gp, 256>>>(-1.f, 15.f, xz, t1, t2, 0.f, 0.f, nullptr);
        gemm64ep_k<<<gp, 256>>>(-1.f, 13.f, xz, t2, t1, 0.f, 0.f, nullptr);
        gemm64ep_k<<<gp, 256>>>(0.25f, 0.f, zin, t1, zout, 0.f, 0.f, nullptr);
        float* tmp = zin; zin = zout; zout = tmp;
    }
    float* zfin = zin;

    // 7. a3 = softmax(scale * q_l @ k^T)  [h,256,8192]
    gemmH(MLAND, NTOK, DHEAD, qscale,
          ql, DHEAD, (long)MLAND * DHEAD,
          qkv + NHEADS * DHEAD, QKVW, DHEAD,
          a3, NTOK, (long)MLAND * NTOK, NHEADS);
    softmax8192_k<<<NHEADS * MLAND, 1024>>>(a3);

    // 8. a3v = a3 @ v  [h,256,64]  (tf32 split-K 16, atomic; pre-zeroed)
    gemmT64(MLAND, NTOK, 1.f,
            a3, NTOK, (long)MLAND * NTOK,
            qkv + 2 * NHEADS * DHEAD, QKVW, DHEAD,
            a3v, DHEAD, (long)MLAND * DHEAD, NHEADS, 16);

    // 9. zv = zfin @ a3v  [h,256,64]
    gemmT64(MLAND, MLAND, 1.f,
            zfin, MLAND, smm,
            a3v, DHEAD, (long)MLAND * DHEAD,
            zv, DHEAD, (long)MLAND * DHEAD, NHEADS, 1);

    // 10. xh[n, h*64:+64] = a1 @ zv
    gemmT64(NTOK, MLAND, 1.f,
            a1, MLAND, (long)NTOK * MLAND,
            zv, DHEAD, (long)MLAND * DHEAD,
            xh, DMODEL, DHEAD, NHEADS, 1);

    // 11. residual depthwise conv on v, added into xh
    convadd2_k<<<(NTOK / 8) * DMODEL / 256, 256>>>(qkv, rker, xh);

    // 12. enc = xh @ w_out^T + b_out + dense  (fused epilogue)
    gemmH(NTOK, DMODEL, DMODEL, 1.f, xh, DMODEL, 0, w_out, DMODEL, 0,
          enc, DMODEL, 0, 1, dense, b_out);

    // 13. qe = enc @ wq ; ke = enc @ wk  (TB via transposed weights)
    gemmH(NTOK, WPD, DMODEL, 1.f, enc, DMODEL, 0, wqT, DMODEL, 0, qe, WPD, 0, 1);
    gemmH(NTOK, WPD, DMODEL, 1.f, enc, DMODEL, 0, wkT, DMODEL, 0, ke, WPD, 0, 1);

    // 14. edge scores -> segment sum
    edge_k<<<(NEDGE + 7) / 8, 256>>>(qe, ke, arows, acols, avals, Araw);

    // 15. alpha = softmax(A_raw)
    softmax_all_k<<<1, 1024>>>(Araw, alpha, NTOK);

    // 16. value = dense @ wv_w^T
    gemmH(NTOK, DMODEL, DMODEL, 1.f, dense, DMODEL, 0, wv_w, DMODEL, 0,
          val, DMODEL, 0, 1);

    // 17. final gated blend + A_raw copy
    final_k<<<(int)(((long)NTOK * DMODEL + 255) / 256), 256>>>(val, wv_b, alpha, enc, Araw, out);
}

// round 12
// speedup vs baseline: 1.6007x; 1.0026x over previous
#include <cuda_runtime.h>
#include <cuda_fp16.h>
#include <math.h>

// ---------------- problem constants ----------------
static const int NTOK   = 8192;   // N
static const int DMODEL = 512;    // D
static const int NHEADS = 8;
static const int DHEAD  = 64;
static const int MLAND  = 256;    // M landmarks
static const int LFOLD  = 32;     // N / M
static const int WPD    = 256;    // weight_params_dim
static const int NEDGE  = 262144; // E
static const int KCONV  = 33;
static const int QKVW   = 3 * NHEADS * DHEAD; // 1536
static const int PITERS = 6;

// ---------------- device scratch (BSS) ----------------
__device__ float g_qkv [NTOK * QKVW];
__device__ float g_ql  [NHEADS * MLAND * DHEAD];
__device__ float g_kl  [NHEADS * MLAND * DHEAD];
__device__ float g_a1  [(long)NHEADS * NTOK * MLAND];
__device__ float g_a2  [NHEADS * MLAND * MLAND];
__device__ float g_a3  [(long)NHEADS * MLAND * NTOK];
__device__ float g_z   [NHEADS * MLAND * MLAND];
__device__ float g_z2  [NHEADS * MLAND * MLAND];
__device__ float g_xz  [NHEADS * MLAND * MLAND];
__device__ float g_t1  [NHEADS * MLAND * MLAND];
__device__ float g_t2  [NHEADS * MLAND * MLAND];
__device__ float g_a3v [NHEADS * MLAND * DHEAD];
__device__ float g_zv  [NHEADS * MLAND * DHEAD];
__device__ float g_xh  [NTOK * DMODEL];
__device__ float g_enc [NTOK * DMODEL];
__device__ float g_val [NTOK * DMODEL];
__device__ float g_qe  [NTOK * WPD];
__device__ float g_ke  [NTOK * WPD];
__device__ float g_wqT [WPD * DMODEL];
__device__ float g_wkT [WPD * DMODEL];
__device__ float g_Araw [NTOK];
__device__ float g_alpha[NTOK];
__device__ unsigned int g_norm[2];

// ---------------- ptx helpers ----------------
__device__ __forceinline__ unsigned sptr(const void* p) {
    return (unsigned)__cvta_generic_to_shared(p);
}
__device__ __forceinline__ void ldsm4(unsigned& r0, unsigned& r1, unsigned& r2,
                                      unsigned& r3, unsigned addr) {
    asm volatile("ldmatrix.sync.aligned.m8n8.x4.shared.b16 {%0,%1,%2,%3}, [%4];"
        : "=r"(r0), "=r"(r1), "=r"(r2), "=r"(r3) : "r"(addr));
}
__device__ __forceinline__ void mma16(float* c, const unsigned* a, const unsigned* b) {
    asm volatile(
        "mma.sync.aligned.m16n8k16.row.col.f32.f16.f16.f32 "
        "{%0,%1,%2,%3}, {%4,%5,%6,%7}, {%8,%9}, {%0,%1,%2,%3};"
        : "+f"(c[0]), "+f"(c[1]), "+f"(c[2]), "+f"(c[3])
        : "r"(a[0]), "r"(a[1]), "r"(a[2]), "r"(a[3]), "r"(b[0]), "r"(b[1]));
}

// split 8 fp32 -> 8 f16 hi-plane + 8 f16 residual-plane (packed uint4 each)
__device__ __forceinline__ void packsplit8(const float4& v0, const float4& v1,
                                           uint4& h, uint4& r)
{
    float v[8];
    *(float4*)v       = v0;
    *(float4*)(v + 4) = v1;
    unsigned hh[4], rr[4];
    #pragma unroll
    for (int i = 0; i < 4; i++) {
        __half2 p = __floats2half2_rn(v[2 * i], v[2 * i + 1]);
        hh[i] = *(unsigned*)&p;
        float lo = __half2float(__low2half(p));
        float hi = __half2float(__high2half(p));
        __half2 q = __floats2half2_rn(v[2 * i] - lo, v[2 * i + 1] - hi);
        rr[i] = *(unsigned*)&q;
    }
    h = make_uint4(hh[0], hh[1], hh[2], hh[3]);
    r = make_uint4(rr[0], rr[1], rr[2], rr[3]);
}

// =====================================================================
// gemmH: fp16x2 tensor GEMM (h/r split, 3 passes of m16n8k16).
// C = alpha * A[M,K] @ B^T (+addC +bias).  B stored [N,K] (TB form).
// CTA tile 128x128, 128 threads = 4 warps, warp tile 64x64.
// Double-buffered smem, ONE barrier per k16 chunk.
// REQUIRES M%128==0, N%128==0, K%16==0, 16B-aligned rows.
// =====================================================================
static const int HROWB  = 48;            // bytes per row (32B halves + pad)
static const int HPLANE = 128 * HROWB;   // 6144 B
static const int HBUF   = 4 * HPLANE;    // Ah Ar Bh Br = 24576 B
__global__ __launch_bounds__(128, 2)
void gemmH_k(int M, int N, int K, float alpha,
             const float* __restrict__ A, int lda, long sA,
             const float* __restrict__ B, int ldb, long sB,
             float* __restrict__ C, int ldc, long sC,
             const float* __restrict__ addC, const float* __restrict__ bias)
{
    __shared__ __align__(16) char smem[2 * HBUF];  // double buffer

    A += (long)blockIdx.z * sA;
    B += (long)blockIdx.z * sB;
    C += (long)blockIdx.z * sC;
    if (addC) addC += (long)blockIdx.z * sC;

    const int row0 = blockIdx.y * 128;
    const int col0 = blockIdx.x * 128;
    const int tid  = threadIdx.x;
    const int lane = tid & 31, w = tid >> 5, wr = w >> 1, wc = w & 1;

    // staging: thread tid handles A row tid and B row tid, full 16-k chunk
    const float* aSrc = A + (long)(row0 + tid) * lda;
    const float* bSrc = B + (long)(col0 + tid) * ldb;

    // per-buffer plane offsets
    // buf b: Ah = b*HBUF, Ar = +HPLANE, Bh = +2*HPLANE, Br = +3*HPLANE
    const unsigned stA = sptr(smem + tid * HROWB);           // + b*HBUF
    const unsigned stB = sptr(smem + 2 * HPLANE + tid * HROWB);

    // ldmatrix addresses (within buffer 0; add b*HBUF at use)
    unsigned aLd[4];
    #pragma unroll
    for (int rt = 0; rt < 4; rt++) {
        int rrow = wr * 64 + rt * 16 + (lane & 15);
        aLd[rt] = sptr(smem + rrow * HROWB + (lane >> 4) * 16);
    }
    unsigned bLd[4];
    #pragma unroll
    for (int p = 0; p < 4; p++) {
        int n = wc * 64 + p * 16 + (lane & 7) + ((lane & 16) >> 1);
        bLd[p] = sptr(smem + 2 * HPLANE + n * HROWB + ((lane >> 3) & 1) * 16);
    }

    float acc[4][8][4];
    #pragma unroll
    for (int i = 0; i < 4; i++)
        #pragma unroll
        for (int j = 0; j < 8; j++)
            #pragma unroll
            for (int v = 0; v < 4; v++) acc[i][j][v] = 0.f;

    const int CH = K >> 4;
    float4 pa0, pa1, pa2, pa3, pb0, pb1, pb2, pb3;
    auto loadRegs = [&](int c) {
        const float* a = aSrc + c * 16;
        const float* b = bSrc + c * 16;
        pa0 = *(const float4*)(a);      pa1 = *(const float4*)(a + 4);
        pa2 = *(const float4*)(a + 8);  pa3 = *(const float4*)(a + 12);
        pb0 = *(const float4*)(b);      pb1 = *(const float4*)(b + 4);
        pb2 = *(const float4*)(b + 8);  pb3 = *(const float4*)(b + 12);
    };
    auto stsAll = [&](int b) {
        unsigned off = b * HBUF;
        uint4 h, r;
        packsplit8(pa0, pa1, h, r);
        *(uint4*)(smem + (stA - sptr(smem)) + off)               = h;
        *(uint4*)(smem + (stA - sptr(smem)) + off + HPLANE)      = r;
        packsplit8(pa2, pa3, h, r);
        *(uint4*)(smem + (stA - sptr(smem)) + off + 16)          = h;
        *(uint4*)(smem + (stA - sptr(smem)) + off + HPLANE + 16) = r;
        packsplit8(pb0, pb1, h, r);
        *(uint4*)(smem + (stB - sptr(smem)) + off)               = h;
        *(uint4*)(smem + (stB - sptr(smem)) + off + HPLANE)      = r;
        packsplit8(pb2, pb3, h, r);
        *(uint4*)(smem + (stB - sptr(smem)) + off + 16)          = h;
        *(uint4*)(smem + (stB - sptr(smem)) + off + HPLANE + 16) = r;
    };

    loadRegs(0);
    for (int c = 0; c < CH; c++) {
        int b = c & 1;
        stsAll(b);
        if (c + 1 < CH) loadRegs(c + 1);   // overlaps barrier + compute below
        __syncthreads();
        unsigned off = b * HBUF;
        // A fragments for this chunk
        unsigned ah[4][4], ar[4][4];
        #pragma unroll
        for (int rt = 0; rt < 4; rt++) {
            ldsm4(ah[rt][0], ah[rt][1], ah[rt][2], ah[rt][3], aLd[rt] + off);
            ldsm4(ar[rt][0], ar[rt][1], ar[rt][2], ar[rt][3],
                  aLd[rt] + off + HPLANE);
        }
        #pragma unroll
        for (int p = 0; p < 4; p++) {
            unsigned bh[4], br[4];
            ldsm4(bh[0], bh[1], bh[2], bh[3], bLd[p] + off);
            ldsm4(br[0], br[1], br[2], br[3], bLd[p] + off + HPLANE);
            #pragma unroll
            for (int rt = 0; rt < 4; rt++) {
                mma16(acc[rt][2 * p],     ah[rt], bh);      // h·h
                mma16(acc[rt][2 * p],     ah[rt], br);      // h·r
                mma16(acc[rt][2 * p],     ar[rt], bh);      // r·h
                mma16(acc[rt][2 * p + 1], ah[rt], bh + 2);
                mma16(acc[rt][2 * p + 1], ah[rt], br + 2);
                mma16(acc[rt][2 * p + 1], ar[rt], bh + 2);
            }
        }
    }

    // ---- epilogue ----
    const int g = lane >> 2, tg = lane & 3;
    #pragma unroll
    for (int rt = 0; rt < 4; rt++) {
        #pragma unroll
        for (int n2 = 0; n2 < 8; n2++) {
            int gr = row0 + wr * 64 + rt * 16 + g;
            int gc = col0 + wc * 64 + n2 * 8 + tg * 2;
            float* c = acc[rt][n2];
            long i0 = (long)gr * ldc + gc;
            long i1 = i0 + 8 * (long)ldc;
            float v00 = alpha * c[0], v01 = alpha * c[1];
            float v10 = alpha * c[2], v11 = alpha * c[3];
            if (addC) {
                v00 += addC[i0]; v01 += addC[i0 + 1];
                v10 += addC[i1]; v11 += addC[i1 + 1];
            }
            if (bias) {
                v00 += bias[gc]; v01 += bias[gc + 1];
                v10 += bias[gc]; v11 += bias[gc + 1];
            }
            C[i0] = v00; C[i0 + 1] = v01;
            C[i1] = v10; C[i1 + 1] = v11;
        }
    }
}

static void gemmH(int M, int N, int K, float alpha,
                  const float* A, int lda, long sA,
                  const float* B, int ldb, long sB,
                  float* C, int ldc, long sC, int batch,
                  const float* addC = nullptr, const float* bias = nullptr)
{
    dim3 g(N / 128, M / 128, batch);
    gemmH_k<<<g, 128>>>(M, N, K, alpha, A, lda, sA, B, ldb, sB,
                        C, ldc, sC, addC, bias);
}

// =====================================================================
// tf32x3 mma.sync 128x64 kernel (N=64 GEMMs: a3v split-K, zv, xh)
// =====================================================================
__device__ __forceinline__ unsigned f2tf(float x) {
    unsigned u;
    asm("cvt.rna.tf32.f32 %0, %1;" : "=r"(u) : "f"(x));
    return u;
}
__device__ __forceinline__ void split_u(unsigned x, unsigned& hi, unsigned& lo) {
    float f = __uint_as_float(x);
    hi = f2tf(f);
    lo = f2tf(f - __uint_as_float(hi));
}
__device__ __forceinline__ void mma8(float* c, const unsigned* a, const unsigned* b) {
    asm volatile(
        "mma.sync.aligned.m16n8k8.row.col.f32.tf32.tf32.f32 "
        "{%0,%1,%2,%3}, {%4,%5,%6,%7}, {%8,%9}, {%0,%1,%2,%3};"
        : "+f"(c[0]), "+f"(c[1]), "+f"(c[2]), "+f"(c[3])
        : "r"(a[0]), "r"(a[1]), "r"(a[2]), "r"(a[3]), "r"(b[0]), "r"(b[1]));
}
#define CP16(d, s)  asm volatile("cp.async.ca.shared.global [%0], [%1], 16;" :: "r"(d), "l"(s))
#define CP4(d, s)   asm volatile("cp.async.ca.shared.global [%0], [%1], 4;"  :: "r"(d), "l"(s))
#define CPCOMMIT()  asm volatile("cp.async.commit_group;")
#define CPWAIT1()   asm volatile("cp.async.wait_group 1;")
#define CPWAIT0()   asm volatile("cp.async.wait_group 0;")
__device__ __forceinline__ int prp(int r) { return r + (r >> 3); }
static const int SROWS = 144;
struct StageT { float A[2][2][SROWS][4]; float B[2][2][SROWS][4]; };
static const int NSTAGE = 3;

__global__ __launch_bounds__(256, 2)
void gemmT64_k(int M, int K, float alpha,
               const float* __restrict__ A, int lda, long sA,
               const float* __restrict__ B, int ldb, long sB,
               float* __restrict__ C, int ldc, long sC, int kSplit)
{
    constexpr int BN = 64, WNT = 4, NP = 2, NB = 4;
    int bz = blockIdx.z;
    int batch = bz / kSplit, ks = bz - batch * kSplit;
    A += (long)batch * sA; B += (long)batch * sB; C += (long)batch * sC;
    const int chunk = K / kSplit;
    const int k0s = ks * chunk;
    const int T = chunk >> 4;

    const int row0 = blockIdx.y * 128;
    const int tid = threadIdx.x;
    const int lane = tid & 31, w = tid >> 5, wr = w >> 1, wc = w & 1;

    extern __shared__ __align__(16) char smraw[];
    StageT* sm = reinterpret_cast<StageT*>(smraw);
    const unsigned stageSz = (unsigned)sizeof(StageT);

    const int ar = tid >> 1, akt = tid & 1;
    const float* aSrc = A + (long)(row0 + ar) * lda + akt * 8;
    const unsigned aD0 = sptr(&sm[0].A[akt][0][prp(ar)][0]);
    const unsigned aD1 = sptr(&sm[0].A[akt][1][prp(ar)][0]);

    int n = tid & (BN - 1);
    int kb = (tid >> 6) * NB;
    const float* bSrc = B + (long)kb * ldb + n;
    unsigned bDst[NB];
    #pragma unroll
    for (int j = 0; j < NB; j++) {
        int kk = kb + j;
        bDst[j] = sptr(&sm[0].B[kk >> 3][(kk >> 2) & 1][prp(n)][kk & 3]);
    }

    auto fill = [&](int kAbs, int s) {
        unsigned so = s * stageSz;
        CP16(aD0 + so, aSrc + kAbs);
        CP16(aD1 + so, aSrc + kAbs + 4);
        #pragma unroll
        for (int j = 0; j < NB; j++)
            CP4(bDst[j] + so, bSrc + (long)(kAbs + j) * ldb);
    };

    const int aRow = wr * 32 + (lane & 15);
    const int aKj = lane >> 4;
    unsigned aAdr[2][2];
    #pragma unroll
    for (int kt = 0; kt < 2; kt++)
        #pragma unroll
        for (int rt = 0; rt < 2; rt++)
            aAdr[kt][rt] = sptr(&sm[0].A[kt][aKj][prp(aRow + rt * 16)][0]);
    const int bKj = (lane >> 3) & 1;
    const int bRow = wc * 32 + ((lane & 7) | ((lane & 16) >> 1));
    unsigned bAdr[2][NP];
    #pragma unroll
    for (int kt = 0; kt < 2; kt++)
        #pragma unroll
        for (int p = 0; p < NP; p++)
            bAdr[kt][p] = sptr(&sm[0].B[kt][bKj][prp(bRow + p * 16)][0]);

    float acc[2][WNT][4];
    #pragma unroll
    for (int i = 0; i < 2; i++)
        #pragma unroll
        for (int j = 0; j < WNT; j++)
            #pragma unroll
            for (int v = 0; v < 4; v++) acc[i][j][v] = 0.f;

    auto compute = [&](int s) {
        unsigned so = s * stageSz;
        #pragma unroll
        for (int kt = 0; kt < 2; kt++) {
            unsigned ah[2][4], al[2][4];
            #pragma unroll
            for (int rt = 0; rt < 2; rt++) {
                unsigned r0, r1, r2, r3;
                ldsm4(r0, r1, r2, r3, aAdr[kt][rt] + so);
                split_u(r0, ah[rt][0], al[rt][0]);
                split_u(r1, ah[rt][1], al[rt][1]);
                split_u(r2, ah[rt][2], al[rt][2]);
                split_u(r3, ah[rt][3], al[rt][3]);
            }
            #pragma unroll
            for (int p = 0; p < NP; p++) {
                unsigned r0, r1, r2, r3;
                ldsm4(r0, r1, r2, r3, bAdr[kt][p] + so);
                unsigned bh0[2], bl0[2], bh1[2], bl1[2];
                split_u(r0, bh0[0], bl0[0]);
                split_u(r1, bh0[1], bl0[1]);
                split_u(r2, bh1[0], bl1[0]);
                split_u(r3, bh1[1], bl1[1]);
                #pragma unroll
                for (int rt = 0; rt < 2; rt++) {
                    mma8(acc[rt][2 * p],     ah[rt], bh0);
                    mma8(acc[rt][2 * p],     al[rt], bh0);
                    mma8(acc[rt][2 * p],     ah[rt], bl0);
                    mma8(acc[rt][2 * p + 1], ah[rt], bh1);
                    mma8(acc[rt][2 * p + 1], al[rt], bh1);
                    mma8(acc[rt][2 * p + 1], ah[rt], bl1);
                }
            }
        }
    };

    fill(k0s, 0);
    CPCOMMIT();
    if (T > 1) { fill(k0s + 16, 1); CPCOMMIT(); }
    for (int t = 0; t < T; t++) {
        if (t + 1 < T) CPWAIT1(); else CPWAIT0();
        __syncthreads();
        if (t + 2 < T) { fill(k0s + (t + 2) * 16, (t + 2) % NSTAGE); CPCOMMIT(); }
        compute(t % NSTAGE);
    }

    const int g = lane >> 2, tg = lane & 3;
    #pragma unroll
    for (int rt = 0; rt < 2; rt++) {
        #pragma unroll
        for (int n2 = 0; n2 < WNT; n2++) {
            int gr = row0 + wr * 32 + rt * 16 + g;
            int gc = wc * 32 + n2 * 8 + tg * 2;
            float* c = acc[rt][n2];
            float* p0 = C + (long)gr * ldc + gc;
            float* p1 = p0 + 8 * (long)ldc;
            if (kSplit > 1) {
                atomicAdd(p0 + 0, alpha * c[0]); atomicAdd(p0 + 1, alpha * c[1]);
                atomicAdd(p1 + 0, alpha * c[2]); atomicAdd(p1 + 1, alpha * c[3]);
            } else {
                p0[0] = alpha * c[0]; p0[1] = alpha * c[1];
                p1[0] = alpha * c[2]; p1[1] = alpha * c[3];
            }
        }
    }
}
static const int GT_SMEM = NSTAGE * (int)sizeof(StageT);

static void gemmT64(int M, int K, float alpha,
                    const float* A, int lda, long sA,
                    const float* B, int ldb, long sB,
                    float* C, int ldc, long sC, int batch, int kSplit)
{
    dim3 g(1, M / 128, batch * kSplit);
    cudaFuncSetAttribute(gemmT64_k, cudaFuncAttributeMaxDynamicSharedMemorySize, GT_SMEM);
    gemmT64_k<<<g, 256, GT_SMEM>>>(M, K, alpha, A, lda, sA, B, ldb, sB,
                                   C, ldc, sC, kSplit);
}

// =====================================================================
// gemm64ep: fp32 SIMT pinv GEMM (measured best for 256x256 batch)
// =====================================================================
__global__ __launch_bounds__(256)
void gemm64ep_k(float alpha, float diag,
                const float* __restrict__ A, const float* __restrict__ B,
                float* __restrict__ C,
                float alpha2, float diag2, float* __restrict__ C2)
{
    const long sb = (long)MLAND * MLAND;
    A += blockIdx.z * sb; B += blockIdx.z * sb; C += blockIdx.z * sb;
    if (C2) C2 += blockIdx.z * sb;
    __shared__ float As[64 * 17];
    __shared__ float Bs[16 * 64];
    int tid = threadIdx.x;
    int row0 = blockIdx.y * 64, col0 = blockIdx.x * 64;
    int tx = tid & 15, ty = tid >> 4;
    float acc[4][4] = {};
    for (int kk = 0; kk < 256; kk += 16) {
        #pragma unroll
        for (int i = 0; i < 4; i++) {
            int e = tid + i * 256;
            int r = e >> 4, c = e & 15;
            As[r * 17 + c] = A[(long)(row0 + r) * 256 + kk + c];
        }
        #pragma unroll
        for (int i = 0; i < 4; i++) {
            int e = tid + i * 256;
            int c = e >> 6, n = e & 63;
            Bs[c * 64 + n] = B[(long)(kk + c) * 256 + col0 + n];
        }
        __syncthreads();
        #pragma unroll
        for (int c = 0; c < 16; c++) {
            float a[4], b[4];
            #pragma unroll
            for (int i = 0; i < 4; i++) a[i] = As[(ty * 4 + i) * 17 + c];
            #pragma unroll
            for (int j = 0; j < 4; j++) b[j] = Bs[c * 64 + tx * 4 + j];
            #pragma unroll
            for (int i = 0; i < 4; i++)
                #pragma unroll
                for (int j = 0; j < 4; j++)
                    acc[i][j] = fmaf(a[i], b[j], acc[i][j]);
        }
        __syncthreads();
    }
    #pragma unroll
    for (int i = 0; i < 4; i++) {
        int gr = row0 + ty * 4 + i;
        #pragma unroll
        for (int j = 0; j < 4; j++) {
            int gc = col0 + tx * 4 + j;
            float d = (gr == gc) ? 1.f : 0.f;
            C[(long)gr * 256 + gc] = alpha * acc[i][j] + diag * d;
            if (C2) C2[(long)gr * 256 + gc] = alpha2 * acc[i][j] + diag2 * d;
        }
    }
}

// ---------------- small kernels ----------------
__global__ void transpose_k(const float* __restrict__ S, float* __restrict__ D,
                            int R, int C)
{
    __shared__ float t[32][33];
    int r0 = blockIdx.y * 32, c0 = blockIdx.x * 32;
    int x = threadIdx.x, y0 = threadIdx.y;
    #pragma unroll
    for (int i = y0; i < 32; i += 8)
        t[i][x] = S[(long)(r0 + i) * C + c0 + x];
    __syncthreads();
    #pragma unroll
    for (int i = y0; i < 32; i += 8)
        D[(long)(c0 + i) * R + r0 + x] = t[x][i];
}

__global__ void zeros_k(float* a3v, float* Araw, unsigned int* norm)
{
    long i = (long)blockIdx.x * 256 + threadIdx.x;
    if (i < NHEADS * MLAND * DHEAD) a3v[i] = 0.f;
    if (i < NTOK) Araw[i] = 0.f;
    if (i < 2) norm[i] = 0u;
}

__global__ void landmarks_k(const float* __restrict__ qkv,
                            float* __restrict__ ql, float* __restrict__ kl)
{
    int idx = blockIdx.x * blockDim.x + threadIdx.x;
    if (idx >= NHEADS * MLAND * DHEAD) return;
    int d = idx & 63; int j = (idx >> 6) & 255; int h = idx >> 14;
    const float* qp = qkv + (long)(j * LFOLD) * QKVW + h * DHEAD + d;
    const float* kp = qp + NHEADS * DHEAD;
    float sq = 0.f, sk = 0.f;
    #pragma unroll 4
    for (int t = 0; t < LFOLD; t++) {
        sq += qp[(long)t * QKVW];
        sk += kp[(long)t * QKVW];
    }
    ql[idx] = sq * (1.f / LFOLD);
    kl[idx] = sk * (1.f / LFOLD);
}

__global__ __launch_bounds__(256)
void softmax256_k(float* __restrict__ X)
{
    float* x = X + (long)blockIdx.x * 256;
    int tid = threadIdx.x;
    __shared__ float sm[8];
    float v = x[tid];
    float m = v;
    #pragma unroll
    for (int o = 16; o; o >>= 1) m = fmaxf(m, __shfl_xor_sync(0xffffffffu, m, o));
    if ((tid & 31) == 0) sm[tid >> 5] = m;
    __syncthreads();
    m = sm[0];
    #pragma unroll
    for (int i = 1; i < 8; i++) m = fmaxf(m, sm[i]);
    float e = __expf(v - m);
    float s = e;
    #pragma unroll
    for (int o = 16; o; o >>= 1) s += __shfl_xor_sync(0xffffffffu, s, o);
    __syncthreads();
    if ((tid & 31) == 0) sm[tid >> 5] = s;
    __syncthreads();
    s = sm[0];
    #pragma unroll
    for (int i = 1; i < 8; i++) s += sm[i];
    x[tid] = e * (1.f / s);
}

__global__ __launch_bounds__(1024)
void softmax8192_k(float* __restrict__ X)
{
    float* x = X + (long)blockIdx.x * 8192;
    int tid = threadIdx.x;
    __shared__ float sm[32];
    float4 v0 = *(const float4*)(x + tid * 8);
    float4 v1 = *(const float4*)(x + tid * 8 + 4);
    float m = fmaxf(fmaxf(fmaxf(v0.x, v0.y), fmaxf(v0.z, v0.w)),
                    fmaxf(fmaxf(v1.x, v1.y), fmaxf(v1.z, v1.w)));
    #pragma unroll
    for (int o = 16; o; o >>= 1) m = fmaxf(m, __shfl_xor_sync(0xffffffffu, m, o));
    if ((tid & 31) == 0) sm[tid >> 5] = m;
    __syncthreads();
    m = sm[0];
    #pragma unroll
    for (int i = 1; i < 32; i++) m = fmaxf(m, sm[i]);
    float e0 = __expf(v0.x - m), e1 = __expf(v0.y - m);
    float e2 = __expf(v0.z - m), e3 = __expf(v0.w - m);
    float e4 = __expf(v1.x - m), e5 = __expf(v1.y - m);
    float e6 = __expf(v1.z - m), e7 = __expf(v1.w - m);
    float s = ((e0 + e1) + (e2 + e3)) + ((e4 + e5) + (e6 + e7));
    #pragma unroll
    for (int o = 16; o; o >>= 1) s += __shfl_xor_sync(0xffffffffu, s, o);
    __syncthreads();
    if ((tid & 31) == 0) sm[tid >> 5] = s;
    __syncthreads();
    s = sm[0];
    #pragma unroll
    for (int i = 1; i < 32; i++) s += sm[i];
    float inv = 1.f / s;
    *(float4*)(x + tid * 8)     = make_float4(e0 * inv, e1 * inv, e2 * inv, e3 * inv);
    *(float4*)(x + tid * 8 + 4) = make_float4(e4 * inv, e5 * inv, e6 * inv, e7 * inv);
}

__global__ void a2norm_k(const float* __restrict__ a2, unsigned int* norm)
{
    int h = blockIdx.x; int t = threadIdx.x;
    const float* x = a2 + (long)h * MLAND * MLAND;
    float rs = 0.f, cs = 0.f;
    for (int j = 0; j < MLAND; j++) {
        rs += fabsf(x[t * MLAND + j]);
        cs += fabsf(x[j * MLAND + t]);
    }
    __shared__ float s1[8], s2[8];
    for (int o = 16; o; o >>= 1) {
        rs = fmaxf(rs, __shfl_xor_sync(0xffffffffu, rs, o));
        cs = fmaxf(cs, __shfl_xor_sync(0xffffffffu, cs, o));
    }
    if ((t & 31) == 0) { s1[t >> 5] = rs; s2[t >> 5] = cs; }
    __syncthreads();
    if (t == 0) {
        rs = s1[0]; cs = s2[0];
        for (int w = 1; w < 8; w++) { rs = fmaxf(rs, s1[w]); cs = fmaxf(cs, s2[w]); }
        atomicMax(&norm[0], __float_as_uint(rs));
        atomicMax(&norm[1], __float_as_uint(cs));
    }
}

__global__ void zinit_k(const float* __restrict__ a2, float* __restrict__ z,
                        const unsigned int* __restrict__ norm)
{
    long idx = (long)blockIdx.x * 256 + threadIdx.x;
    if (idx >= (long)NHEADS * MLAND * MLAND) return;
    float inv = 1.f / (__uint_as_float(norm[0]) * __uint_as_float(norm[1]));
    int j = idx & 255; int i = (idx >> 8) & 255; long h = idx >> 16;
    z[idx] = a2[h * 65536 + (long)j * 256 + i] * inv;
}

__global__ __launch_bounds__(256)
void convadd2_k(const float* __restrict__ qkv,
                const float* __restrict__ rker,
                float* __restrict__ xh)
{
    __shared__ float skr[NHEADS * KCONV];
    for (int i = threadIdx.x; i < NHEADS * KCONV; i += 256) skr[i] = rker[i];
    __syncthreads();
    int idx = blockIdx.x * 256 + threadIdx.x;
    int col = idx & 511;
    int ng = idx >> 9;
    if (ng >= NTOK / 8) return;
    long n0 = (long)ng * 8;
    const float* kr = skr + (col >> 6) * KCONV;
    const float* v = qkv + 2 * NHEADS * DHEAD + col;
    float win[40];
    #pragma unroll
    for (int j = 0; j < 40; j++) {
        long r = n0 - 16 + j;
        win[j] = (r >= 0 && r < NTOK) ? v[r * QKVW] : 0.f;
    }
    #pragma unroll
    for (int i = 0; i < 8; i++) {
        float s = 0.f;
        #pragma unroll
        for (int t = 0; t < KCONV; t++) s += kr[t] * win[i + t];
        xh[(n0 + i) * DMODEL + col] += s;
    }
}

__global__ void edge_k(const float* __restrict__ qe, const float* __restrict__ ke,
                       const int* __restrict__ rows, const int* __restrict__ cols,
                       const float* __restrict__ vals, float* __restrict__ Araw)
{
    int e = blockIdx.x * (blockDim.x >> 5) + (threadIdx.x >> 5);
    int lane = threadIdx.x & 31;
    if (e >= NEDGE) return;
    int r = rows[e], c = cols[e];
    const float4* qr = (const float4*)(qe + (long)r * WPD);
    const float4* kc = (const float4*)(ke + (long)c * WPD);
    float s = 0.f;
    #pragma unroll
    for (int i = lane; i < WPD / 4; i += 32) {
        float4 a = qr[i], b = kc[i];
        s += a.x * b.x + a.y * b.y + a.z * b.z + a.w * b.w;
    }
    for (int o = 16; o; o >>= 1) s += __shfl_xor_sync(0xffffffffu, s, o);
    if (lane == 0) atomicAdd(&Araw[r], s * 0.0625f * vals[e]);
}

__global__ void softmax_all_k(const float* __restrict__ A, float* __restrict__ alpha, int n)
{
    __shared__ float sm[32];
    int tid = threadIdx.x;
    float m = -1e30f;
    for (int i = tid; i < n; i += 1024) m = fmaxf(m, A[i]);
    for (int o = 16; o; o >>= 1) m = fmaxf(m, __shfl_xor_sync(0xffffffffu, m, o));
    if ((tid & 31) == 0) sm[tid >> 5] = m;
    __syncthreads();
    if (tid == 0) { float bm = sm[0]; for (int w = 1; w < 32; w++) bm = fmaxf(bm, sm[w]); sm[0] = bm; }
    __syncthreads();
    m = sm[0];
    __syncthreads();
    float s = 0.f;
    for (int i = tid; i < n; i += 1024) s += __expf(A[i] - m);
    for (int o = 16; o; o >>= 1) s += __shfl_xor_sync(0xffffffffu, s, o);
    if ((tid & 31) == 0) sm[tid >> 5] = s;
    __syncthreads();
    if (tid == 0) { float bs = 0.f; for (int w = 0; w < 32; w++) bs += sm[w]; sm[0] = bs; }
    __syncthreads();
    float inv = 1.f / sm[0];
    for (int i = tid; i < n; i += 1024) alpha[i] = __expf(A[i] - m) * inv;
}

__global__ void final_k(const float* __restrict__ val, const float* __restrict__ wvb,
                        const float* __restrict__ alpha, const float* __restrict__ enc,
                        const float* __restrict__ Araw, float* __restrict__ out)
{
    long idx = (long)blockIdx.x * 256 + threadIdx.x;
    long total = (long)NTOK * DMODEL;
    if (idx < total) {
        int col = idx & 511; long n = idx >> 9;
        float v = val[idx] + wvb[col];
        float xl = alpha[n] * v;
        float w = 1.f / (1.f + __expf(xl));
        float sq = w * w;
        float e = enc[idx];
        out[idx] = xl * 2.f * sq + 2.f * e * (1.f - sq);
    }
    if (idx < NTOK) out[total + idx] = Araw[idx];
}

// ---------------- driver ----------------
extern "C" void kernel_launch(void* const* d_in, const int* in_sizes, int n_in,
                              void* d_out, int out_size)
{
    const float* dense  = (const float*)d_in[0];
    const int*   arows  = (const int*)  d_in[1];
    const int*   acols  = (const int*)  d_in[2];
    const float* avals  = (const float*)d_in[3];
    const float* wq     = (const float*)d_in[4];
    const float* wk     = (const float*)d_in[5];
    const float* w_qkv  = (const float*)d_in[6];
    const float* w_out  = (const float*)d_in[7];
    const float* b_out  = (const float*)d_in[8];
    const float* rker   = (const float*)d_in[9];
    const float* wv_w   = (const float*)d_in[10];
    const float* wv_b   = (const float*)d_in[11];
    float* out = (float*)d_out;

    float *qkv, *ql, *kl, *a1, *a2, *a3, *z, *z2, *xz, *t1, *t2, *a3v, *zv;
    float *xh, *enc, *val, *qe, *ke, *wqT, *wkT, *Araw, *alpha;
    unsigned int* norm;
    cudaGetSymbolAddress((void**)&qkv, g_qkv);
    cudaGetSymbolAddress((void**)&ql,  g_ql);
    cudaGetSymbolAddress((void**)&kl,  g_kl);
    cudaGetSymbolAddress((void**)&a1,  g_a1);
    cudaGetSymbolAddress((void**)&a2,  g_a2);
    cudaGetSymbolAddress((void**)&a3,  g_a3);
    cudaGetSymbolAddress((void**)&z,   g_z);
    cudaGetSymbolAddress((void**)&z2,  g_z2);
    cudaGetSymbolAddress((void**)&xz,  g_xz);
    cudaGetSymbolAddress((void**)&t1,  g_t1);
    cudaGetSymbolAddress((void**)&t2,  g_t2);
    cudaGetSymbolAddress((void**)&a3v, g_a3v);
    cudaGetSymbolAddress((void**)&zv,  g_zv);
    cudaGetSymbolAddress((void**)&xh,  g_xh);
    cudaGetSymbolAddress((void**)&enc, g_enc);
    cudaGetSymbolAddress((void**)&val, g_val);
    cudaGetSymbolAddress((void**)&qe,  g_qe);
    cudaGetSymbolAddress((void**)&ke,  g_ke);
    cudaGetSymbolAddress((void**)&wqT, g_wqT);
    cudaGetSymbolAddress((void**)&wkT, g_wkT);
    cudaGetSymbolAddress((void**)&Araw, g_Araw);
    cudaGetSymbolAddress((void**)&alpha, g_alpha);
    cudaGetSymbolAddress((void**)&norm, g_norm);

    const float qscale = 0.125f;
    const long  smm    = (long)MLAND * MLAND;

    // 0. zero scratch + weight transposes (wq,wk -> [WPD, DMODEL])
    zeros_k<<<(NHEADS * MLAND * DHEAD + 255) / 256, 256>>>(a3v, Araw, norm);
    {
        dim3 b(32, 8);
        transpose_k<<<dim3(WPD / 32, DMODEL / 32), b>>>(wq, wqT, DMODEL, WPD);
        transpose_k<<<dim3(WPD / 32, DMODEL / 32), b>>>(wk, wkT, DMODEL, WPD);
    }

    // 1. qkv = dense @ w_qkv^T  [8192,1536]
    gemmH(NTOK, QKVW, DMODEL, 1.f, dense, DMODEL, 0, w_qkv, DMODEL, 0,
          qkv, QKVW, 0, 1);

    // 2. landmarks
    landmarks_k<<<(NHEADS * MLAND * DHEAD + 255) / 256, 256>>>(qkv, ql, kl);

    // 3. a1 = softmax(scale * q @ k_l^T)   [h,8192,256]
    gemmH(NTOK, MLAND, DHEAD, qscale,
          qkv, QKVW, DHEAD, kl, DHEAD, (long)MLAND * DHEAD,
          a1, MLAND, (long)NTOK * MLAND, NHEADS);
    softmax256_k<<<NHEADS * NTOK, 256>>>(a1);

    // 4. a2 = softmax(scale * q_l @ k_l^T) [h,256,256]
    gemmH(MLAND, MLAND, DHEAD, qscale,
          ql, DHEAD, (long)MLAND * DHEAD, kl, DHEAD, (long)MLAND * DHEAD,
          a2, MLAND, smm, NHEADS);
    softmax256_k<<<NHEADS * MLAND, 256>>>(a2);

    // 5. pinv init
    a2norm_k<<<NHEADS, 256>>>(a2, norm);
    zinit_k<<<(int)((NHEADS * smm + 255) / 256), 256>>>(a2, z, norm);

    // 6. pinv iterations (fp32 SIMT — measured best)
    float* zin = z; float* zout = z2;
    dim3 gp(4, 4, NHEADS);
    for (int it = 0; it < PITERS; it++) {
        gemm64ep_k<<<gp, 256>>>(1.f, 0.f, a2, zin, xz, -1.f, 7.f, t1);
        gemm64ep_k<<<gp, 256>>>(-1.f, 15.f, xz, t1, t2, 0.f, 0.f, nullptr);
        gemm64ep_k<<<gp, 256>>>(-1.f, 13.f, xz, t2, t1, 0.f, 0.f, nullptr);
        gemm64ep_k<<<gp, 256>>>(0.25f, 0.f, zin, t1, zout, 0.f, 0.f, nullptr);
        float* tmp = zin; zin = zout; zout = tmp;
    }
    float* zfin = zin;

    // 7. a3 = softmax(scale * q_l @ k^T)  [h,256,8192]
    gemmH(MLAND, NTOK, DHEAD, qscale,
          ql, DHEAD, (long)MLAND * DHEAD,
          qkv + NHEADS * DHEAD, QKVW, DHEAD,
          a3, NTOK, (long)MLAND * NTOK, NHEADS);
    softmax8192_k<<<NHEADS * MLAND, 1024>>>(a3);

    // 8. a3v = a3 @ v  [h,256,64]  (tf32 split-K 16, atomic; pre-zeroed)
    gemmT64(MLAND, NTOK, 1.f,
            a3, NTOK, (long)MLAND * NTOK,
            qkv + 2 * NHEADS * DHEAD, QKVW, DHEAD,
            a3v, DHEAD, (long)MLAND * DHEAD, NHEADS, 16);

    // 9. zv = zfin @ a3v  [h,256,64]
    gemmT64(MLAND, MLAND, 1.f,
            zfin, MLAND, smm,
            a3v, DHEAD, (long)MLAND * DHEAD,
            zv, DHEAD, (long)MLAND * DHEAD, NHEADS, 1);

    // 10. xh[n, h*64:+64] = a1 @ zv
    gemmT64(NTOK, MLAND, 1.f,
            a1, MLAND, (long)NTOK * MLAND,
            zv, DHEAD, (long)MLAND * DHEAD,
            xh, DMODEL, DHEAD, NHEADS, 1);

    // 11. residual depthwise conv on v, added into xh
    convadd2_k<<<(NTOK / 8) * DMODEL / 256, 256>>>(qkv, rker, xh);

    // 12. enc = xh @ w_out^T + b_out + dense  (fused epilogue)
    gemmH(NTOK, DMODEL, DMODEL, 1.f, xh, DMODEL, 0, w_out, DMODEL, 0,
          enc, DMODEL, 0, 1, dense, b_out);

    // 13. qe = enc @ wq ; ke = enc @ wk  (TB via transposed weights)
    gemmH(NTOK, WPD, DMODEL, 1.f, enc, DMODEL, 0, wqT, DMODEL, 0, qe, WPD, 0, 1);
    gemmH(NTOK, WPD, DMODEL, 1.f, enc, DMODEL, 0, wkT, DMODEL, 0, ke, WPD, 0, 1);

    // 14. edge scores -> segment sum
    edge_k<<<(NEDGE + 7) / 8, 256>>>(qe, ke, arows, acols, avals, Araw);

    // 15. alpha = softmax(A_raw)
    softmax_all_k<<<1, 1024>>>(Araw, alpha, NTOK);

    // 16. value = dense @ wv_w^T
    gemmH(NTOK, DMODEL, DMODEL, 1.f, dense, DMODEL, 0, wv_w, DMODEL, 0,
          val, DMODEL, 0, 1);

    // 17. final gated blend + A_raw copy
    final_k<<<(int)(((long)NTOK * DMODEL + 255) / 256), 256>>>(val, wv_b, alpha, enc, Araw, out);
}

// round 13
// speedup vs baseline: 1.8497x; 1.1555x over previous
#include <cuda_runtime.h>
#include <cuda_fp16.h>
#include <math.h>

// ---------------- problem constants ----------------
static const int NTOK   = 8192;   // N
static const int DMODEL = 512;    // D
static const int NHEADS = 8;
static const int DHEAD  = 64;
static const int MLAND  = 256;    // M landmarks
static const int LFOLD  = 32;     // N / M
static const int WPD    = 256;    // weight_params_dim
static const int NEDGE  = 262144; // E
static const int KCONV  = 33;
static const int QKVW   = 3 * NHEADS * DHEAD; // 1536
static const int PITERS = 6;

// ---------------- device scratch (BSS) ----------------
__device__ float g_qkv [NTOK * QKVW];
__device__ float g_ql  [NHEADS * MLAND * DHEAD];
__device__ float g_kl  [NHEADS * MLAND * DHEAD];
__device__ float g_a1  [(long)NHEADS * NTOK * MLAND];
__device__ float g_a2  [NHEADS * MLAND * MLAND];
__device__ float g_a3  [(long)NHEADS * MLAND * NTOK];
__device__ float g_z   [NHEADS * MLAND * MLAND];
__device__ float g_zT  [NHEADS * MLAND * MLAND];
__device__ float g_z2  [NHEADS * MLAND * MLAND];
__device__ float g_z2T [NHEADS * MLAND * MLAND];
__device__ float g_xz  [NHEADS * MLAND * MLAND];
__device__ float g_t1  [NHEADS * MLAND * MLAND];
__device__ float g_t1T [NHEADS * MLAND * MLAND];
__device__ float g_t2  [NHEADS * MLAND * MLAND];
__device__ float g_t2T [NHEADS * MLAND * MLAND];
__device__ float g_a3v [NHEADS * MLAND * DHEAD];
__device__ float g_zv  [NHEADS * MLAND * DHEAD];
__device__ float g_xh  [NTOK * DMODEL];
__device__ float g_enc [NTOK * DMODEL];
__device__ float g_val [NTOK * DMODEL];
__device__ float g_qe  [NTOK * WPD];
__device__ float g_ke  [NTOK * WPD];
__device__ float g_wqT [WPD * DMODEL];
__device__ float g_wkT [WPD * DMODEL];
__device__ float g_Araw [NTOK];
__device__ float g_alpha[NTOK];
__device__ unsigned int g_norm[2];

// ---------------- ptx helpers ----------------
__device__ __forceinline__ unsigned sptr(const void* p) {
    return (unsigned)__cvta_generic_to_shared(p);
}
__device__ __forceinline__ void ldsm4(unsigned& r0, unsigned& r1, unsigned& r2,
                                      unsigned& r3, unsigned addr) {
    asm volatile("ldmatrix.sync.aligned.m8n8.x4.shared.b16 {%0,%1,%2,%3}, [%4];"
        : "=r"(r0), "=r"(r1), "=r"(r2), "=r"(r3) : "r"(addr));
}
__device__ __forceinline__ void mma16(float* c, const unsigned* a, const unsigned* b) {
    asm volatile(
        "mma.sync.aligned.m16n8k16.row.col.f32.f16.f16.f32 "
        "{%0,%1,%2,%3}, {%4,%5,%6,%7}, {%8,%9}, {%0,%1,%2,%3};"
        : "+f"(c[0]), "+f"(c[1]), "+f"(c[2]), "+f"(c[3])
        : "r"(a[0]), "r"(a[1]), "r"(a[2]), "r"(a[3]), "r"(b[0]), "r"(b[1]));
}

// split 8 fp32 -> 8 f16 hi-plane + 8 f16 residual-plane (packed uint4 each)
__device__ __forceinline__ void packsplit8(const float4& v0, const float4& v1,
                                           uint4& h, uint4& r)
{
    float v[8];
    *(float4*)v       = v0;
    *(float4*)(v + 4) = v1;
    unsigned hh[4], rr[4];
    #pragma unroll
    for (int i = 0; i < 4; i++) {
        __half2 p = __floats2half2_rn(v[2 * i], v[2 * i + 1]);
        hh[i] = *(unsigned*)&p;
        float lo = __half2float(__low2half(p));
        float hi = __half2float(__high2half(p));
        __half2 q = __floats2half2_rn(v[2 * i] - lo, v[2 * i + 1] - hi);
        rr[i] = *(unsigned*)&q;
    }
    h = make_uint4(hh[0], hh[1], hh[2], hh[3]);
    r = make_uint4(rr[0], rr[1], rr[2], rr[3]);
}

// =====================================================================
// gemmH: fp16x2 tensor GEMM (h/r split, 3 passes of m16n8k16).
// C = alpha * A[M,K] @ B^T (+addC +bias).  B stored [N,K] (TB form).
// CTA tile 128x128, 128 threads = 4 warps, warp tile 64x64.
// Double-buffered smem, ONE barrier per k16 chunk.  (R12, measured best)
// =====================================================================
static const int HROWB  = 48;            // bytes per row (32B halves + pad)
static const int HPLANE = 128 * HROWB;   // 6144 B
static const int HBUF   = 4 * HPLANE;    // Ah Ar Bh Br = 24576 B
__global__ __launch_bounds__(128, 2)
void gemmH_k(int M, int N, int K, float alpha,
             const float* __restrict__ A, int lda, long sA,
             const float* __restrict__ B, int ldb, long sB,
             float* __restrict__ C, int ldc, long sC,
             const float* __restrict__ addC, const float* __restrict__ bias)
{
    __shared__ __align__(16) char smem[2 * HBUF];  // double buffer

    A += (long)blockIdx.z * sA;
    B += (long)blockIdx.z * sB;
    C += (long)blockIdx.z * sC;
    if (addC) addC += (long)blockIdx.z * sC;

    const int row0 = blockIdx.y * 128;
    const int col0 = blockIdx.x * 128;
    const int tid  = threadIdx.x;
    const int lane = tid & 31, w = tid >> 5, wr = w >> 1, wc = w & 1;

    const float* aSrc = A + (long)(row0 + tid) * lda;
    const float* bSrc = B + (long)(col0 + tid) * ldb;

    const unsigned stA = sptr(smem + tid * HROWB);
    const unsigned stB = sptr(smem + 2 * HPLANE + tid * HROWB);

    unsigned aLd[4];
    #pragma unroll
    for (int rt = 0; rt < 4; rt++) {
        int rrow = wr * 64 + rt * 16 + (lane & 15);
        aLd[rt] = sptr(smem + rrow * HROWB + (lane >> 4) * 16);
    }
    unsigned bLd[4];
    #pragma unroll
    for (int p = 0; p < 4; p++) {
        int n = wc * 64 + p * 16 + (lane & 7) + ((lane & 16) >> 1);
        bLd[p] = sptr(smem + 2 * HPLANE + n * HROWB + ((lane >> 3) & 1) * 16);
    }

    float acc[4][8][4];
    #pragma unroll
    for (int i = 0; i < 4; i++)
        #pragma unroll
        for (int j = 0; j < 8; j++)
            #pragma unroll
            for (int v = 0; v < 4; v++) acc[i][j][v] = 0.f;

    const int CH = K >> 4;
    float4 pa0, pa1, pa2, pa3, pb0, pb1, pb2, pb3;
    auto loadRegs = [&](int c) {
        const float* a = aSrc + c * 16;
        const float* b = bSrc + c * 16;
        pa0 = *(const float4*)(a);      pa1 = *(const float4*)(a + 4);
        pa2 = *(const float4*)(a + 8);  pa3 = *(const float4*)(a + 12);
        pb0 = *(const float4*)(b);      pb1 = *(const float4*)(b + 4);
        pb2 = *(const float4*)(b + 8);  pb3 = *(const float4*)(b + 12);
    };
    auto stsAll = [&](int b) {
        unsigned off = b * HBUF;
        uint4 h, r;
        packsplit8(pa0, pa1, h, r);
        *(uint4*)(smem + (stA - sptr(smem)) + off)               = h;
        *(uint4*)(smem + (stA - sptr(smem)) + off + HPLANE)      = r;
        packsplit8(pa2, pa3, h, r);
        *(uint4*)(smem + (stA - sptr(smem)) + off + 16)          = h;
        *(uint4*)(smem + (stA - sptr(smem)) + off + HPLANE + 16) = r;
        packsplit8(pb0, pb1, h, r);
        *(uint4*)(smem + (stB - sptr(smem)) + off)               = h;
        *(uint4*)(smem + (stB - sptr(smem)) + off + HPLANE)      = r;
        packsplit8(pb2, pb3, h, r);
        *(uint4*)(smem + (stB - sptr(smem)) + off + 16)          = h;
        *(uint4*)(smem + (stB - sptr(smem)) + off + HPLANE + 16) = r;
    };

    loadRegs(0);
    for (int c = 0; c < CH; c++) {
        int b = c & 1;
        stsAll(b);
        if (c + 1 < CH) loadRegs(c + 1);
        __syncthreads();
        unsigned off = b * HBUF;
        unsigned ah[4][4], ar[4][4];
        #pragma unroll
        for (int rt = 0; rt < 4; rt++) {
            ldsm4(ah[rt][0], ah[rt][1], ah[rt][2], ah[rt][3], aLd[rt] + off);
            ldsm4(ar[rt][0], ar[rt][1], ar[rt][2], ar[rt][3],
                  aLd[rt] + off + HPLANE);
        }
        #pragma unroll
        for (int p = 0; p < 4; p++) {
            unsigned bh[4], br[4];
            ldsm4(bh[0], bh[1], bh[2], bh[3], bLd[p] + off);
            ldsm4(br[0], br[1], br[2], br[3], bLd[p] + off + HPLANE);
            #pragma unroll
            for (int rt = 0; rt < 4; rt++) {
                mma16(acc[rt][2 * p],     ah[rt], bh);
                mma16(acc[rt][2 * p],     ah[rt], br);
                mma16(acc[rt][2 * p],     ar[rt], bh);
                mma16(acc[rt][2 * p + 1], ah[rt], bh + 2);
                mma16(acc[rt][2 * p + 1], ah[rt], br + 2);
                mma16(acc[rt][2 * p + 1], ar[rt], bh + 2);
            }
        }
    }

    const int g = lane >> 2, tg = lane & 3;
    #pragma unroll
    for (int rt = 0; rt < 4; rt++) {
        #pragma unroll
        for (int n2 = 0; n2 < 8; n2++) {
            int gr = row0 + wr * 64 + rt * 16 + g;
            int gc = col0 + wc * 64 + n2 * 8 + tg * 2;
            float* c = acc[rt][n2];
            long i0 = (long)gr * ldc + gc;
            long i1 = i0 + 8 * (long)ldc;
            float v00 = alpha * c[0], v01 = alpha * c[1];
            float v10 = alpha * c[2], v11 = alpha * c[3];
            if (addC) {
                v00 += addC[i0]; v01 += addC[i0 + 1];
                v10 += addC[i1]; v11 += addC[i1 + 1];
            }
            if (bias) {
                v00 += bias[gc]; v01 += bias[gc + 1];
                v10 += bias[gc]; v11 += bias[gc + 1];
            }
            C[i0] = v00; C[i0 + 1] = v01;
            C[i1] = v10; C[i1 + 1] = v11;
        }
    }
}

static void gemmH(int M, int N, int K, float alpha,
                  const float* A, int lda, long sA,
                  const float* B, int ldb, long sB,
                  float* C, int ldc, long sC, int batch,
                  const float* addC = nullptr, const float* bias = nullptr)
{
    dim3 g(N / 128, M / 128, batch);
    gemmH_k<<<g, 128>>>(M, N, K, alpha, A, lda, sA, B, ldb, sB,
                        C, ldc, sC, addC, bias);
}

// =====================================================================
// gemmHP: fp16x2 pinv GEMM. 64x64 CTA tile, K=256, batched [256,256].
// C  = alpha *(A@B'^T) + diag*I   (+ optional transposed copy CT)
// C2 = alpha2*(A@B'^T) + diag2*I  (+ optional C2T).  B' is [N,K] row-major.
// grid (4,4,8) = 128 CTAs; 128 threads = 4 warps (2x2), warp tile 32x32.
// =====================================================================
static const int PROWB  = 48;
static const int PPLANE = 64 * PROWB;    // 3072 B
static const int PBUF   = 4 * PPLANE;    // 12288 B
__global__ __launch_bounds__(128, 3)
void gemmHP_k(float alpha, float diag,
              const float* __restrict__ A, const float* __restrict__ B,
              float* __restrict__ C, float* __restrict__ CT,
              float alpha2, float diag2,
              float* __restrict__ C2, float* __restrict__ C2T)
{
    __shared__ __align__(16) char smem[2 * PBUF];

    const long sb = (long)MLAND * MLAND;
    A += blockIdx.z * sb; B += blockIdx.z * sb; C += blockIdx.z * sb;
    if (CT)  CT  += blockIdx.z * sb;
    if (C2)  C2  += blockIdx.z * sb;
    if (C2T) C2T += blockIdx.z * sb;

    const int row0 = blockIdx.y * 64;
    const int col0 = blockIdx.x * 64;
    const int tid  = threadIdx.x;
    const int lane = tid & 31, w = tid >> 5, wr = w >> 1, wc = w & 1;

    // staging: t<64 -> A row t; t>=64 -> B row t-64
    const int  sr    = tid & 63;
    const bool isB   = tid >= 64;
    const float* src = isB ? (B + (long)(col0 + sr) * MLAND)
                           : (A + (long)(row0 + sr) * MLAND);
    const unsigned stOff = (isB ? 2 * PPLANE : 0) + sr * PROWB;

    unsigned aLd[2];
    #pragma unroll
    for (int rt = 0; rt < 2; rt++) {
        int rrow = wr * 32 + rt * 16 + (lane & 15);
        aLd[rt] = sptr(smem + rrow * PROWB + (lane >> 4) * 16);
    }
    unsigned bLd[2];
    #pragma unroll
    for (int p = 0; p < 2; p++) {
        int n = wc * 32 + p * 16 + (lane & 7) + ((lane & 16) >> 1);
        bLd[p] = sptr(smem + 2 * PPLANE + n * PROWB + ((lane >> 3) & 1) * 16);
    }

    float acc[2][4][4];
    #pragma unroll
    for (int i = 0; i < 2; i++)
        #pragma unroll
        for (int j = 0; j < 4; j++)
            #pragma unroll
            for (int v = 0; v < 4; v++) acc[i][j][v] = 0.f;

    const int CH = MLAND >> 4;  // 16
    float4 p0, p1, p2, p3;
    auto loadRegs = [&](int c) {
        const float* s = src + c * 16;
        p0 = *(const float4*)(s);     p1 = *(const float4*)(s + 4);
        p2 = *(const float4*)(s + 8); p3 = *(const float4*)(s + 12);
    };
    auto stsAll = [&](int b) {
        unsigned off = b * PBUF + stOff;
        uint4 h, r;
        packsplit8(p0, p1, h, r);
        *(uint4*)(smem + off)               = h;
        *(uint4*)(smem + off + PPLANE)      = r;
        packsplit8(p2, p3, h, r);
        *(uint4*)(smem + off + 16)          = h;
        *(uint4*)(smem + off + PPLANE + 16) = r;
    };

    loadRegs(0);
    for (int c = 0; c < CH; c++) {
        int b = c & 1;
        stsAll(b);
        if (c + 1 < CH) loadRegs(c + 1);
        __syncthreads();
        unsigned off = b * PBUF;
        unsigned ah[2][4], ar[2][4];
        #pragma unroll
        for (int rt = 0; rt < 2; rt++) {
            ldsm4(ah[rt][0], ah[rt][1], ah[rt][2], ah[rt][3], aLd[rt] + off);
            ldsm4(ar[rt][0], ar[rt][1], ar[rt][2], ar[rt][3],
                  aLd[rt] + off + PPLANE);
        }
        #pragma unroll
        for (int p = 0; p < 2; p++) {
            unsigned bh[4], br[4];
            ldsm4(bh[0], bh[1], bh[2], bh[3], bLd[p] + off);
            ldsm4(br[0], br[1], br[2], br[3], bLd[p] + off + PPLANE);
            #pragma unroll
            for (int rt = 0; rt < 2; rt++) {
                mma16(acc[rt][2 * p],     ah[rt], bh);
                mma16(acc[rt][2 * p],     ah[rt], br);
                mma16(acc[rt][2 * p],     ar[rt], bh);
                mma16(acc[rt][2 * p + 1], ah[rt], bh + 2);
                mma16(acc[rt][2 * p + 1], ah[rt], br + 2);
                mma16(acc[rt][2 * p + 1], ar[rt], bh + 2);
            }
        }
    }

    const int g = lane >> 2, tg = lane & 3;
    #pragma unroll
    for (int rt = 0; rt < 2; rt++) {
        #pragma unroll
        for (int n2 = 0; n2 < 4; n2++) {
            int gr = row0 + wr * 32 + rt * 16 + g;
            int gc = col0 + wc * 32 + n2 * 8 + tg * 2;
            float* c = acc[rt][n2];
            float d00 = (gr == gc) ? 1.f : 0.f;
            float d01 = (gr == gc + 1) ? 1.f : 0.f;
            float d10 = (gr + 8 == gc) ? 1.f : 0.f;
            float d11 = (gr + 8 == gc + 1) ? 1.f : 0.f;
            float v00 = alpha * c[0] + diag * d00;
            float v01 = alpha * c[1] + diag * d01;
            float v10 = alpha * c[2] + diag * d10;
            float v11 = alpha * c[3] + diag * d11;
            long i0 = (long)gr * MLAND + gc;
            long i1 = i0 + 8 * MLAND;
            C[i0] = v00; C[i0 + 1] = v01;
            C[i1] = v10; C[i1 + 1] = v11;
            if (CT) {
                CT[(long)gc * MLAND + gr]           = v00;
                CT[(long)(gc + 1) * MLAND + gr]     = v01;
                CT[(long)gc * MLAND + gr + 8]       = v10;
                CT[(long)(gc + 1) * MLAND + gr + 8] = v11;
            }
            if (C2) {
                float w00 = alpha2 * c[0] + diag2 * d00;
                float w01 = alpha2 * c[1] + diag2 * d01;
                float w10 = alpha2 * c[2] + diag2 * d10;
                float w11 = alpha2 * c[3] + diag2 * d11;
                C2[i0] = w00; C2[i0 + 1] = w01;
                C2[i1] = w10; C2[i1 + 1] = w11;
                if (C2T) {
                    C2T[(long)gc * MLAND + gr]           = w00;
                    C2T[(long)(gc + 1) * MLAND + gr]     = w01;
                    C2T[(long)gc * MLAND + gr + 8]       = w10;
                    C2T[(long)(gc + 1) * MLAND + gr + 8] = w11;
                }
            }
        }
    }
}

// =====================================================================
// tf32x3 mma.sync 128x64 kernel (N=64 GEMMs: a3v split-K, zv, xh)
// =====================================================================
__device__ __forceinline__ unsigned f2tf(float x) {
    unsigned u;
    asm("cvt.rna.tf32.f32 %0, %1;" : "=r"(u) : "f"(x));
    return u;
}
__device__ __forceinline__ void split_u(unsigned x, unsigned& hi, unsigned& lo) {
    float f = __uint_as_float(x);
    hi = f2tf(f);
    lo = f2tf(f - __uint_as_float(hi));
}
__device__ __forceinline__ void mma8(float* c, const unsigned* a, const unsigned* b) {
    asm volatile(
        "mma.sync.aligned.m16n8k8.row.col.f32.tf32.tf32.f32 "
        "{%0,%1,%2,%3}, {%4,%5,%6,%7}, {%8,%9}, {%0,%1,%2,%3};"
        : "+f"(c[0]), "+f"(c[1]), "+f"(c[2]), "+f"(c[3])
        : "r"(a[0]), "r"(a[1]), "r"(a[2]), "r"(a[3]), "r"(b[0]), "r"(b[1]));
}
#define CP16(d, s)  asm volatile("cp.async.ca.shared.global [%0], [%1], 16;" :: "r"(d), "l"(s))
#define CP4(d, s)   asm volatile("cp.async.ca.shared.global [%0], [%1], 4;"  :: "r"(d), "l"(s))
#define CPCOMMIT()  asm volatile("cp.async.commit_group;")
#define CPWAIT1()   asm volatile("cp.async.wait_group 1;")
#define CPWAIT0()   asm volatile("cp.async.wait_group 0;")
__device__ __forceinline__ int prp(int r) { return r + (r >> 3); }
static const int SROWS = 144;
struct StageT { float A[2][2][SROWS][4]; float B[2][2][SROWS][4]; };
static const int NSTAGE = 3;

__global__ __launch_bounds__(256, 2)
void gemmT64_k(int M, int K, float alpha,
               const float* __restrict__ A, int lda, long sA,
               const float* __restrict__ B, int ldb, long sB,
               float* __restrict__ C, int ldc, long sC, int kSplit)
{
    constexpr int BN = 64, WNT = 4, NP = 2, NB = 4;
    int bz = blockIdx.z;
    int batch = bz / kSplit, ks = bz - batch * kSplit;
    A += (long)batch * sA; B += (long)batch * sB; C += (long)batch * sC;
    const int chunk = K / kSplit;
    const int k0s = ks * chunk;
    const int T = chunk >> 4;

    const int row0 = blockIdx.y * 128;
    const int tid = threadIdx.x;
    const int lane = tid & 31, w = tid >> 5, wr = w >> 1, wc = w & 1;

    extern __shared__ __align__(16) char smraw[];
    StageT* sm = reinterpret_cast<StageT*>(smraw);
    const unsigned stageSz = (unsigned)sizeof(StageT);

    const int ar = tid >> 1, akt = tid & 1;
    const float* aSrc = A + (long)(row0 + ar) * lda + akt * 8;
    const unsigned aD0 = sptr(&sm[0].A[akt][0][prp(ar)][0]);
    const unsigned aD1 = sptr(&sm[0].A[akt][1][prp(ar)][0]);

    int n = tid & (BN - 1);
    int kb = (tid >> 6) * NB;
    const float* bSrc = B + (long)kb * ldb + n;
    unsigned bDst[NB];
    #pragma unroll
    for (int j = 0; j < NB; j++) {
        int kk = kb + j;
        bDst[j] = sptr(&sm[0].B[kk >> 3][(kk >> 2) & 1][prp(n)][kk & 3]);
    }

    auto fill = [&](int kAbs, int s) {
        unsigned so = s * stageSz;
        CP16(aD0 + so, aSrc + kAbs);
        CP16(aD1 + so, aSrc + kAbs + 4);
        #pragma unroll
        for (int j = 0; j < NB; j++)
            CP4(bDst[j] + so, bSrc + (long)(kAbs + j) * ldb);
    };

    const int aRow = wr * 32 + (lane & 15);
    const int aKj = lane >> 4;
    unsigned aAdr[2][2];
    #pragma unroll
    for (int kt = 0; kt < 2; kt++)
        #pragma unroll
        for (int rt = 0; rt < 2; rt++)
            aAdr[kt][rt] = sptr(&sm[0].A[kt][aKj][prp(aRow + rt * 16)][0]);
    const int bKj = (lane >> 3) & 1;
    const int bRow = wc * 32 + ((lane & 7) | ((lane & 16) >> 1));
    unsigned bAdr[2][NP];
    #pragma unroll
    for (int kt = 0; kt < 2; kt++)
        #pragma unroll
        for (int p = 0; p < NP; p++)
            bAdr[kt][p] = sptr(&sm[0].B[kt][bKj][prp(bRow + p * 16)][0]);

    float acc[2][WNT][4];
    #pragma unroll
    for (int i = 0; i < 2; i++)
        #pragma unroll
        for (int j = 0; j < WNT; j++)
            #pragma unroll
            for (int v = 0; v < 4; v++) acc[i][j][v] = 0.f;

    auto compute = [&](int s) {
        unsigned so = s * stageSz;
        #pragma unroll
        for (int kt = 0; kt < 2; kt++) {
            unsigned ah[2][4], al[2][4];
            #pragma unroll
            for (int rt = 0; rt < 2; rt++) {
                unsigned r0, r1, r2, r3;
                ldsm4(r0, r1, r2, r3, aAdr[kt][rt] + so);
                split_u(r0, ah[rt][0], al[rt][0]);
                split_u(r1, ah[rt][1], al[rt][1]);
                split_u(r2, ah[rt][2], al[rt][2]);
                split_u(r3, ah[rt][3], al[rt][3]);
            }
            #pragma unroll
            for (int p = 0; p < NP; p++) {
                unsigned r0, r1, r2, r3;
                ldsm4(r0, r1, r2, r3, bAdr[kt][p] + so);
                unsigned bh0[2], bl0[2], bh1[2], bl1[2];
                split_u(r0, bh0[0], bl0[0]);
                split_u(r1, bh0[1], bl0[1]);
                split_u(r2, bh1[0], bl1[0]);
                split_u(r3, bh1[1], bl1[1]);
                #pragma unroll
                for (int rt = 0; rt < 2; rt++) {
                    mma8(acc[rt][2 * p],     ah[rt], bh0);
                    mma8(acc[rt][2 * p],     al[rt], bh0);
                    mma8(acc[rt][2 * p],     ah[rt], bl0);
                    mma8(acc[rt][2 * p + 1], ah[rt], bh1);
                    mma8(acc[rt][2 * p + 1], al[rt], bh1);
                    mma8(acc[rt][2 * p + 1], ah[rt], bl1);
                }
            }
        }
    };

    fill(k0s, 0);
    CPCOMMIT();
    if (T > 1) { fill(k0s + 16, 1); CPCOMMIT(); }
    for (int t = 0; t < T; t++) {
        if (t + 1 < T) CPWAIT1(); else CPWAIT0();
        __syncthreads();
        if (t + 2 < T) { fill(k0s + (t + 2) * 16, (t + 2) % NSTAGE); CPCOMMIT(); }
        compute(t % NSTAGE);
    }

    const int g = lane >> 2, tg = lane & 3;
    #pragma unroll
    for (int rt = 0; rt < 2; rt++) {
        #pragma unroll
        for (int n2 = 0; n2 < WNT; n2++) {
            int gr = row0 + wr * 32 + rt * 16 + g;
            int gc = wc * 32 + n2 * 8 + tg * 2;
            float* c = acc[rt][n2];
            float* p0 = C + (long)gr * ldc + gc;
            float* p1 = p0 + 8 * (long)ldc;
            if (kSplit > 1) {
                atomicAdd(p0 + 0, alpha * c[0]); atomicAdd(p0 + 1, alpha * c[1]);
                atomicAdd(p1 + 0, alpha * c[2]); atomicAdd(p1 + 1, alpha * c[3]);
            } else {
                p0[0] = alpha * c[0]; p0[1] = alpha * c[1];
                p1[0] = alpha * c[2]; p1[1] = alpha * c[3];
            }
        }
    }
}
static const int GT_SMEM = NSTAGE * (int)sizeof(StageT);

static void gemmT64(int M, int K, float alpha,
                    const float* A, int lda, long sA,
                    const float* B, int ldb, long sB,
                    float* C, int ldc, long sC, int batch, int kSplit)
{
    dim3 g(1, M / 128, batch * kSplit);
    cudaFuncSetAttribute(gemmT64_k, cudaFuncAttributeMaxDynamicSharedMemorySize, GT_SMEM);
    gemmT64_k<<<g, 256, GT_SMEM>>>(M, K, alpha, A, lda, sA, B, ldb, sB,
                                   C, ldc, sC, kSplit);
}

// ---------------- small kernels ----------------
__global__ void transpose_k(const float* __restrict__ S, float* __restrict__ D,
                            int R, int C)
{
    __shared__ float t[32][33];
    int r0 = blockIdx.y * 32, c0 = blockIdx.x * 32;
    int x = threadIdx.x, y0 = threadIdx.y;
    #pragma unroll
    for (int i = y0; i < 32; i += 8)
        t[i][x] = S[(long)(r0 + i) * C + c0 + x];
    __syncthreads();
    #pragma unroll
    for (int i = y0; i < 32; i += 8)
        D[(long)(c0 + i) * R + r0 + x] = t[x][i];
}

__global__ void zeros_k(float* a3v, float* Araw, unsigned int* norm)
{
    long i = (long)blockIdx.x * 256 + threadIdx.x;
    if (i < NHEADS * MLAND * DHEAD) a3v[i] = 0.f;
    if (i < NTOK) Araw[i] = 0.f;
    if (i < 2) norm[i] = 0u;
}

__global__ void landmarks_k(const float* __restrict__ qkv,
                            float* __restrict__ ql, float* __restrict__ kl)
{
    int idx = blockIdx.x * blockDim.x + threadIdx.x;
    if (idx >= NHEADS * MLAND * DHEAD) return;
    int d = idx & 63; int j = (idx >> 6) & 255; int h = idx >> 14;
    const float* qp = qkv + (long)(j * LFOLD) * QKVW + h * DHEAD + d;
    const float* kp = qp + NHEADS * DHEAD;
    float sq = 0.f, sk = 0.f;
    #pragma unroll 4
    for (int t = 0; t < LFOLD; t++) {
        sq += qp[(long)t * QKVW];
        sk += kp[(long)t * QKVW];
    }
    ql[idx] = sq * (1.f / LFOLD);
    kl[idx] = sk * (1.f / LFOLD);
}

__global__ __launch_bounds__(256)
void softmax256_k(float* __restrict__ X)
{
    float* x = X + (long)blockIdx.x * 256;
    int tid = threadIdx.x;
    __shared__ float sm[8];
    float v = x[tid];
    float m = v;
    #pragma unroll
    for (int o = 16; o; o >>= 1) m = fmaxf(m, __shfl_xor_sync(0xffffffffu, m, o));
    if ((tid & 31) == 0) sm[tid >> 5] = m;
    __syncthreads();
    m = sm[0];
    #pragma unroll
    for (int i = 1; i < 8; i++) m = fmaxf(m, sm[i]);
    float e = __expf(v - m);
    float s = e;
    #pragma unroll
    for (int o = 16; o; o >>= 1) s += __shfl_xor_sync(0xffffffffu, s, o);
    __syncthreads();
    if ((tid & 31) == 0) sm[tid >> 5] = s;
    __syncthreads();
    s = sm[0];
    #pragma unroll
    for (int i = 1; i < 8; i++) s += sm[i];
    x[tid] = e * (1.f / s);
}

__global__ __launch_bounds__(1024)
void softmax8192_k(float* __restrict__ X)
{
    float* x = X + (long)blockIdx.x * 8192;
    int tid = threadIdx.x;
    __shared__ float sm[32];
    float4 v0 = *(const float4*)(x + tid * 8);
    float4 v1 = *(const float4*)(x + tid * 8 + 4);
    float m = fmaxf(fmaxf(fmaxf(v0.x, v0.y), fmaxf(v0.z, v0.w)),
                    fmaxf(fmaxf(v1.x, v1.y), fmaxf(v1.z, v1.w)));
    #pragma unroll
    for (int o = 16; o; o >>= 1) m = fmaxf(m, __shfl_xor_sync(0xffffffffu, m, o));
    if ((tid & 31) == 0) sm[tid >> 5] = m;
    __syncthreads();
    m = sm[0];
    #pragma unroll
    for (int i = 1; i < 32; i++) m = fmaxf(m, sm[i]);
    float e0 = __expf(v0.x - m), e1 = __expf(v0.y - m);
    float e2 = __expf(v0.z - m), e3 = __expf(v0.w - m);
    float e4 = __expf(v1.x - m), e5 = __expf(v1.y - m);
    float e6 = __expf(v1.z - m), e7 = __expf(v1.w - m);
    float s = ((e0 + e1) + (e2 + e3)) + ((e4 + e5) + (e6 + e7));
    #pragma unroll
    for (int o = 16; o; o >>= 1) s += __shfl_xor_sync(0xffffffffu, s, o);
    __syncthreads();
    if ((tid & 31) == 0) sm[tid >> 5] = s;
    __syncthreads();
    s = sm[0];
    #pragma unroll
    for (int i = 1; i < 32; i++) s += sm[i];
    float inv = 1.f / s;
    *(float4*)(x + tid * 8)     = make_float4(e0 * inv, e1 * inv, e2 * inv, e3 * inv);
    *(float4*)(x + tid * 8 + 4) = make_float4(e4 * inv, e5 * inv, e6 * inv, e7 * inv);
}

__global__ void a2norm_k(const float* __restrict__ a2, unsigned int* norm)
{
    int h = blockIdx.x; int t = threadIdx.x;
    const float* x = a2 + (long)h * MLAND * MLAND;
    float rs = 0.f, cs = 0.f;
    for (int j = 0; j < MLAND; j++) {
        rs += fabsf(x[t * MLAND + j]);
        cs += fabsf(x[j * MLAND + t]);
    }
    __shared__ float s1[8], s2[8];
    for (int o = 16; o; o >>= 1) {
        rs = fmaxf(rs, __shfl_xor_sync(0xffffffffu, rs, o));
        cs = fmaxf(cs, __shfl_xor_sync(0xffffffffu, cs, o));
    }
    if ((t & 31) == 0) { s1[t >> 5] = rs; s2[t >> 5] = cs; }
    __syncthreads();
    if (t == 0) {
        rs = s1[0]; cs = s2[0];
        for (int w = 1; w < 8; w++) { rs = fmaxf(rs, s1[w]); cs = fmaxf(cs, s2[w]); }
        atomicMax(&norm[0], __float_as_uint(rs));
        atomicMax(&norm[1], __float_as_uint(cs));
    }
}

// writes z = a2^T * inv  AND  zT = a2 * inv
__global__ void zinit2_k(const float* __restrict__ a2, float* __restrict__ z,
                         float* __restrict__ zT,
                         const unsigned int* __restrict__ norm)
{
    long idx = (long)blockIdx.x * 256 + threadIdx.x;
    if (idx >= (long)NHEADS * MLAND * MLAND) return;
    float inv = 1.f / (__uint_as_float(norm[0]) * __uint_as_float(norm[1]));
    int j = idx & 255; int i = (idx >> 8) & 255; long h = idx >> 16;
    z[idx]  = a2[h * 65536 + (long)j * 256 + i] * inv;
    zT[idx] = a2[idx] * inv;
}

__global__ __launch_bounds__(256)
void convadd2_k(const float* __restrict__ qkv,
                const float* __restrict__ rker,
                float* __restrict__ xh)
{
    __shared__ float skr[NHEADS * KCONV];
    for (int i = threadIdx.x; i < NHEADS * KCONV; i += 256) skr[i] = rker[i];
    __syncthreads();
    int idx = blockIdx.x * 256 + threadIdx.x;
    int col = idx & 511;
    int ng = idx >> 9;
    if (ng >= NTOK / 8) return;
    long n0 = (long)ng * 8;
    const float* kr = skr + (col >> 6) * KCONV;
    const float* v = qkv + 2 * NHEADS * DHEAD + col;
    float win[40];
    #pragma unroll
    for (int j = 0; j < 40; j++) {
        long r = n0 - 16 + j;
        win[j] = (r >= 0 && r < NTOK) ? v[r * QKVW] : 0.f;
    }
    #pragma unroll
    for (int i = 0; i < 8; i++) {
        float s = 0.f;
        #pragma unroll
        for (int t = 0; t < KCONV; t++) s += kr[t] * win[i + t];
        xh[(n0 + i) * DMODEL + col] += s;
    }
}

__global__ void edge_k(const float* __restrict__ qe, const float* __restrict__ ke,
                       const int* __restrict__ rows, const int* __restrict__ cols,
                       const float* __restrict__ vals, float* __restrict__ Araw)
{
    int e = blockIdx.x * (blockDim.x >> 5) + (threadIdx.x >> 5);
    int lane = threadIdx.x & 31;
    if (e >= NEDGE) return;
    int r = rows[e], c = cols[e];
    const float4* qr = (const float4*)(qe + (long)r * WPD);
    const float4* kc = (const float4*)(ke + (long)c * WPD);
    float s = 0.f;
    #pragma unroll
    for (int i = lane; i < WPD / 4; i += 32) {
        float4 a = qr[i], b = kc[i];
        s += a.x * b.x + a.y * b.y + a.z * b.z + a.w * b.w;
    }
    for (int o = 16; o; o >>= 1) s += __shfl_xor_sync(0xffffffffu, s, o);
    if (lane == 0) atomicAdd(&Araw[r], s * 0.0625f * vals[e]);
}

__global__ void softmax_all_k(const float* __restrict__ A, float* __restrict__ alpha, int n)
{
    __shared__ float sm[32];
    int tid = threadIdx.x;
    float m = -1e30f;
    for (int i = tid; i < n; i += 1024) m = fmaxf(m, A[i]);
    for (int o = 16; o; o >>= 1) m = fmaxf(m, __shfl_xor_sync(0xffffffffu, m, o));
    if ((tid & 31) == 0) sm[tid >> 5] = m;
    __syncthreads();
    if (tid == 0) { float bm = sm[0]; for (int w = 1; w < 32; w++) bm = fmaxf(bm, sm[w]); sm[0] = bm; }
    __syncthreads();
    m = sm[0];
    __syncthreads();
    float s = 0.f;
    for (int i = tid; i < n; i += 1024) s += __expf(A[i] - m);
    for (int o = 16; o; o >>= 1) s += __shfl_xor_sync(0xffffffffu, s, o);
    if ((tid & 31) == 0) sm[tid >> 5] = s;
    __syncthreads();
    if (tid == 0) { float bs = 0.f; for (int w = 0; w < 32; w++) bs += sm[w]; sm[0] = bs; }
    __syncthreads();
    float inv = 1.f / sm[0];
    for (int i = tid; i < n; i += 1024) alpha[i] = __expf(A[i] - m) * inv;
}

__global__ void final_k(const float* __restrict__ val, const float* __restrict__ wvb,
                        const float* __restrict__ alpha, const float* __restrict__ enc,
                        const float* __restrict__ Araw, float* __restrict__ out)
{
    long idx = (long)blockIdx.x * 256 + threadIdx.x;
    long total = (long)NTOK * DMODEL;
    if (idx < total) {
        int col = idx & 511; long n = idx >> 9;
        float v = val[idx] + wvb[col];
        float xl = alpha[n] * v;
        float w = 1.f / (1.f + __expf(xl));
        float sq = w * w;
        float e = enc[idx];
        out[idx] = xl * 2.f * sq + 2.f * e * (1.f - sq);
    }
    if (idx < NTOK) out[total + idx] = Araw[idx];
}

// ---------------- driver ----------------
extern "C" void kernel_launch(void* const* d_in, const int* in_sizes, int n_in,
                              void* d_out, int out_size)
{
    const float* dense  = (const float*)d_in[0];
    const int*   arows  = (const int*)  d_in[1];
    const int*   acols  = (const int*)  d_in[2];
    const float* avals  = (const float*)d_in[3];
    const float* wq     = (const float*)d_in[4];
    const float* wk     = (const float*)d_in[5];
    const float* w_qkv  = (const float*)d_in[6];
    const float* w_out  = (const float*)d_in[7];
    const float* b_out  = (const float*)d_in[8];
    const float* rker   = (const float*)d_in[9];
    const float* wv_w   = (const float*)d_in[10];
    const float* wv_b   = (const float*)d_in[11];
    float* out = (float*)d_out;

    float *qkv, *ql, *kl, *a1, *a2, *a3, *z, *zT, *z2, *z2T, *xz;
    float *t1, *t1T, *t2, *t2T, *a3v, *zv;
    float *xh, *enc, *val, *qe, *ke, *wqT, *wkT, *Araw, *alpha;
    unsigned int* norm;
    cudaGetSymbolAddress((void**)&qkv, g_qkv);
    cudaGetSymbolAddress((void**)&ql,  g_ql);
    cudaGetSymbolAddress((void**)&kl,  g_kl);
    cudaGetSymbolAddress((void**)&a1,  g_a1);
    cudaGetSymbolAddress((void**)&a2,  g_a2);
    cudaGetSymbolAddress((void**)&a3,  g_a3);
    cudaGetSymbolAddress((void**)&z,   g_z);
    cudaGetSymbolAddress((void**)&zT,  g_zT);
    cudaGetSymbolAddress((void**)&z2,  g_z2);
    cudaGetSymbolAddress((void**)&z2T, g_z2T);
    cudaGetSymbolAddress((void**)&xz,  g_xz);
    cudaGetSymbolAddress((void**)&t1,  g_t1);
    cudaGetSymbolAddress((void**)&t1T, g_t1T);
    cudaGetSymbolAddress((void**)&t2,  g_t2);
    cudaGetSymbolAddress((void**)&t2T, g_t2T);
    cudaGetSymbolAddress((void**)&a3v, g_a3v);
    cudaGetSymbolAddress((void**)&zv,  g_zv);
    cudaGetSymbolAddress((void**)&xh,  g_xh);
    cudaGetSymbolAddress((void**)&enc, g_enc);
    cudaGetSymbolAddress((void**)&val, g_val);
    cudaGetSymbolAddress((void**)&qe,  g_qe);
    cudaGetSymbolAddress((void**)&ke,  g_ke);
    cudaGetSymbolAddress((void**)&wqT, g_wqT);
    cudaGetSymbolAddress((void**)&wkT, g_wkT);
    cudaGetSymbolAddress((void**)&Araw, g_Araw);
    cudaGetSymbolAddress((void**)&alpha, g_alpha);
    cudaGetSymbolAddress((void**)&norm, g_norm);

    const float qscale = 0.125f;
    const long  smm    = (long)MLAND * MLAND;

    // 0. zero scratch + weight transposes (wq,wk -> [WPD, DMODEL])
    zeros_k<<<(NHEADS * MLAND * DHEAD + 255) / 256, 256>>>(a3v, Araw, norm);
    {
        dim3 b(32, 8);
        transpose_k<<<dim3(WPD / 32, DMODEL / 32), b>>>(wq, wqT, DMODEL, WPD);
        transpose_k<<<dim3(WPD / 32, DMODEL / 32), b>>>(wk, wkT, DMODEL, WPD);
    }

    // 1. qkv = dense @ w_qkv^T  [8192,1536]
    gemmH(NTOK, QKVW, DMODEL, 1.f, dense, DMODEL, 0, w_qkv, DMODEL, 0,
          qkv, QKVW, 0, 1);

    // 2. landmarks
    landmarks_k<<<(NHEADS * MLAND * DHEAD + 255) / 256, 256>>>(qkv, ql, kl);

    // 3. a1 = softmax(scale * q @ k_l^T)   [h,8192,256]
    gemmH(NTOK, MLAND, DHEAD, qscale,
          qkv, QKVW, DHEAD, kl, DHEAD, (long)MLAND * DHEAD,
          a1, MLAND, (long)NTOK * MLAND, NHEADS);
    softmax256_k<<<NHEADS * NTOK, 256>>>(a1);

    // 4. a2 = softmax(scale * q_l @ k_l^T) [h,256,256]
    gemmH(MLAND, MLAND, DHEAD, qscale,
          ql, DHEAD, (long)MLAND * DHEAD, kl, DHEAD, (long)MLAND * DHEAD,
          a2, MLAND, smm, NHEADS);
    softmax256_k<<<NHEADS * MLAND, 256>>>(a2);

    // 5. pinv init: z = a2^T/norm, zT = a2/norm
    a2norm_k<<<NHEADS, 256>>>(a2, norm);
    zinit2_k<<<(int)((NHEADS * smm + 255) / 256), 256>>>(a2, z, zT, norm);

    // 6. pinv iterations on fp16x2 tensor path (128 CTAs/launch, fused
    //    diag epilogues + transposed outputs kept in sync)
    float *zin = z, *zinT = zT, *zout = z2, *zoutT = z2T;
    dim3 gp(4, 4, NHEADS);
    for (int it = 0; it < PITERS; it++) {
        // xz = a2 @ zin ; t1 = 7I - xz (+t1T)
        gemmHP_k<<<gp, 128>>>(1.f, 0.f, a2, zinT, xz, nullptr,
                              -1.f, 7.f, t1, t1T);
        // t2 = 15I - xz @ t1 (+t2T)
        gemmHP_k<<<gp, 128>>>(-1.f, 15.f, xz, t1T, t2, t2T,
                              0.f, 0.f, nullptr, nullptr);
        // t1 = 13I - xz @ t2 (+t1T)
        gemmHP_k<<<gp, 128>>>(-1.f, 13.f, xz, t2T, t1, t1T,
                              0.f, 0.f, nullptr, nullptr);
        // zout = 0.25 * zin @ t1 (+zoutT)
        gemmHP_k<<<gp, 128>>>(0.25f, 0.f, zin, t1T, zout, zoutT,
                              0.f, 0.f, nullptr, nullptr);
        float* tmp;
        tmp = zin;  zin = zout;   zout = tmp;
        tmp = zinT; zinT = zoutT; zoutT = tmp;
    }
    float* zfin = zin;

    // 7. a3 = softmax(scale * q_l @ k^T)  [h,256,8192]
    gemmH(MLAND, NTOK, DHEAD, qscale,
          ql, DHEAD, (long)MLAND * DHEAD,
          qkv + NHEADS * DHEAD, QKVW, DHEAD,
          a3, NTOK, (long)MLAND * NTOK, NHEADS);
    softmax8192_k<<<NHEADS * MLAND, 1024>>>(a3);

    // 8. a3v = a3 @ v  [h,256,64]  (tf32 split-K 16, atomic; pre-zeroed)
    gemmT64(MLAND, NTOK, 1.f,
            a3, NTOK, (long)MLAND * NTOK,
            qkv + 2 * NHEADS * DHEAD, QKVW, DHEAD,
            a3v, DHEAD, (long)MLAND * DHEAD, NHEADS, 16);

    // 9. zv = zfin @ a3v  [h,256,64]
    gemmT64(MLAND, MLAND, 1.f,
            zfin, MLAND, smm,
            a3v, DHEAD, (long)MLAND * DHEAD,
            zv, DHEAD, (long)MLAND * DHEAD, NHEADS, 1);

    // 10. xh[n, h*64:+64] = a1 @ zv
    gemmT64(NTOK, MLAND, 1.f,
            a1, MLAND, (long)NTOK * MLAND,
            zv, DHEAD, (long)MLAND * DHEAD,
            xh, DMODEL, DHEAD, NHEADS, 1);

    // 11. residual depthwise conv on v, added into xh
    convadd2_k<<<(NTOK / 8) * DMODEL / 256, 256>>>(qkv, rker, xh);

    // 12. enc = xh @ w_out^T + b_out + dense  (fused epilogue)
    gemmH(NTOK, DMODEL, DMODEL, 1.f, xh, DMODEL, 0, w_out, DMODEL, 0,
          enc, DMODEL, 0, 1, dense, b_out);

    // 13. qe = enc @ wq ; ke = enc @ wk  (TB via transposed weights)
    gemmH(NTOK, WPD, DMODEL, 1.f, enc, DMODEL, 0, wqT, DMODEL, 0, qe, WPD, 0, 1);
    gemmH(NTOK, WPD, DMODEL, 1.f, enc, DMODEL, 0, wkT, DMODEL, 0, ke, WPD, 0, 1);

    // 14. edge scores -> segment sum
    edge_k<<<(NEDGE + 7) / 8, 256>>>(qe, ke, arows, acols, avals, Araw);

    // 15. alpha = softmax(A_raw)
    softmax_all_k<<<1, 1024>>>(Araw, alpha, NTOK);

    // 16. value = dense @ wv_w^T
    gemmH(NTOK, DMODEL, DMODEL, 1.f, dense, DMODEL, 0, wv_w, DMODEL, 0,
          val, DMODEL, 0, 1);

    // 17. final gated blend + A_raw copy
    final_k<<<(int)(((long)NTOK * DMODEL + 255) / 256), 256>>>(val, wv_b, alpha, enc, Araw, out);
}

// round 14
// speedup vs baseline: 1.9208x; 1.0385x over previous
#include <cuda_runtime.h>
#include <cuda_fp16.h>
#include <math.h>

// ---------------- problem constants ----------------
static const int NTOK   = 8192;   // N
static const int DMODEL = 512;    // D
static const int NHEADS = 8;
static const int DHEAD  = 64;
static const int MLAND  = 256;    // M landmarks
static const int LFOLD  = 32;     // N / M
static const int WPD    = 256;    // weight_params_dim
static const int NEDGE  = 262144; // E
static const int KCONV  = 33;
static const int QKVW   = 3 * NHEADS * DHEAD; // 1536
static const int PITERS = 6;

// ---------------- device scratch (BSS) ----------------
__device__ float g_qkv [NTOK * QKVW];
__device__ float g_ql  [NHEADS * MLAND * DHEAD];
__device__ float g_kl  [NHEADS * MLAND * DHEAD];
__device__ float g_a1  [(long)NHEADS * NTOK * MLAND];
__device__ float g_a2  [NHEADS * MLAND * MLAND];
__device__ float g_a3  [(long)NHEADS * MLAND * NTOK];
__device__ float g_z   [NHEADS * MLAND * MLAND];
__device__ float g_zT  [NHEADS * MLAND * MLAND];
__device__ float g_z2  [NHEADS * MLAND * MLAND];
__device__ float g_z2T [NHEADS * MLAND * MLAND];
__device__ float g_xz  [NHEADS * MLAND * MLAND];
__device__ float g_t1  [NHEADS * MLAND * MLAND];
__device__ float g_t1T [NHEADS * MLAND * MLAND];
__device__ float g_t2  [NHEADS * MLAND * MLAND];
__device__ float g_t2T [NHEADS * MLAND * MLAND];
__device__ float g_a3v [NHEADS * MLAND * DHEAD];
__device__ float g_zv  [NHEADS * MLAND * DHEAD];
__device__ float g_xh  [NTOK * DMODEL];
__device__ float g_enc [NTOK * DMODEL];
__device__ float g_val [NTOK * DMODEL];
__device__ float g_qeke [NTOK * 2 * WPD];
__device__ float g_wqkT [2 * WPD * DMODEL];
__device__ float g_Araw [NTOK];
__device__ float g_alpha[NTOK];
__device__ unsigned int g_norm[2];

// ---------------- ptx helpers ----------------
__device__ __forceinline__ unsigned sptr(const void* p) {
    return (unsigned)__cvta_generic_to_shared(p);
}
__device__ __forceinline__ void ldsm4(unsigned& r0, unsigned& r1, unsigned& r2,
                                      unsigned& r3, unsigned addr) {
    asm volatile("ldmatrix.sync.aligned.m8n8.x4.shared.b16 {%0,%1,%2,%3}, [%4];"
        : "=r"(r0), "=r"(r1), "=r"(r2), "=r"(r3) : "r"(addr));
}
__device__ __forceinline__ void mma16(float* c, const unsigned* a, const unsigned* b) {
    asm volatile(
        "mma.sync.aligned.m16n8k16.row.col.f32.f16.f16.f32 "
        "{%0,%1,%2,%3}, {%4,%5,%6,%7}, {%8,%9}, {%0,%1,%2,%3};"
        : "+f"(c[0]), "+f"(c[1]), "+f"(c[2]), "+f"(c[3])
        : "r"(a[0]), "r"(a[1]), "r"(a[2]), "r"(a[3]), "r"(b[0]), "r"(b[1]));
}

// split 8 fp32 -> 8 f16 hi-plane + 8 f16 residual-plane (packed uint4 each)
__device__ __forceinline__ void packsplit8(const float4& v0, const float4& v1,
                                           uint4& h, uint4& r)
{
    float v[8];
    *(float4*)v       = v0;
    *(float4*)(v + 4) = v1;
    unsigned hh[4], rr[4];
    #pragma unroll
    for (int i = 0; i < 4; i++) {
        __half2 p = __floats2half2_rn(v[2 * i], v[2 * i + 1]);
        hh[i] = *(unsigned*)&p;
        float lo = __half2float(__low2half(p));
        float hi = __half2float(__high2half(p));
        __half2 q = __floats2half2_rn(v[2 * i] - lo, v[2 * i + 1] - hi);
        rr[i] = *(unsigned*)&q;
    }
    h = make_uint4(hh[0], hh[1], hh[2], hh[3]);
    r = make_uint4(rr[0], rr[1], rr[2], rr[3]);
}

// =====================================================================
// gemmH: fp16x2 tensor GEMM (h/r split, 3 passes of m16n8k16).
// C = alpha * A[M,K] @ B^T (+addC +bias).  B stored [N,K] (TB form).
// CTA tile 128x128, 128 threads = 4 warps, warp tile 64x64.  (measured)
// =====================================================================
static const int HROWB  = 48;
static const int HPLANE = 128 * HROWB;   // 6144 B
static const int HBUF   = 4 * HPLANE;    // 24576 B
__global__ __launch_bounds__(128, 2)
void gemmH_k(int M, int N, int K, float alpha,
             const float* __restrict__ A, int lda, long sA,
             const float* __restrict__ B, int ldb, long sB,
             float* __restrict__ C, int ldc, long sC,
             const float* __restrict__ addC, const float* __restrict__ bias)
{
    __shared__ __align__(16) char smem[2 * HBUF];

    A += (long)blockIdx.z * sA;
    B += (long)blockIdx.z * sB;
    C += (long)blockIdx.z * sC;
    if (addC) addC += (long)blockIdx.z * sC;

    const int row0 = blockIdx.y * 128;
    const int col0 = blockIdx.x * 128;
    const int tid  = threadIdx.x;
    const int lane = tid & 31, w = tid >> 5, wr = w >> 1, wc = w & 1;

    const float* aSrc = A + (long)(row0 + tid) * lda;
    const float* bSrc = B + (long)(col0 + tid) * ldb;

    const unsigned offA = tid * HROWB;
    const unsigned offB = 2 * HPLANE + tid * HROWB;

    unsigned aLd[4];
    #pragma unroll
    for (int rt = 0; rt < 4; rt++) {
        int rrow = wr * 64 + rt * 16 + (lane & 15);
        aLd[rt] = sptr(smem + rrow * HROWB + (lane >> 4) * 16);
    }
    unsigned bLd[4];
    #pragma unroll
    for (int p = 0; p < 4; p++) {
        int n = wc * 64 + p * 16 + (lane & 7) + ((lane & 16) >> 1);
        bLd[p] = sptr(smem + 2 * HPLANE + n * HROWB + ((lane >> 3) & 1) * 16);
    }

    float acc[4][8][4];
    #pragma unroll
    for (int i = 0; i < 4; i++)
        #pragma unroll
        for (int j = 0; j < 8; j++)
            #pragma unroll
            for (int v = 0; v < 4; v++) acc[i][j][v] = 0.f;

    const int CH = K >> 4;
    float4 pa0, pa1, pa2, pa3, pb0, pb1, pb2, pb3;
    auto loadRegs = [&](int c) {
        const float* a = aSrc + c * 16;
        const float* b = bSrc + c * 16;
        pa0 = *(const float4*)(a);      pa1 = *(const float4*)(a + 4);
        pa2 = *(const float4*)(a + 8);  pa3 = *(const float4*)(a + 12);
        pb0 = *(const float4*)(b);      pb1 = *(const float4*)(b + 4);
        pb2 = *(const float4*)(b + 8);  pb3 = *(const float4*)(b + 12);
    };
    auto stsAll = [&](int b) {
        unsigned off = b * HBUF;
        uint4 h, r;
        packsplit8(pa0, pa1, h, r);
        *(uint4*)(smem + offA + off)               = h;
        *(uint4*)(smem + offA + off + HPLANE)      = r;
        packsplit8(pa2, pa3, h, r);
        *(uint4*)(smem + offA + off + 16)          = h;
        *(uint4*)(smem + offA + off + HPLANE + 16) = r;
        packsplit8(pb0, pb1, h, r);
        *(uint4*)(smem + offB + off)               = h;
        *(uint4*)(smem + offB + off + HPLANE)      = r;
        packsplit8(pb2, pb3, h, r);
        *(uint4*)(smem + offB + off + 16)          = h;
        *(uint4*)(smem + offB + off + HPLANE + 16) = r;
    };

    loadRegs(0);
    for (int c = 0; c < CH; c++) {
        int b = c & 1;
        stsAll(b);
        if (c + 1 < CH) loadRegs(c + 1);
        __syncthreads();
        unsigned off = b * HBUF;
        unsigned ah[4][4], ar[4][4];
        #pragma unroll
        for (int rt = 0; rt < 4; rt++) {
            ldsm4(ah[rt][0], ah[rt][1], ah[rt][2], ah[rt][3], aLd[rt] + off);
            ldsm4(ar[rt][0], ar[rt][1], ar[rt][2], ar[rt][3],
                  aLd[rt] + off + HPLANE);
        }
        #pragma unroll
        for (int p = 0; p < 4; p++) {
            unsigned bh[4], br[4];
            ldsm4(bh[0], bh[1], bh[2], bh[3], bLd[p] + off);
            ldsm4(br[0], br[1], br[2], br[3], bLd[p] + off + HPLANE);
            #pragma unroll
            for (int rt = 0; rt < 4; rt++) {
                mma16(acc[rt][2 * p],     ah[rt], bh);
                mma16(acc[rt][2 * p],     ah[rt], br);
                mma16(acc[rt][2 * p],     ar[rt], bh);
                mma16(acc[rt][2 * p + 1], ah[rt], bh + 2);
                mma16(acc[rt][2 * p + 1], ah[rt], br + 2);
                mma16(acc[rt][2 * p + 1], ar[rt], bh + 2);
            }
        }
    }

    const int g = lane >> 2, tg = lane & 3;
    #pragma unroll
    for (int rt = 0; rt < 4; rt++) {
        #pragma unroll
        for (int n2 = 0; n2 < 8; n2++) {
            int gr = row0 + wr * 64 + rt * 16 + g;
            int gc = col0 + wc * 64 + n2 * 8 + tg * 2;
            float* c = acc[rt][n2];
            long i0 = (long)gr * ldc + gc;
            long i1 = i0 + 8 * (long)ldc;
            float v00 = alpha * c[0], v01 = alpha * c[1];
            float v10 = alpha * c[2], v11 = alpha * c[3];
            if (addC) {
                v00 += addC[i0]; v01 += addC[i0 + 1];
                v10 += addC[i1]; v11 += addC[i1 + 1];
            }
            if (bias) {
                v00 += bias[gc]; v01 += bias[gc + 1];
                v10 += bias[gc]; v11 += bias[gc + 1];
            }
            C[i0] = v00; C[i0 + 1] = v01;
            C[i1] = v10; C[i1 + 1] = v11;
        }
    }
}

static void gemmH(int M, int N, int K, float alpha,
                  const float* A, int lda, long sA,
                  const float* B, int ldb, long sB,
                  float* C, int ldc, long sC, int batch,
                  const float* addC = nullptr, const float* bias = nullptr)
{
    dim3 g(N / 128, M / 128, batch);
    gemmH_k<<<g, 128>>>(M, N, K, alpha, A, lda, sA, B, ldb, sB,
                        C, ldc, sC, addC, bias);
}

// =====================================================================
// gemmH64: fp16x2 GEMM, CTA tile 128x64, NT form (B = [K,N] row-major).
// 128 threads = 4 warps (4x1), warp tile 32x64. Optional split-K atomic.
// REQUIRES M%128==0, N==64, (K/kSplit)%16==0.
// =====================================================================
static const int QROWB   = 48;
static const int QAPLANE = 128 * QROWB;              // 6144
static const int QBPLANE = 64 * QROWB;               // 3072
static const int QBUF    = 2 * QAPLANE + 2 * QBPLANE; // 18432
__global__ __launch_bounds__(128, 3)
void gemmH64_k(int M, int K, float alpha,
               const float* __restrict__ A, int lda, long sA,
               const float* __restrict__ B, int ldb, long sB,
               float* __restrict__ C, int ldc, long sC, int kSplit)
{
    __shared__ __align__(16) char smem[2 * QBUF];   // 36864 B

    int bz = blockIdx.z;
    int batch = bz / kSplit, ks = bz - batch * kSplit;
    A += (long)batch * sA; B += (long)batch * sB; C += (long)batch * sC;
    const int chunk = K / kSplit;
    const int k0s = ks * chunk;
    const int CH = chunk >> 4;

    const int row0 = blockIdx.y * 128;
    const int tid  = threadIdx.x;
    const int lane = tid & 31, w = tid >> 5;   // w = row group 0..3

    // A staging: thread t -> row row0+t, 16 k's
    const float* aSrc = A + (long)(row0 + tid) * lda + k0s;
    const unsigned offA = tid * QROWB;
    // B staging: thread t -> n = t&63, k-half = (t>>6)*8 (8 strided loads)
    const int bn = tid & 63, bkh = (tid >> 6) * 8;
    const float* bSrc = B + (long)(k0s + bkh) * ldb + bn;
    const unsigned offB = 2 * QAPLANE + bn * QROWB + bkh * 2;

    unsigned aLd[2];
    #pragma unroll
    for (int rt = 0; rt < 2; rt++) {
        int rrow = w * 32 + rt * 16 + (lane & 15);
        aLd[rt] = sptr(smem + rrow * QROWB + (lane >> 4) * 16);
    }
    unsigned bLd[4];
    #pragma unroll
    for (int p = 0; p < 4; p++) {
        int n = p * 16 + (lane & 7) + ((lane & 16) >> 1);
        bLd[p] = sptr(smem + 2 * QAPLANE + n * QROWB + ((lane >> 3) & 1) * 16);
    }

    float acc[2][8][4];
    #pragma unroll
    for (int i = 0; i < 2; i++)
        #pragma unroll
        for (int j = 0; j < 8; j++)
            #pragma unroll
            for (int v = 0; v < 4; v++) acc[i][j][v] = 0.f;

    float4 pa0, pa1, pa2, pa3;
    float vb[8];
    auto loadRegs = [&](int c) {
        const float* a = aSrc + c * 16;
        pa0 = *(const float4*)(a);      pa1 = *(const float4*)(a + 4);
        pa2 = *(const float4*)(a + 8);  pa3 = *(const float4*)(a + 12);
        const float* b = bSrc + (long)c * 16 * ldb;
        #pragma unroll
        for (int j = 0; j < 8; j++) vb[j] = b[(long)j * ldb];
    };
    auto stsAll = [&](int b) {
        unsigned off = b * QBUF;
        uint4 h, r;
        packsplit8(pa0, pa1, h, r);
        *(uint4*)(smem + offA + off)                = h;
        *(uint4*)(smem + offA + off + QAPLANE)      = r;
        packsplit8(pa2, pa3, h, r);
        *(uint4*)(smem + offA + off + 16)           = h;
        *(uint4*)(smem + offA + off + QAPLANE + 16) = r;
        packsplit8(make_float4(vb[0], vb[1], vb[2], vb[3]),
                   make_float4(vb[4], vb[5], vb[6], vb[7]), h, r);
        *(uint4*)(smem + offB + off)                = h;
        *(uint4*)(smem + offB + off + QBPLANE)      = r;
    };

    loadRegs(0);
    for (int c = 0; c < CH; c++) {
        int b = c & 1;
        stsAll(b);
        if (c + 1 < CH) loadRegs(c + 1);
        __syncthreads();
        unsigned off = b * QBUF;
        unsigned ah[2][4], ar[2][4];
        #pragma unroll
        for (int rt = 0; rt < 2; rt++) {
            ldsm4(ah[rt][0], ah[rt][1], ah[rt][2], ah[rt][3], aLd[rt] + off);
            ldsm4(ar[rt][0], ar[rt][1], ar[rt][2], ar[rt][3],
                  aLd[rt] + off + QAPLANE);
        }
        #pragma unroll
        for (int p = 0; p < 4; p++) {
            unsigned bh[4], br[4];
            ldsm4(bh[0], bh[1], bh[2], bh[3], bLd[p] + off);
            ldsm4(br[0], br[1], br[2], br[3], bLd[p] + off + QBPLANE);
            #pragma unroll
            for (int rt = 0; rt < 2; rt++) {
                mma16(acc[rt][2 * p],     ah[rt], bh);
                mma16(acc[rt][2 * p],     ah[rt], br);
                mma16(acc[rt][2 * p],     ar[rt], bh);
                mma16(acc[rt][2 * p + 1], ah[rt], bh + 2);
                mma16(acc[rt][2 * p + 1], ah[rt], br + 2);
                mma16(acc[rt][2 * p + 1], ar[rt], bh + 2);
            }
        }
    }

    const int g = lane >> 2, tg = lane & 3;
    #pragma unroll
    for (int rt = 0; rt < 2; rt++) {
        #pragma unroll
        for (int n2 = 0; n2 < 8; n2++) {
            int gr = row0 + w * 32 + rt * 16 + g;
            int gc = n2 * 8 + tg * 2;
            float* c = acc[rt][n2];
            float* p0 = C + (long)gr * ldc + gc;
            float* p1 = p0 + 8 * (long)ldc;
            if (kSplit > 1) {
                atomicAdd(p0 + 0, alpha * c[0]); atomicAdd(p0 + 1, alpha * c[1]);
                atomicAdd(p1 + 0, alpha * c[2]); atomicAdd(p1 + 1, alpha * c[3]);
            } else {
                p0[0] = alpha * c[0]; p0[1] = alpha * c[1];
                p1[0] = alpha * c[2]; p1[1] = alpha * c[3];
            }
        }
    }
}

static void gemmH64(int M, int K, float alpha,
                    const float* A, int lda, long sA,
                    const float* B, int ldb, long sB,
                    float* C, int ldc, long sC, int batch, int kSplit)
{
    dim3 g(1, M / 128, batch * kSplit);
    gemmH64_k<<<g, 128>>>(M, K, alpha, A, lda, sA, B, ldb, sB,
                          C, ldc, sC, kSplit);
}

// =====================================================================
// gemmHP: fp16x2 pinv GEMM (R13, measured). 64x64 CTA, batched 256x256.
// =====================================================================
static const int PROWB  = 48;
static const int PPLANE = 64 * PROWB;
static const int PBUF   = 4 * PPLANE;
__global__ __launch_bounds__(128, 3)
void gemmHP_k(float alpha, float diag,
              const float* __restrict__ A, const float* __restrict__ B,
              float* __restrict__ C, float* __restrict__ CT,
              float alpha2, float diag2,
              float* __restrict__ C2, float* __restrict__ C2T)
{
    __shared__ __align__(16) char smem[2 * PBUF];

    const long sb = (long)MLAND * MLAND;
    A += blockIdx.z * sb; B += blockIdx.z * sb; C += blockIdx.z * sb;
    if (CT)  CT  += blockIdx.z * sb;
    if (C2)  C2  += blockIdx.z * sb;
    if (C2T) C2T += blockIdx.z * sb;

    const int row0 = blockIdx.y * 64;
    const int col0 = blockIdx.x * 64;
    const int tid  = threadIdx.x;
    const int lane = tid & 31, w = tid >> 5, wr = w >> 1, wc = w & 1;

    const int  sr    = tid & 63;
    const bool isB   = tid >= 64;
    const float* src = isB ? (B + (long)(col0 + sr) * MLAND)
                           : (A + (long)(row0 + sr) * MLAND);
    const unsigned stOff = (isB ? 2 * PPLANE : 0) + sr * PROWB;

    unsigned aLd[2];
    #pragma unroll
    for (int rt = 0; rt < 2; rt++) {
        int rrow = wr * 32 + rt * 16 + (lane & 15);
        aLd[rt] = sptr(smem + rrow * PROWB + (lane >> 4) * 16);
    }
    unsigned bLd[2];
    #pragma unroll
    for (int p = 0; p < 2; p++) {
        int n = wc * 32 + p * 16 + (lane & 7) + ((lane & 16) >> 1);
        bLd[p] = sptr(smem + 2 * PPLANE + n * PROWB + ((lane >> 3) & 1) * 16);
    }

    float acc[2][4][4];
    #pragma unroll
    for (int i = 0; i < 2; i++)
        #pragma unroll
        for (int j = 0; j < 4; j++)
            #pragma unroll
            for (int v = 0; v < 4; v++) acc[i][j][v] = 0.f;

    const int CH = MLAND >> 4;
    float4 p0, p1, p2, p3;
    auto loadRegs = [&](int c) {
        const float* s = src + c * 16;
        p0 = *(const float4*)(s);     p1 = *(const float4*)(s + 4);
        p2 = *(const float4*)(s + 8); p3 = *(const float4*)(s + 12);
    };
    auto stsAll = [&](int b) {
        unsigned off = b * PBUF + stOff;
        uint4 h, r;
        packsplit8(p0, p1, h, r);
        *(uint4*)(smem + off)               = h;
        *(uint4*)(smem + off + PPLANE)      = r;
        packsplit8(p2, p3, h, r);
        *(uint4*)(smem + off + 16)          = h;
        *(uint4*)(smem + off + PPLANE + 16) = r;
    };

    loadRegs(0);
    for (int c = 0; c < CH; c++) {
        int b = c & 1;
        stsAll(b);
        if (c + 1 < CH) loadRegs(c + 1);
        __syncthreads();
        unsigned off = b * PBUF;
        unsigned ah[2][4], ar[2][4];
        #pragma unroll
        for (int rt = 0; rt < 2; rt++) {
            ldsm4(ah[rt][0], ah[rt][1], ah[rt][2], ah[rt][3], aLd[rt] + off);
            ldsm4(ar[rt][0], ar[rt][1], ar[rt][2], ar[rt][3],
                  aLd[rt] + off + PPLANE);
        }
        #pragma unroll
        for (int p = 0; p < 2; p++) {
            unsigned bh[4], br[4];
            ldsm4(bh[0], bh[1], bh[2], bh[3], bLd[p] + off);
            ldsm4(br[0], br[1], br[2], br[3], bLd[p] + off + PPLANE);
            #pragma unroll
            for (int rt = 0; rt < 2; rt++) {
                mma16(acc[rt][2 * p],     ah[rt], bh);
                mma16(acc[rt][2 * p],     ah[rt], br);
                mma16(acc[rt][2 * p],     ar[rt], bh);
                mma16(acc[rt][2 * p + 1], ah[rt], bh + 2);
                mma16(acc[rt][2 * p + 1], ah[rt], br + 2);
                mma16(acc[rt][2 * p + 1], ar[rt], bh + 2);
            }
        }
    }

    const int g = lane >> 2, tg = lane & 3;
    #pragma unroll
    for (int rt = 0; rt < 2; rt++) {
        #pragma unroll
        for (int n2 = 0; n2 < 4; n2++) {
            int gr = row0 + wr * 32 + rt * 16 + g;
            int gc = col0 + wc * 32 + n2 * 8 + tg * 2;
            float* c = acc[rt][n2];
            float d00 = (gr == gc) ? 1.f : 0.f;
            float d01 = (gr == gc + 1) ? 1.f : 0.f;
            float d10 = (gr + 8 == gc) ? 1.f : 0.f;
            float d11 = (gr + 8 == gc + 1) ? 1.f : 0.f;
            float v00 = alpha * c[0] + diag * d00;
            float v01 = alpha * c[1] + diag * d01;
            float v10 = alpha * c[2] + diag * d10;
            float v11 = alpha * c[3] + diag * d11;
            long i0 = (long)gr * MLAND + gc;
            long i1 = i0 + 8 * MLAND;
            C[i0] = v00; C[i0 + 1] = v01;
            C[i1] = v10; C[i1 + 1] = v11;
            if (CT) {
                CT[(long)gc * MLAND + gr]           = v00;
                CT[(long)(gc + 1) * MLAND + gr]     = v01;
                CT[(long)gc * MLAND + gr + 8]       = v10;
                CT[(long)(gc + 1) * MLAND + gr + 8] = v11;
            }
            if (C2) {
                float w00 = alpha2 * c[0] + diag2 * d00;
                float w01 = alpha2 * c[1] + diag2 * d01;
                float w10 = alpha2 * c[2] + diag2 * d10;
                float w11 = alpha2 * c[3] + diag2 * d11;
                C2[i0] = w00; C2[i0 + 1] = w01;
                C2[i1] = w10; C2[i1 + 1] = w11;
                if (C2T) {
                    C2T[(long)gc * MLAND + gr]           = w00;
                    C2T[(long)(gc + 1) * MLAND + gr]     = w01;
                    C2T[(long)gc * MLAND + gr + 8]       = w10;
                    C2T[(long)(gc + 1) * MLAND + gr + 8] = w11;
                }
            }
        }
    }
}

// ---------------- small kernels ----------------
__global__ void transpose_k(const float* __restrict__ S, float* __restrict__ D,
                            int R, int C)
{
    __shared__ float t[32][33];
    int r0 = blockIdx.y * 32, c0 = blockIdx.x * 32;
    int x = threadIdx.x, y0 = threadIdx.y;
    #pragma unroll
    for (int i = y0; i < 32; i += 8)
        t[i][x] = S[(long)(r0 + i) * C + c0 + x];
    __syncthreads();
    #pragma unroll
    for (int i = y0; i < 32; i += 8)
        D[(long)(c0 + i) * R + r0 + x] = t[x][i];
}

__global__ void zeros_k(float* a3v, float* Araw, unsigned int* norm)
{
    long i = (long)blockIdx.x * 256 + threadIdx.x;
    if (i < NHEADS * MLAND * DHEAD) a3v[i] = 0.f;
    if (i < NTOK) Araw[i] = 0.f;
    if (i < 2) norm[i] = 0u;
}

__global__ void landmarks_k(const float* __restrict__ qkv,
                            float* __restrict__ ql, float* __restrict__ kl)
{
    int idx = blockIdx.x * blockDim.x + threadIdx.x;
    if (idx >= NHEADS * MLAND * DHEAD) return;
    int d = idx & 63; int j = (idx >> 6) & 255; int h = idx >> 14;
    const float* qp = qkv + (long)(j * LFOLD) * QKVW + h * DHEAD + d;
    const float* kp = qp + NHEADS * DHEAD;
    float sq = 0.f, sk = 0.f;
    #pragma unroll 4
    for (int t = 0; t < LFOLD; t++) {
        sq += qp[(long)t * QKVW];
        sk += kp[(long)t * QKVW];
    }
    ql[idx] = sq * (1.f / LFOLD);
    kl[idx] = sk * (1.f / LFOLD);
}

__global__ __launch_bounds__(256)
void softmax256_k(float* __restrict__ X)
{
    float* x = X + (long)blockIdx.x * 256;
    int tid = threadIdx.x;
    __shared__ float sm[8];
    float v = x[tid];
    float m = v;
    #pragma unroll
    for (int o = 16; o; o >>= 1) m = fmaxf(m, __shfl_xor_sync(0xffffffffu, m, o));
    if ((tid & 31) == 0) sm[tid >> 5] = m;
    __syncthreads();
    m = sm[0];
    #pragma unroll
    for (int i = 1; i < 8; i++) m = fmaxf(m, sm[i]);
    float e = __expf(v - m);
    float s = e;
    #pragma unroll
    for (int o = 16; o; o >>= 1) s += __shfl_xor_sync(0xffffffffu, s, o);
    __syncthreads();
    if ((tid & 31) == 0) sm[tid >> 5] = s;
    __syncthreads();
    s = sm[0];
    #pragma unroll
    for (int i = 1; i < 8; i++) s += sm[i];
    x[tid] = e * (1.f / s);
}

__global__ __launch_bounds__(1024)
void softmax8192_k(float* __restrict__ X)
{
    float* x = X + (long)blockIdx.x * 8192;
    int tid = threadIdx.x;
    __shared__ float sm[32];
    float4 v0 = *(const float4*)(x + tid * 8);
    float4 v1 = *(const float4*)(x + tid * 8 + 4);
    float m = fmaxf(fmaxf(fmaxf(v0.x, v0.y), fmaxf(v0.z, v0.w)),
                    fmaxf(fmaxf(v1.x, v1.y), fmaxf(v1.z, v1.w)));
    #pragma unroll
    for (int o = 16; o; o >>= 1) m = fmaxf(m, __shfl_xor_sync(0xffffffffu, m, o));
    if ((tid & 31) == 0) sm[tid >> 5] = m;
    __syncthreads();
    m = sm[0];
    #pragma unroll
    for (int i = 1; i < 32; i++) m = fmaxf(m, sm[i]);
    float e0 = __expf(v0.x - m), e1 = __expf(v0.y - m);
    float e2 = __expf(v0.z - m), e3 = __expf(v0.w - m);
    float e4 = __expf(v1.x - m), e5 = __expf(v1.y - m);
    float e6 = __expf(v1.z - m), e7 = __expf(v1.w - m);
    float s = ((e0 + e1) + (e2 + e3)) + ((e4 + e5) + (e6 + e7));
    #pragma unroll
    for (int o = 16; o; o >>= 1) s += __shfl_xor_sync(0xffffffffu, s, o);
    __syncthreads();
    if ((tid & 31) == 0) sm[tid >> 5] = s;
    __syncthreads();
    s = sm[0];
    #pragma unroll
    for (int i = 1; i < 32; i++) s += sm[i];
    float inv = 1.f / s;
    *(float4*)(x + tid * 8)     = make_float4(e0 * inv, e1 * inv, e2 * inv, e3 * inv);
    *(float4*)(x + tid * 8 + 4) = make_float4(e4 * inv, e5 * inv, e6 * inv, e7 * inv);
}

__global__ void a2norm_k(const float* __restrict__ a2, unsigned int* norm)
{
    int h = blockIdx.x; int t = threadIdx.x;
    const float* x = a2 + (long)h * MLAND * MLAND;
    float rs = 0.f, cs = 0.f;
    for (int j = 0; j < MLAND; j++) {
        rs += fabsf(x[t * MLAND + j]);
        cs += fabsf(x[j * MLAND + t]);
    }
    __shared__ float s1[8], s2[8];
    for (int o = 16; o; o >>= 1) {
        rs = fmaxf(rs, __shfl_xor_sync(0xffffffffu, rs, o));
        cs = fmaxf(cs, __shfl_xor_sync(0xffffffffu, cs, o));
    }
    if ((t & 31) == 0) { s1[t >> 5] = rs; s2[t >> 5] = cs; }
    __syncthreads();
    if (t == 0) {
        rs = s1[0]; cs = s2[0];
        for (int w = 1; w < 8; w++) { rs = fmaxf(rs, s1[w]); cs = fmaxf(cs, s2[w]); }
        atomicMax(&norm[0], __float_as_uint(rs));
        atomicMax(&norm[1], __float_as_uint(cs));
    }
}

// writes z = a2^T * inv  AND  zT = a2 * inv
__global__ void zinit2_k(const float* __restrict__ a2, float* __restrict__ z,
                         float* __restrict__ zT,
                         const unsigned int* __restrict__ norm)
{
    long idx = (long)blockIdx.x * 256 + threadIdx.x;
    if (idx >= (long)NHEADS * MLAND * MLAND) return;
    float inv = 1.f / (__uint_as_float(norm[0]) * __uint_as_float(norm[1]));
    int j = idx & 255; int i = (idx >> 8) & 255; long h = idx >> 16;
    z[idx]  = a2[h * 65536 + (long)j * 256 + i] * inv;
    zT[idx] = a2[idx] * inv;
}

__global__ __launch_bounds__(256)
void convadd2_k(const float* __restrict__ qkv,
                const float* __restrict__ rker,
                float* __restrict__ xh)
{
    __shared__ float skr[NHEADS * KCONV];
    for (int i = threadIdx.x; i < NHEADS * KCONV; i += 256) skr[i] = rker[i];
    __syncthreads();
    int idx = blockIdx.x * 256 + threadIdx.x;
    int col = idx & 511;
    int ng = idx >> 9;
    if (ng >= NTOK / 8) return;
    long n0 = (long)ng * 8;
    const float* kr = skr + (col >> 6) * KCONV;
    const float* v = qkv + 2 * NHEADS * DHEAD + col;
    float win[40];
    #pragma unroll
    for (int j = 0; j < 40; j++) {
        long r = n0 - 16 + j;
        win[j] = (r >= 0 && r < NTOK) ? v[r * QKVW] : 0.f;
    }
    #pragma unroll
    for (int i = 0; i < 8; i++) {
        float s = 0.f;
        #pragma unroll
        for (int t = 0; t < KCONV; t++) s += kr[t] * win[i + t];
        xh[(n0 + i) * DMODEL + col] += s;
    }
}

__global__ void edge_k(const float* __restrict__ qeke,
                       const int* __restrict__ rows, const int* __restrict__ cols,
                       const float* __restrict__ vals, float* __restrict__ Araw)
{
    int e = blockIdx.x * (blockDim.x >> 5) + (threadIdx.x >> 5);
    int lane = threadIdx.x & 31;
    if (e >= NEDGE) return;
    int r = rows[e], c = cols[e];
    const float4* qr = (const float4*)(qeke + (long)r * 512);
    const float4* kc = (const float4*)(qeke + (long)c * 512 + WPD);
    float s = 0.f;
    #pragma unroll
    for (int i = lane; i < WPD / 4; i += 32) {
        float4 a = qr[i], b = kc[i];
        s += a.x * b.x + a.y * b.y + a.z * b.z + a.w * b.w;
    }
    for (int o = 16; o; o >>= 1) s += __shfl_xor_sync(0xffffffffu, s, o);
    if (lane == 0) atomicAdd(&Araw[r], s * 0.0625f * vals[e]);
}

__global__ void softmax_all_k(const float* __restrict__ A, float* __restrict__ alpha, int n)
{
    __shared__ float sm[32];
    int tid = threadIdx.x;
    float m = -1e30f;
    for (int i = tid; i < n; i += 1024) m = fmaxf(m, A[i]);
    for (int o = 16; o; o >>= 1) m = fmaxf(m, __shfl_xor_sync(0xffffffffu, m, o));
    if ((tid & 31) == 0) sm[tid >> 5] = m;
    __syncthreads();
    if (tid == 0) { float bm = sm[0]; for (int w = 1; w < 32; w++) bm = fmaxf(bm, sm[w]); sm[0] = bm; }
    __syncthreads();
    m = sm[0];
    __syncthreads();
    float s = 0.f;
    for (int i = tid; i < n; i += 1024) s += __expf(A[i] - m);
    for (int o = 16; o; o >>= 1) s += __shfl_xor_sync(0xffffffffu, s, o);
    if ((tid & 31) == 0) sm[tid >> 5] = s;
    __syncthreads();
    if (tid == 0) { float bs = 0.f; for (int w = 0; w < 32; w++) bs += sm[w]; sm[0] = bs; }
    __syncthreads();
    float inv = 1.f / sm[0];
    for (int i = tid; i < n; i += 1024) alpha[i] = __expf(A[i] - m) * inv;
}

__global__ void final_k(const float* __restrict__ val, const float* __restrict__ wvb,
                        const float* __restrict__ alpha, const float* __restrict__ enc,
                        const float* __restrict__ Araw, float* __restrict__ out)
{
    long idx = (long)blockIdx.x * 256 + threadIdx.x;
    long total = (long)NTOK * DMODEL;
    if (idx < total) {
        int col = idx & 511; long n = idx >> 9;
        float v = val[idx] + wvb[col];
        float xl = alpha[n] * v;
        float w = 1.f / (1.f + __expf(xl));
        float sq = w * w;
        float e = enc[idx];
        out[idx] = xl * 2.f * sq + 2.f * e * (1.f - sq);
    }
    if (idx < NTOK) out[total + idx] = Araw[idx];
}

// ---------------- driver ----------------
extern "C" void kernel_launch(void* const* d_in, const int* in_sizes, int n_in,
                              void* d_out, int out_size)
{
    const float* dense  = (const float*)d_in[0];
    const int*   arows  = (const int*)  d_in[1];
    const int*   acols  = (const int*)  d_in[2];
    const float* avals  = (const float*)d_in[3];
    const float* wq     = (const float*)d_in[4];
    const float* wk     = (const float*)d_in[5];
    const float* w_qkv  = (const float*)d_in[6];
    const float* w_out  = (const float*)d_in[7];
    const float* b_out  = (const float*)d_in[8];
    const float* rker   = (const float*)d_in[9];
    const float* wv_w   = (const float*)d_in[10];
    const float* wv_b   = (const float*)d_in[11];
    float* out = (float*)d_out;

    float *qkv, *ql, *kl, *a1, *a2, *a3, *z, *zT, *z2, *z2T, *xz;
    float *t1, *t1T, *t2, *t2T, *a3v, *zv;
    float *xh, *enc, *val, *qeke, *wqkT, *Araw, *alpha;
    unsigned int* norm;
    cudaGetSymbolAddress((void**)&qkv, g_qkv);
    cudaGetSymbolAddress((void**)&ql,  g_ql);
    cudaGetSymbolAddress((void**)&kl,  g_kl);
    cudaGetSymbolAddress((void**)&a1,  g_a1);
    cudaGetSymbolAddress((void**)&a2,  g_a2);
    cudaGetSymbolAddress((void**)&a3,  g_a3);
    cudaGetSymbolAddress((void**)&z,   g_z);
    cudaGetSymbolAddress((void**)&zT,  g_zT);
    cudaGetSymbolAddress((void**)&z2,  g_z2);
    cudaGetSymbolAddress((void**)&z2T, g_z2T);
    cudaGetSymbolAddress((void**)&xz,  g_xz);
    cudaGetSymbolAddress((void**)&t1,  g_t1);
    cudaGetSymbolAddress((void**)&t1T, g_t1T);
    cudaGetSymbolAddress((void**)&t2,  g_t2);
    cudaGetSymbolAddress((void**)&t2T, g_t2T);
    cudaGetSymbolAddress((void**)&a3v, g_a3v);
    cudaGetSymbolAddress((void**)&zv,  g_zv);
    cudaGetSymbolAddress((void**)&xh,  g_xh);
    cudaGetSymbolAddress((void**)&enc, g_enc);
    cudaGetSymbolAddress((void**)&val, g_val);
    cudaGetSymbolAddress((void**)&qeke, g_qeke);
    cudaGetSymbolAddress((void**)&wqkT, g_wqkT);
    cudaGetSymbolAddress((void**)&Araw, g_Araw);
    cudaGetSymbolAddress((void**)&alpha, g_alpha);
    cudaGetSymbolAddress((void**)&norm, g_norm);

    const float qscale = 0.125f;
    const long  smm    = (long)MLAND * MLAND;

    // 0. zero scratch + combined weight transpose (wq|wk -> [512, DMODEL])
    zeros_k<<<(NHEADS * MLAND * DHEAD + 255) / 256, 256>>>(a3v, Araw, norm);
    {
        dim3 b(32, 8);
        transpose_k<<<dim3(WPD / 32, DMODEL / 32), b>>>(wq, wqkT, DMODEL, WPD);
        transpose_k<<<dim3(WPD / 32, DMODEL / 32), b>>>(wk, wqkT + WPD * DMODEL,
                                                        DMODEL, WPD);
    }

    // 1. qkv = dense @ w_qkv^T  [8192,1536]
    gemmH(NTOK, QKVW, DMODEL, 1.f, dense, DMODEL, 0, w_qkv, DMODEL, 0,
          qkv, QKVW, 0, 1);

    // 2. landmarks
    landmarks_k<<<(NHEADS * MLAND * DHEAD + 255) / 256, 256>>>(qkv, ql, kl);

    // 3. a1 = softmax(scale * q @ k_l^T)   [h,8192,256]
    gemmH(NTOK, MLAND, DHEAD, qscale,
          qkv, QKVW, DHEAD, kl, DHEAD, (long)MLAND * DHEAD,
          a1, MLAND, (long)NTOK * MLAND, NHEADS);
    softmax256_k<<<NHEADS * NTOK, 256>>>(a1);

    // 4. a2 = softmax(scale * q_l @ k_l^T) [h,256,256]
    gemmH(MLAND, MLAND, DHEAD, qscale,
          ql, DHEAD, (long)MLAND * DHEAD, kl, DHEAD, (long)MLAND * DHEAD,
          a2, MLAND, smm, NHEADS);
    softmax256_k<<<NHEADS * MLAND, 256>>>(a2);

    // 5. pinv init: z = a2^T/norm, zT = a2/norm
    a2norm_k<<<NHEADS, 256>>>(a2, norm);
    zinit2_k<<<(int)((NHEADS * smm + 255) / 256), 256>>>(a2, z, zT, norm);

    // 6. pinv iterations (fp16x2, fused diag + transposed outputs)
    float *zin = z, *zinT = zT, *zout = z2, *zoutT = z2T;
    dim3 gp(4, 4, NHEADS);
    for (int it = 0; it < PITERS; it++) {
        gemmHP_k<<<gp, 128>>>(1.f, 0.f, a2, zinT, xz, nullptr,
                              -1.f, 7.f, t1, t1T);
        gemmHP_k<<<gp, 128>>>(-1.f, 15.f, xz, t1T, t2, t2T,
                              0.f, 0.f, nullptr, nullptr);
        gemmHP_k<<<gp, 128>>>(-1.f, 13.f, xz, t2T, t1, t1T,
                              0.f, 0.f, nullptr, nullptr);
        gemmHP_k<<<gp, 128>>>(0.25f, 0.f, zin, t1T, zout, zoutT,
                              0.f, 0.f, nullptr, nullptr);
        float* tmp;
        tmp = zin;  zin = zout;   zout = tmp;
        tmp = zinT; zinT = zoutT; zoutT = tmp;
    }
    float* zfin = zin;

    // 7. a3 = softmax(scale * q_l @ k^T)  [h,256,8192]
    gemmH(MLAND, NTOK, DHEAD, qscale,
          ql, DHEAD, (long)MLAND * DHEAD,
          qkv + NHEADS * DHEAD, QKVW, DHEAD,
          a3, NTOK, (long)MLAND * NTOK, NHEADS);
    softmax8192_k<<<NHEADS * MLAND, 1024>>>(a3);

    // 8. a3v = a3 @ v  [h,256,64]  (fp16x2 split-K 16, atomic; pre-zeroed)
    gemmH64(MLAND, NTOK, 1.f,
            a3, NTOK, (long)MLAND * NTOK,
            qkv + 2 * NHEADS * DHEAD, QKVW, DHEAD,
            a3v, DHEAD, (long)MLAND * DHEAD, NHEADS, 16);

    // 9. zv = zfin @ a3v  [h,256,64]
    gemmH64(MLAND, MLAND, 1.f,
            zfin, MLAND, smm,
            a3v, DHEAD, (long)MLAND * DHEAD,
            zv, DHEAD, (long)MLAND * DHEAD, NHEADS, 1);

    // 10. xh[n, h*64:+64] = a1 @ zv
    gemmH64(NTOK, MLAND, 1.f,
            a1, MLAND, (long)NTOK * MLAND,
            zv, DHEAD, (long)MLAND * DHEAD,
            xh, DMODEL, DHEAD, NHEADS, 1);

    // 11. residual depthwise conv on v, added into xh
    convadd2_k<<<(NTOK / 8) * DMODEL / 256, 256>>>(qkv, rker, xh);

    // 12. enc = xh @ w_out^T + b_out + dense  (fused epilogue)
    gemmH(NTOK, DMODEL, DMODEL, 1.f, xh, DMODEL, 0, w_out, DMODEL, 0,
          enc, DMODEL, 0, 1, dense, b_out);

    // 13. qeke = enc @ [wq|wk]  (single N=512 GEMM via combined transpose)
    gemmH(NTOK, 2 * WPD, DMODEL, 1.f, enc, DMODEL, 0, wqkT, DMODEL, 0,
          qeke, 2 * WPD, 0, 1);

    // 14. edge scores -> segment sum
    edge_k<<<(NEDGE + 7) / 8, 256>>>(qeke, arows, acols, avals, Araw);

    // 15. alpha = softmax(A_raw)
    softmax_all_k<<<1, 1024>>>(Araw, alpha, NTOK);

    // 16. value = dense @ wv_w^T
    gemmH(NTOK, DMODEL, DMODEL, 1.f, dense, DMODEL, 0, wv_w, DMODEL, 0,
          val, DMODEL, 0, 1);

    // 17. final gated blend + A_raw copy
    final_k<<<(int)(((long)NTOK * DMODEL + 255) / 256), 256>>>(val, wv_b, alpha, enc, Araw, out);
}

// round 16
// speedup vs baseline: 1.9633x; 1.0221x over previous
#include <cuda_runtime.h>
#include <cuda_fp16.h>
#include <math.h>

// ---------------- problem constants ----------------
static const int NTOK   = 8192;   // N
static const int DMODEL = 512;    // D
static const int NHEADS = 8;
static const int DHEAD  = 64;
static const int MLAND  = 256;    // M landmarks
static const int LFOLD  = 32;     // N / M
static const int WPD    = 256;    // weight_params_dim
static const int NEDGE  = 262144; // E
static const int KCONV  = 33;
static const int QKVW   = 3 * NHEADS * DHEAD; // 1536
static const int PITERS = 6;

// ---------------- device scratch (BSS) ----------------
__device__ float g_qkv [NTOK * QKVW];
__device__ float g_ql  [NHEADS * MLAND * DHEAD];
__device__ float g_kl  [NHEADS * MLAND * DHEAD];
__device__ float g_a1  [(long)NHEADS * NTOK * MLAND];
__device__ float g_a2  [NHEADS * MLAND * MLAND];
__device__ float g_a3  [(long)NHEADS * MLAND * NTOK];
__device__ float g_z   [NHEADS * MLAND * MLAND];
__device__ float g_zT  [NHEADS * MLAND * MLAND];
__device__ float g_z2  [NHEADS * MLAND * MLAND];
__device__ float g_z2T [NHEADS * MLAND * MLAND];
__device__ float g_xz  [NHEADS * MLAND * MLAND];
__device__ float g_t1  [NHEADS * MLAND * MLAND];
__device__ float g_t1T [NHEADS * MLAND * MLAND];
__device__ float g_t2  [NHEADS * MLAND * MLAND];
__device__ float g_t2T [NHEADS * MLAND * MLAND];
__device__ float g_a3v [NHEADS * MLAND * DHEAD];
__device__ float g_zv  [NHEADS * MLAND * DHEAD];
__device__ float g_xh  [NTOK * DMODEL];
__device__ float g_enc [NTOK * DMODEL];
__device__ float g_val [NTOK * DMODEL];
__device__ float g_qeke [NTOK * 2 * WPD];
__device__ float g_wqkT [2 * WPD * DMODEL];
__device__ float g_rs1 [NHEADS * NTOK];   // a1 exp row sums
__device__ float g_rs3 [NHEADS * MLAND];  // a3 exp row sums
__device__ float g_Araw [NTOK];
__device__ float g_alpha[NTOK];
__device__ unsigned int g_norm[2];

// ---------------- ptx helpers ----------------
__device__ __forceinline__ unsigned sptr(const void* p) {
    return (unsigned)__cvta_generic_to_shared(p);
}
__device__ __forceinline__ void ldsm4(unsigned& r0, unsigned& r1, unsigned& r2,
                                      unsigned& r3, unsigned addr) {
    asm volatile("ldmatrix.sync.aligned.m8n8.x4.shared.b16 {%0,%1,%2,%3}, [%4];"
        : "=r"(r0), "=r"(r1), "=r"(r2), "=r"(r3) : "r"(addr));
}
__device__ __forceinline__ void mma16(float* c, const unsigned* a, const unsigned* b) {
    asm volatile(
        "mma.sync.aligned.m16n8k16.row.col.f32.f16.f16.f32 "
        "{%0,%1,%2,%3}, {%4,%5,%6,%7}, {%8,%9}, {%0,%1,%2,%3};"
        : "+f"(c[0]), "+f"(c[1]), "+f"(c[2]), "+f"(c[3])
        : "r"(a[0]), "r"(a[1]), "r"(a[2]), "r"(a[3]), "r"(b[0]), "r"(b[1]));
}

// split 8 fp32 -> 8 f16 hi-plane + 8 f16 residual-plane (packed uint4 each)
__device__ __forceinline__ void packsplit8(const float4& v0, const float4& v1,
                                           uint4& h, uint4& r)
{
    float v[8];
    *(float4*)v       = v0;
    *(float4*)(v + 4) = v1;
    unsigned hh[4], rr[4];
    #pragma unroll
    for (int i = 0; i < 4; i++) {
        __half2 p = __floats2half2_rn(v[2 * i], v[2 * i + 1]);
        hh[i] = *(unsigned*)&p;
        float lo = __half2float(__low2half(p));
        float hi = __half2float(__high2half(p));
        __half2 q = __floats2half2_rn(v[2 * i] - lo, v[2 * i + 1] - hi);
        rr[i] = *(unsigned*)&q;
    }
    h = make_uint4(hh[0], hh[1], hh[2], hh[3]);
    r = make_uint4(rr[0], rr[1], rr[2], rr[3]);
}

// =====================================================================
// gemmH: fp16x2 tensor GEMM (h/r split, 3 passes of m16n8k16).
// C = alpha * A[M,K] @ B^T (+addC +bias); optional exp epilogue with
// per-row sums (atomicAdd). B stored [N,K] (TB form).
// CTA tile 128x128, 128 threads = 4 warps, warp tile 64x64.  (measured)
// =====================================================================
static const int HROWB  = 48;
static const int HPLANE = 128 * HROWB;   // 6144 B
static const int HBUF   = 4 * HPLANE;    // 24576 B
__global__ __launch_bounds__(128, 2)
void gemmH_k(int M, int N, int K, float alpha,
             const float* __restrict__ A, int lda, long sA,
             const float* __restrict__ B, int ldb, long sB,
             float* __restrict__ C, int ldc, long sC,
             const float* __restrict__ addC, const float* __restrict__ bias,
             int doExp, float* __restrict__ rowsum)
{
    __shared__ __align__(16) char smem[2 * HBUF];

    A += (long)blockIdx.z * sA;
    B += (long)blockIdx.z * sB;
    C += (long)blockIdx.z * sC;
    if (addC)   addC   += (long)blockIdx.z * sC;
    if (rowsum) rowsum += (long)blockIdx.z * M;

    const int row0 = blockIdx.y * 128;
    const int col0 = blockIdx.x * 128;
    const int tid  = threadIdx.x;
    const int lane = tid & 31, w = tid >> 5, wr = w >> 1, wc = w & 1;

    const float* aSrc = A + (long)(row0 + tid) * lda;
    const float* bSrc = B + (long)(col0 + tid) * ldb;

    const unsigned offA = tid * HROWB;
    const unsigned offB = 2 * HPLANE + tid * HROWB;

    unsigned aLd[4];
    #pragma unroll
    for (int rt = 0; rt < 4; rt++) {
        int rrow = wr * 64 + rt * 16 + (lane & 15);
        aLd[rt] = sptr(smem + rrow * HROWB + (lane >> 4) * 16);
    }
    unsigned bLd[4];
    #pragma unroll
    for (int p = 0; p < 4; p++) {
        int n = wc * 64 + p * 16 + (lane & 7) + ((lane & 16) >> 1);
        bLd[p] = sptr(smem + 2 * HPLANE + n * HROWB + ((lane >> 3) & 1) * 16);
    }

    float acc[4][8][4];
    #pragma unroll
    for (int i = 0; i < 4; i++)
        #pragma unroll
        for (int j = 0; j < 8; j++)
            #pragma unroll
            for (int v = 0; v < 4; v++) acc[i][j][v] = 0.f;

    const int CH = K >> 4;
    float4 pa0, pa1, pa2, pa3, pb0, pb1, pb2, pb3;
    auto loadRegs = [&](int c) {
        const float* a = aSrc + c * 16;
        const float* b = bSrc + c * 16;
        pa0 = *(const float4*)(a);      pa1 = *(const float4*)(a + 4);
        pa2 = *(const float4*)(a + 8);  pa3 = *(const float4*)(a + 12);
        pb0 = *(const float4*)(b);      pb1 = *(const float4*)(b + 4);
        pb2 = *(const float4*)(b + 8);  pb3 = *(const float4*)(b + 12);
    };
    auto stsAll = [&](int b) {
        unsigned off = b * HBUF;
        uint4 h, r;
        packsplit8(pa0, pa1, h, r);
        *(uint4*)(smem + offA + off)               = h;
        *(uint4*)(smem + offA + off + HPLANE)      = r;
        packsplit8(pa2, pa3, h, r);
        *(uint4*)(smem + offA + off + 16)          = h;
        *(uint4*)(smem + offA + off + HPLANE + 16) = r;
        packsplit8(pb0, pb1, h, r);
        *(uint4*)(smem + offB + off)               = h;
        *(uint4*)(smem + offB + off + HPLANE)      = r;
        packsplit8(pb2, pb3, h, r);
        *(uint4*)(smem + offB + off + 16)          = h;
        *(uint4*)(smem + offB + off + HPLANE + 16) = r;
    };

    loadRegs(0);
    for (int c = 0; c < CH; c++) {
        int b = c & 1;
        stsAll(b);
        if (c + 1 < CH) loadRegs(c + 1);
        __syncthreads();
        unsigned off = b * HBUF;
        unsigned ah[4][4], ar[4][4];
        #pragma unroll
        for (int rt = 0; rt < 4; rt++) {
            ldsm4(ah[rt][0], ah[rt][1], ah[rt][2], ah[rt][3], aLd[rt] + off);
            ldsm4(ar[rt][0], ar[rt][1], ar[rt][2], ar[rt][3],
                  aLd[rt] + off + HPLANE);
        }
        #pragma unroll
        for (int p = 0; p < 4; p++) {
            unsigned bh[4], br[4];
            ldsm4(bh[0], bh[1], bh[2], bh[3], bLd[p] + off);
            ldsm4(br[0], br[1], br[2], br[3], bLd[p] + off + HPLANE);
            #pragma unroll
            for (int rt = 0; rt < 4; rt++) {
                mma16(acc[rt][2 * p],     ah[rt], bh);
                mma16(acc[rt][2 * p],     ah[rt], br);
                mma16(acc[rt][2 * p],     ar[rt], bh);
                mma16(acc[rt][2 * p + 1], ah[rt], bh + 2);
                mma16(acc[rt][2 * p + 1], ah[rt], br + 2);
                mma16(acc[rt][2 * p + 1], ar[rt], bh + 2);
            }
        }
    }

    const int g = lane >> 2, tg = lane & 3;
    #pragma unroll
    for (int rt = 0; rt < 4; rt++) {
        float rsum0 = 0.f, rsum1 = 0.f;
        #pragma unroll
        for (int n2 = 0; n2 < 8; n2++) {
            int gr = row0 + wr * 64 + rt * 16 + g;
            int gc = col0 + wc * 64 + n2 * 8 + tg * 2;
            float* c = acc[rt][n2];
            long i0 = (long)gr * ldc + gc;
            long i1 = i0 + 8 * (long)ldc;
            float v00 = alpha * c[0], v01 = alpha * c[1];
            float v10 = alpha * c[2], v11 = alpha * c[3];
            if (addC) {
                v00 += addC[i0]; v01 += addC[i0 + 1];
                v10 += addC[i1]; v11 += addC[i1 + 1];
            }
            if (bias) {
                v00 += bias[gc]; v01 += bias[gc + 1];
                v10 += bias[gc]; v11 += bias[gc + 1];
            }
            if (doExp) {
                v00 = __expf(v00); v01 = __expf(v01);
                v10 = __expf(v10); v11 = __expf(v11);
            }
            C[i0] = v00; C[i0 + 1] = v01;
            C[i1] = v10; C[i1 + 1] = v11;
            rsum0 += v00 + v01;
            rsum1 += v10 + v11;
        }
        if (rowsum) {
            rsum0 += __shfl_xor_sync(0xffffffffu, rsum0, 1);
            rsum0 += __shfl_xor_sync(0xffffffffu, rsum0, 2);
            rsum1 += __shfl_xor_sync(0xffffffffu, rsum1, 1);
            rsum1 += __shfl_xor_sync(0xffffffffu, rsum1, 2);
            if (tg == 0) {
                int gr = row0 + wr * 64 + rt * 16 + g;
                atomicAdd(&rowsum[gr], rsum0);
                atomicAdd(&rowsum[gr + 8], rsum1);
            }
        }
    }
}

static void gemmH(int M, int N, int K, float alpha,
                  const float* A, int lda, long sA,
                  const float* B, int ldb, long sB,
                  float* C, int ldc, long sC, int batch,
                  const float* addC = nullptr, const float* bias = nullptr,
                  int doExp = 0, float* rowsum = nullptr)
{
    dim3 g(N / 128, M / 128, batch);
    gemmH_k<<<g, 128>>>(M, N, K, alpha, A, lda, sA, B, ldb, sB,
                        C, ldc, sC, addC, bias, doExp, rowsum);
}

// =====================================================================
// gemmH64: fp16x2 GEMM, CTA tile 128x64, NT form (B = [K,N] row-major).
// Optional per-B-row divide by brs[row] (folded softmax normalization).
// 128 threads = 4 warps (4x1), warp tile 32x64. Optional split-K atomic.
// =====================================================================
static const int QROWB   = 48;
static const int QAPLANE = 128 * QROWB;
static const int QBPLANE = 64 * QROWB;
static const int QBUF    = 2 * QAPLANE + 2 * QBPLANE;
__global__ __launch_bounds__(128, 3)
void gemmH64_k(int M, int K, float alpha,
               const float* __restrict__ A, int lda, long sA,
               const float* __restrict__ B, int ldb, long sB,
               float* __restrict__ C, int ldc, long sC, int kSplit,
               const float* __restrict__ brs)
{
    __shared__ __align__(16) char smem[2 * QBUF];

    int bz = blockIdx.z;
    int batch = bz / kSplit, ks = bz - batch * kSplit;
    A += (long)batch * sA; B += (long)batch * sB; C += (long)batch * sC;
    const int chunk = K / kSplit;
    const int k0s = ks * chunk;
    const int CH = chunk >> 4;

    const int row0 = blockIdx.y * 128;
    const int tid  = threadIdx.x;
    const int lane = tid & 31, w = tid >> 5;

    const float* aSrc = A + (long)(row0 + tid) * lda + k0s;
    const unsigned offA = tid * QROWB;
    const int bn = tid & 63, bkh = (tid >> 6) * 8;
    const float* bSrc = B + (long)(k0s + bkh) * ldb + bn;
    const float* brsRow = brs ? (brs + (long)batch * K + k0s + bkh) : nullptr;
    const unsigned offB = 2 * QAPLANE + bn * QROWB + bkh * 2;

    unsigned aLd[2];
    #pragma unroll
    for (int rt = 0; rt < 2; rt++) {
        int rrow = w * 32 + rt * 16 + (lane & 15);
        aLd[rt] = sptr(smem + rrow * QROWB + (lane >> 4) * 16);
    }
    unsigned bLd[4];
    #pragma unroll
    for (int p = 0; p < 4; p++) {
        int n = p * 16 + (lane & 7) + ((lane & 16) >> 1);
        bLd[p] = sptr(smem + 2 * QAPLANE + n * QROWB + ((lane >> 3) & 1) * 16);
    }

    float acc[2][8][4];
    #pragma unroll
    for (int i = 0; i < 2; i++)
        #pragma unroll
        for (int j = 0; j < 8; j++)
            #pragma unroll
            for (int v = 0; v < 4; v++) acc[i][j][v] = 0.f;

    float4 pa0, pa1, pa2, pa3;
    float vb[8];
    auto loadRegs = [&](int c) {
        const float* a = aSrc + c * 16;
        pa0 = *(const float4*)(a);      pa1 = *(const float4*)(a + 4);
        pa2 = *(const float4*)(a + 8);  pa3 = *(const float4*)(a + 12);
        const float* b = bSrc + (long)c * 16 * ldb;
        #pragma unroll
        for (int j = 0; j < 8; j++) vb[j] = b[(long)j * ldb];
        if (brsRow) {
            const float* s = brsRow + c * 16;
            #pragma unroll
            for (int j = 0; j < 8; j++) vb[j] /= s[j];
        }
    };
    auto stsAll = [&](int b) {
        unsigned off = b * QBUF;
        uint4 h, r;
        packsplit8(pa0, pa1, h, r);
        *(uint4*)(smem + offA + off)                = h;
        *(uint4*)(smem + offA + off + QAPLANE)      = r;
        packsplit8(pa2, pa3, h, r);
        *(uint4*)(smem + offA + off + 16)           = h;
        *(uint4*)(smem + offA + off + QAPLANE + 16) = r;
        packsplit8(make_float4(vb[0], vb[1], vb[2], vb[3]),
                   make_float4(vb[4], vb[5], vb[6], vb[7]), h, r);
        *(uint4*)(smem + offB + off)                = h;
        *(uint4*)(smem + offB + off + QBPLANE)      = r;
    };

    loadRegs(0);
    for (int c = 0; c < CH; c++) {
        int b = c & 1;
        stsAll(b);
        if (c + 1 < CH) loadRegs(c + 1);
        __syncthreads();
        unsigned off = b * QBUF;
        unsigned ah[2][4], ar[2][4];
        #pragma unroll
        for (int rt = 0; rt < 2; rt++) {
            ldsm4(ah[rt][0], ah[rt][1], ah[rt][2], ah[rt][3], aLd[rt] + off);
            ldsm4(ar[rt][0], ar[rt][1], ar[rt][2], ar[rt][3],
                  aLd[rt] + off + QAPLANE);
        }
        #pragma unroll
        for (int p = 0; p < 4; p++) {
            unsigned bh[4], br[4];
            ldsm4(bh[0], bh[1], bh[2], bh[3], bLd[p] + off);
            ldsm4(br[0], br[1], br[2], br[3], bLd[p] + off + QBPLANE);
            #pragma unroll
            for (int rt = 0; rt < 2; rt++) {
                mma16(acc[rt][2 * p],     ah[rt], bh);
                mma16(acc[rt][2 * p],     ah[rt], br);
                mma16(acc[rt][2 * p],     ar[rt], bh);
                mma16(acc[rt][2 * p + 1], ah[rt], bh + 2);
                mma16(acc[rt][2 * p + 1], ah[rt], br + 2);
                mma16(acc[rt][2 * p + 1], ar[rt], bh + 2);
            }
        }
    }

    const int g = lane >> 2, tg = lane & 3;
    #pragma unroll
    for (int rt = 0; rt < 2; rt++) {
        #pragma unroll
        for (int n2 = 0; n2 < 8; n2++) {
            int gr = row0 + w * 32 + rt * 16 + g;
            int gc = n2 * 8 + tg * 2;
            float* c = acc[rt][n2];
            float* p0 = C + (long)gr * ldc + gc;
            float* p1 = p0 + 8 * (long)ldc;
            if (kSplit > 1) {
                atomicAdd(p0 + 0, alpha * c[0]); atomicAdd(p0 + 1, alpha * c[1]);
                atomicAdd(p1 + 0, alpha * c[2]); atomicAdd(p1 + 1, alpha * c[3]);
            } else {
                p0[0] = alpha * c[0]; p0[1] = alpha * c[1];
                p1[0] = alpha * c[2]; p1[1] = alpha * c[3];
            }
        }
    }
}

static void gemmH64(int M, int K, float alpha,
                    const float* A, int lda, long sA,
                    const float* B, int ldb, long sB,
                    float* C, int ldc, long sC, int batch, int kSplit,
                    const float* brs = nullptr)
{
    dim3 g(1, M / 128, batch * kSplit);
    gemmH64_k<<<g, 128>>>(M, K, alpha, A, lda, sA, B, ldb, sB,
                          C, ldc, sC, kSplit, brs);
}

// =====================================================================
// gemmHP: fp16x2 pinv GEMM (R13, measured). 64x64 CTA, batched 256x256.
// =====================================================================
static const int PROWB  = 48;
static const int PPLANE = 64 * PROWB;
static const int PBUF   = 4 * PPLANE;
__global__ __launch_bounds__(128, 3)
void gemmHP_k(float alpha, float diag,
              const float* __restrict__ A, const float* __restrict__ B,
              float* __restrict__ C, float* __restrict__ CT,
              float alpha2, float diag2,
              float* __restrict__ C2, float* __restrict__ C2T)
{
    __shared__ __align__(16) char smem[2 * PBUF];

    const long sb = (long)MLAND * MLAND;
    A += blockIdx.z * sb; B += blockIdx.z * sb; C += blockIdx.z * sb;
    if (CT)  CT  += blockIdx.z * sb;
    if (C2)  C2  += blockIdx.z * sb;
    if (C2T) C2T += blockIdx.z * sb;

    const int row0 = blockIdx.y * 64;
    const int col0 = blockIdx.x * 64;
    const int tid  = threadIdx.x;
    const int lane = tid & 31, w = tid >> 5, wr = w >> 1, wc = w & 1;

    const int  sr    = tid & 63;
    const bool isB   = tid >= 64;
    const float* src = isB ? (B + (long)(col0 + sr) * MLAND)
                           : (A + (long)(row0 + sr) * MLAND);
    const unsigned stOff = (isB ? 2 * PPLANE : 0) + sr * PROWB;

    unsigned aLd[2];
    #pragma unroll
    for (int rt = 0; rt < 2; rt++) {
        int rrow = wr * 32 + rt * 16 + (lane & 15);
        aLd[rt] = sptr(smem + rrow * PROWB + (lane >> 4) * 16);
    }
    unsigned bLd[2];
    #pragma unroll
    for (int p = 0; p < 2; p++) {
        int n = wc * 32 + p * 16 + (lane & 7) + ((lane & 16) >> 1);
        bLd[p] = sptr(smem + 2 * PPLANE + n * PROWB + ((lane >> 3) & 1) * 16);
    }

    float acc[2][4][4];
    #pragma unroll
    for (int i = 0; i < 2; i++)
        #pragma unroll
        for (int j = 0; j < 4; j++)
            #pragma unroll
            for (int v = 0; v < 4; v++) acc[i][j][v] = 0.f;

    const int CH = MLAND >> 4;
    float4 p0, p1, p2, p3;
    auto loadRegs = [&](int c) {
        const float* s = src + c * 16;
        p0 = *(const float4*)(s);     p1 = *(const float4*)(s + 4);
        p2 = *(const float4*)(s + 8); p3 = *(const float4*)(s + 12);
    };
    auto stsAll = [&](int b) {
        unsigned off = b * PBUF + stOff;
        uint4 h, r;
        packsplit8(p0, p1, h, r);
        *(uint4*)(smem + off)               = h;
        *(uint4*)(smem + off + PPLANE)      = r;
        packsplit8(p2, p3, h, r);
        *(uint4*)(smem + off + 16)          = h;
        *(uint4*)(smem + off + PPLANE + 16) = r;
    };

    loadRegs(0);
    for (int c = 0; c < CH; c++) {
        int b = c & 1;
        stsAll(b);
        if (c + 1 < CH) loadRegs(c + 1);
        __syncthreads();
        unsigned off = b * PBUF;
        unsigned ah[2][4], ar[2][4];
        #pragma unroll
        for (int rt = 0; rt < 2; rt++) {
            ldsm4(ah[rt][0], ah[rt][1], ah[rt][2], ah[rt][3], aLd[rt] + off);
            ldsm4(ar[rt][0], ar[rt][1], ar[rt][2], ar[rt][3],
                  aLd[rt] + off + PPLANE);
        }
        #pragma unroll
        for (int p = 0; p < 2; p++) {
            unsigned bh[4], br[4];
            ldsm4(bh[0], bh[1], bh[2], bh[3], bLd[p] + off);
            ldsm4(br[0], br[1], br[2], br[3], bLd[p] + off + PPLANE);
            #pragma unroll
            for (int rt = 0; rt < 2; rt++) {
                mma16(acc[rt][2 * p],     ah[rt], bh);
                mma16(acc[rt][2 * p],     ah[rt], br);
                mma16(acc[rt][2 * p],     ar[rt], bh);
                mma16(acc[rt][2 * p + 1], ah[rt], bh + 2);
                mma16(acc[rt][2 * p + 1], ah[rt], br + 2);
                mma16(acc[rt][2 * p + 1], ar[rt], bh + 2);
            }
        }
    }

    const int g = lane >> 2, tg = lane & 3;
    #pragma unroll
    for (int rt = 0; rt < 2; rt++) {
        #pragma unroll
        for (int n2 = 0; n2 < 4; n2++) {
            int gr = row0 + wr * 32 + rt * 16 + g;
            int gc = col0 + wc * 32 + n2 * 8 + tg * 2;
            float* c = acc[rt][n2];
            float d00 = (gr == gc) ? 1.f : 0.f;
            float d01 = (gr == gc + 1) ? 1.f : 0.f;
            float d10 = (gr + 8 == gc) ? 1.f : 0.f;
            float d11 = (gr + 8 == gc + 1) ? 1.f : 0.f;
            float v00 = alpha * c[0] + diag * d00;
            float v01 = alpha * c[1] + diag * d01;
            float v10 = alpha * c[2] + diag * d10;
            float v11 = alpha * c[3] + diag * d11;
            long i0 = (long)gr * MLAND + gc;
            long i1 = i0 + 8 * MLAND;
            C[i0] = v00; C[i0 + 1] = v01;
            C[i1] = v10; C[i1 + 1] = v11;
            if (CT) {
                CT[(long)gc * MLAND + gr]           = v00;
                CT[(long)(gc + 1) * MLAND + gr]     = v01;
                CT[(long)gc * MLAND + gr + 8]       = v10;
                CT[(long)(gc + 1) * MLAND + gr + 8] = v11;
            }
            if (C2) {
                float w00 = alpha2 * c[0] + diag2 * d00;
                float w01 = alpha2 * c[1] + diag2 * d01;
                float w10 = alpha2 * c[2] + diag2 * d10;
                float w11 = alpha2 * c[3] + diag2 * d11;
                C2[i0] = w00; C2[i0 + 1] = w01;
                C2[i1] = w10; C2[i1 + 1] = w11;
                if (C2T) {
                    C2T[(long)gc * MLAND + gr]           = w00;
                    C2T[(long)(gc + 1) * MLAND + gr]     = w01;
                    C2T[(long)gc * MLAND + gr + 8]       = w10;
                    C2T[(long)(gc + 1) * MLAND + gr + 8] = w11;
                }
            }
        }
    }
}

// ---------------- small kernels ----------------
__global__ void transpose_k(const float* __restrict__ S, float* __restrict__ D,
                            int R, int C)
{
    __shared__ float t[32][33];
    int r0 = blockIdx.y * 32, c0 = blockIdx.x * 32;
    int x = threadIdx.x, y0 = threadIdx.y;
    #pragma unroll
    for (int i = y0; i < 32; i += 8)
        t[i][x] = S[(long)(r0 + i) * C + c0 + x];
    __syncthreads();
    #pragma unroll
    for (int i = y0; i < 32; i += 8)
        D[(long)(c0 + i) * R + r0 + x] = t[x][i];
}

__global__ void zeros_k(float* a3v, float* Araw, unsigned int* norm,
                        float* rs1, float* rs3)
{
    long i = (long)blockIdx.x * 256 + threadIdx.x;
    if (i < NHEADS * MLAND * DHEAD) a3v[i] = 0.f;
    if (i < NTOK) Araw[i] = 0.f;
    if (i < 2) norm[i] = 0u;
    if (i < (long)NHEADS * NTOK) rs1[i] = 0.f;
    if (i < NHEADS * MLAND) rs3[i] = 0.f;
}

__global__ void landmarks_k(const float* __restrict__ qkv,
                            float* __restrict__ ql, float* __restrict__ kl)
{
    int idx = blockIdx.x * blockDim.x + threadIdx.x;
    if (idx >= NHEADS * MLAND * DHEAD) return;
    int d = idx & 63; int j = (idx >> 6) & 255; int h = idx >> 14;
    const float* qp = qkv + (long)(j * LFOLD) * QKVW + h * DHEAD + d;
    const float* kp = qp + NHEADS * DHEAD;
    float sq = 0.f, sk = 0.f;
    #pragma unroll 4
    for (int t = 0; t < LFOLD; t++) {
        sq += qp[(long)t * QKVW];
        sk += kp[(long)t * QKVW];
    }
    ql[idx] = sq * (1.f / LFOLD);
    kl[idx] = sk * (1.f / LFOLD);
}

__global__ __launch_bounds__(256)
void softmax256_k(float* __restrict__ X)
{
    float* x = X + (long)blockIdx.x * 256;
    int tid = threadIdx.x;
    __shared__ float sm[8];
    float v = x[tid];
    float m = v;
    #pragma unroll
    for (int o = 16; o; o >>= 1) m = fmaxf(m, __shfl_xor_sync(0xffffffffu, m, o));
    if ((tid & 31) == 0) sm[tid >> 5] = m;
    __syncthreads();
    m = sm[0];
    #pragma unroll
    for (int i = 1; i < 8; i++) m = fmaxf(m, sm[i]);
    float e = __expf(v - m);
    float s = e;
    #pragma unroll
    for (int o = 16; o; o >>= 1) s += __shfl_xor_sync(0xffffffffu, s, o);
    __syncthreads();
    if ((tid & 31) == 0) sm[tid >> 5] = s;
    __syncthreads();
    s = sm[0];
    #pragma unroll
    for (int i = 1; i < 8; i++) s += sm[i];
    x[tid] = e * (1.f / s);
}

__global__ void a2norm_k(const float* __restrict__ a2, unsigned int* norm)
{
    int h = blockIdx.x; int t = threadIdx.x;
    const float* x = a2 + (long)h * MLAND * MLAND;
    float rs = 0.f, cs = 0.f;
    for (int j = 0; j < MLAND; j++) {
        rs += fabsf(x[t * MLAND + j]);
        cs += fabsf(x[j * MLAND + t]);
    }
    __shared__ float s1[8], s2[8];
    for (int o = 16; o; o >>= 1) {
        rs = fmaxf(rs, __shfl_xor_sync(0xffffffffu, rs, o));
        cs = fmaxf(cs, __shfl_xor_sync(0xffffffffu, cs, o));
    }
    if ((t & 31) == 0) { s1[t >> 5] = rs; s2[t >> 5] = cs; }
    __syncthreads();
    if (t == 0) {
        rs = s1[0]; cs = s2[0];
        for (int w = 1; w < 8; w++) { rs = fmaxf(rs, s1[w]); cs = fmaxf(cs, s2[w]); }
        atomicMax(&norm[0], __float_as_uint(rs));
        atomicMax(&norm[1], __float_as_uint(cs));
    }
}

// writes z = a2^T * inv  AND  zT = a2 * inv
__global__ void zinit2_k(const float* __restrict__ a2, float* __restrict__ z,
                         float* __restrict__ zT,
                         const unsigned int* __restrict__ norm)
{
    long idx = (long)blockIdx.x * 256 + threadIdx.x;
    if (idx >= (long)NHEADS * MLAND * MLAND) return;
    float inv = 1.f / (__uint_as_float(norm[0]) * __uint_as_float(norm[1]));
    int j = idx & 255; int i = (idx >> 8) & 255; long h = idx >> 16;
    z[idx]  = a2[h * 65536 + (long)j * 256 + i] * inv;
    zT[idx] = a2[idx] * inv;
}

// conv + fold 1/rowsum(a1) into xh:  xh = xh*inv + conv(v)
__global__ __launch_bounds__(256)
void convadd2_k(const float* __restrict__ qkv,
                const float* __restrict__ rker,
                float* __restrict__ xh,
                const float* __restrict__ rs1)
{
    __shared__ float skr[NHEADS * KCONV];
    for (int i = threadIdx.x; i < NHEADS * KCONV; i += 256) skr[i] = rker[i];
    __syncthreads();
    int idx = blockIdx.x * 256 + threadIdx.x;
    int col = idx & 511;
    int ng = idx >> 9;
    if (ng >= NTOK / 8) return;
    long n0 = (long)ng * 8;
    int h = col >> 6;
    const float* kr = skr + h * KCONV;
    const float* v = qkv + 2 * NHEADS * DHEAD + col;
    const float* rsb = rs1 + (long)h * NTOK;
    float win[40];
    #pragma unroll
    for (int j = 0; j < 40; j++) {
        long r = n0 - 16 + j;
        win[j] = (r >= 0 && r < NTOK) ? v[r * QKVW] : 0.f;
    }
    #pragma unroll
    for (int i = 0; i < 8; i++) {
        float s = 0.f;
        #pragma unroll
        for (int t = 0; t < KCONV; t++) s += kr[t] * win[i + t];
        long o = (n0 + i) * DMODEL + col;
        xh[o] = xh[o] / rsb[n0 + i] + s;
    }
}

__global__ void edge_k(const float* __restrict__ qeke,
                       const int* __restrict__ rows, const int* __restrict__ cols,
                       const float* __restrict__ vals, float* __restrict__ Araw)
{
    int e = blockIdx.x * (blockDim.x >> 5) + (threadIdx.x >> 5);
    int lane = threadIdx.x & 31;
    if (e >= NEDGE) return;
    int r = rows[e], c = cols[e];
    const float4* qr = (const float4*)(qeke + (long)r * 512);
    const float4* kc = (const float4*)(qeke + (long)c * 512 + WPD);
    float s = 0.f;
    #pragma unroll
    for (int i = lane; i < WPD / 4; i += 32) {
        float4 a = qr[i], b = kc[i];
        s += a.x * b.x + a.y * b.y + a.z * b.z + a.w * b.w;
    }
    for (int o = 16; o; o >>= 1) s += __shfl_xor_sync(0xffffffffu, s, o);
    if (lane == 0) atomicAdd(&Araw[r], s * 0.0625f * vals[e]);
}

__global__ void softmax_all_k(const float* __restrict__ A, float* __restrict__ alpha, int n)
{
    __shared__ float sm[32];
    int tid = threadIdx.x;
    float m = -1e30f;
    for (int i = tid; i < n; i += 1024) m = fmaxf(m, A[i]);
    for (int o = 16; o; o >>= 1) m = fmaxf(m, __shfl_xor_sync(0xffffffffu, m, o));
    if ((tid & 31) == 0) sm[tid >> 5] = m;
    __syncthreads();
    if (tid == 0) { float bm = sm[0]; for (int w = 1; w < 32; w++) bm = fmaxf(bm, sm[w]); sm[0] = bm; }
    __syncthreads();
    m = sm[0];
    __syncthreads();
    float s = 0.f;
    for (int i = tid; i < n; i += 1024) s += __expf(A[i] - m);
    for (int o = 16; o; o >>= 1) s += __shfl_xor_sync(0xffffffffu, s, o);
    if ((tid & 31) == 0) sm[tid >> 5] = s;
    __syncthreads();
    if (tid == 0) { float bs = 0.f; for (int w = 0; w < 32; w++) bs += sm[w]; sm[0] = bs; }
    __syncthreads();
    float inv = 1.f / sm[0];
    for (int i = tid; i < n; i += 1024) alpha[i] = __expf(A[i] - m) * inv;
}

__global__ void final_k(const float* __restrict__ val, const float* __restrict__ wvb,
                        const float* __restrict__ alpha, const float* __restrict__ enc,
                        const float* __restrict__ Araw, float* __restrict__ out)
{
    long idx = (long)blockIdx.x * 256 + threadIdx.x;
    long total = (long)NTOK * DMODEL;
    if (idx < total) {
        int col = idx & 511; long n = idx >> 9;
        float v = val[idx] + wvb[col];
        float xl = alpha[n] * v;
        float w = 1.f / (1.f + __expf(xl));
        float sq = w * w;
        float e = enc[idx];
        out[idx] = xl * 2.f * sq + 2.f * e * (1.f - sq);
    }
    if (idx < NTOK) out[total + idx] = Araw[idx];
}

// ---------------- driver ----------------
extern "C" void kernel_launch(void* const* d_in, const int* in_sizes, int n_in,
                              void* d_out, int out_size)
{
    const float* dense  = (const float*)d_in[0];
    const int*   arows  = (const int*)  d_in[1];
    const int*   acols  = (const int*)  d_in[2];
    const float* avals  = (const float*)d_in[3];
    const float* wq     = (const float*)d_in[4];
    const float* wk     = (const float*)d_in[5];
    const float* w_qkv  = (const float*)d_in[6];
    const float* w_out  = (const float*)d_in[7];
    const float* b_out  = (const float*)d_in[8];
    const float* rker   = (const float*)d_in[9];
    const float* wv_w   = (const float*)d_in[10];
    const float* wv_b   = (const float*)d_in[11];
    float* out = (float*)d_out;

    float *qkv, *ql, *kl, *a1, *a2, *a3, *z, *zT, *z2, *z2T, *xz;
    float *t1, *t1T, *t2, *t2T, *a3v, *zv;
    float *xh, *enc, *val, *qeke, *wqkT, *rs1, *rs3, *Araw, *alpha;
    unsigned int* norm;
    cudaGetSymbolAddress((void**)&qkv, g_qkv);
    cudaGetSymbolAddress((void**)&ql,  g_ql);
    cudaGetSymbolAddress((void**)&kl,  g_kl);
    cudaGetSymbolAddress((void**)&a1,  g_a1);
    cudaGetSymbolAddress((void**)&a2,  g_a2);
    cudaGetSymbolAddress((void**)&a3,  g_a3);
    cudaGetSymbolAddress((void**)&z,   g_z);
    cudaGetSymbolAddress((void**)&zT,  g_zT);
    cudaGetSymbolAddress((void**)&z2,  g_z2);
    cudaGetSymbolAddress((void**)&z2T, g_z2T);
    cudaGetSymbolAddress((void**)&xz,  g_xz);
    cudaGetSymbolAddress((void**)&t1,  g_t1);
    cudaGetSymbolAddress((void**)&t1T, g_t1T);
    cudaGetSymbolAddress((void**)&t2,  g_t2);
    cudaGetSymbolAddress((void**)&t2T, g_t2T);
    cudaGetSymbolAddress((void**)&a3v, g_a3v);
    cudaGetSymbolAddress((void**)&zv,  g_zv);
    cudaGetSymbolAddress((void**)&xh,  g_xh);
    cudaGetSymbolAddress((void**)&enc, g_enc);
    cudaGetSymbolAddress((void**)&val, g_val);
    cudaGetSymbolAddress((void**)&qeke, g_qeke);
    cudaGetSymbolAddress((void**)&wqkT, g_wqkT);
    cudaGetSymbolAddress((void**)&rs1, g_rs1);
    cudaGetSymbolAddress((void**)&rs3, g_rs3);
    cudaGetSymbolAddress((void**)&Araw, g_Araw);
    cudaGetSymbolAddress((void**)&alpha, g_alpha);
    cudaGetSymbolAddress((void**)&norm, g_norm);

    const float qscale = 0.125f;
    const long  smm    = (long)MLAND * MLAND;

    // 0. zero scratch (grid MUST cover a3v: 131072 elems = 512 blocks)
    zeros_k<<<(NHEADS * MLAND * DHEAD + 255) / 256, 256>>>(a3v, Araw, norm, rs1, rs3);
    {
        dim3 b(32, 8);
        transpose_k<<<dim3(WPD / 32, DMODEL / 32), b>>>(wq, wqkT, DMODEL, WPD);
        transpose_k<<<dim3(WPD / 32, DMODEL / 32), b>>>(wk, wqkT + WPD * DMODEL,
                                                        DMODEL, WPD);
    }

    // 1. qkv = dense @ w_qkv^T  [8192,1536]
    gemmH(NTOK, QKVW, DMODEL, 1.f, dense, DMODEL, 0, w_qkv, DMODEL, 0,
          qkv, QKVW, 0, 1);

    // 2. landmarks
    landmarks_k<<<(NHEADS * MLAND * DHEAD + 255) / 256, 256>>>(qkv, ql, kl);

    // 3. a1 = exp(scale * q @ k_l^T) (unnormalized, rowsums -> rs1)
    gemmH(NTOK, MLAND, DHEAD, qscale,
          qkv, QKVW, DHEAD, kl, DHEAD, (long)MLAND * DHEAD,
          a1, MLAND, (long)NTOK * MLAND, NHEADS, nullptr, nullptr, 1, rs1);

    // 4. a2 = softmax(scale * q_l @ k_l^T) [h,256,256]
    gemmH(MLAND, MLAND, DHEAD, qscale,
          ql, DHEAD, (long)MLAND * DHEAD, kl, DHEAD, (long)MLAND * DHEAD,
          a2, MLAND, smm, NHEADS);
    softmax256_k<<<NHEADS * MLAND, 256>>>(a2);

    // 5. pinv init: z = a2^T/norm, zT = a2/norm
    a2norm_k<<<NHEADS, 256>>>(a2, norm);
    zinit2_k<<<(int)((NHEADS * smm + 255) / 256), 256>>>(a2, z, zT, norm);

    // 6. pinv iterations (fp16x2, fused diag + transposed outputs)
    float *zin = z, *zinT = zT, *zout = z2, *zoutT = z2T;
    dim3 gp(4, 4, NHEADS);
    for (int it = 0; it < PITERS; it++) {
        gemmHP_k<<<gp, 128>>>(1.f, 0.f, a2, zinT, xz, nullptr,
                              -1.f, 7.f, t1, t1T);
        gemmHP_k<<<gp, 128>>>(-1.f, 15.f, xz, t1T, t2, t2T,
                              0.f, 0.f, nullptr, nullptr);
        gemmHP_k<<<gp, 128>>>(-1.f, 13.f, xz, t2T, t1, t1T,
                              0.f, 0.f, nullptr, nullptr);
        gemmHP_k<<<gp, 128>>>(0.25f, 0.f, zin, t1T, zout, zoutT,
                              0.f, 0.f, nullptr, nullptr);
        float* tmp;
        tmp = zin;  zin = zout;   zout = tmp;
        tmp = zinT; zinT = zoutT; zoutT = tmp;
    }
    float* zfin = zin;

    // 7. a3 = exp(scale * q_l @ k^T) (unnormalized, rowsums -> rs3)
    gemmH(MLAND, NTOK, DHEAD, qscale,
          ql, DHEAD, (long)MLAND * DHEAD,
          qkv + NHEADS * DHEAD, QKVW, DHEAD,
          a3, NTOK, (long)MLAND * NTOK, NHEADS, nullptr, nullptr, 1, rs3);

    // 8. a3v = a3exp @ v  [h,256,64]  (split-K 16, atomic; pre-zeroed)
    gemmH64(MLAND, NTOK, 1.f,
            a3, NTOK, (long)MLAND * NTOK,
            qkv + 2 * NHEADS * DHEAD, QKVW, DHEAD,
            a3v, DHEAD, (long)MLAND * DHEAD, NHEADS, 16);

    // 9. zv = zfin @ (a3v rows / rs3)  [h,256,64]  (softmax norm folded)
    gemmH64(MLAND, MLAND, 1.f,
            zfin, MLAND, smm,
            a3v, DHEAD, (long)MLAND * DHEAD,
            zv, DHEAD, (long)MLAND * DHEAD, NHEADS, 1, rs3);

    // 10. xh_un = a1exp @ zv   (a1 norm folded into convadd2)
    gemmH64(NTOK, MLAND, 1.f,
            a1, MLAND, (long)NTOK * MLAND,
            zv, DHEAD, (long)MLAND * DHEAD,
            xh, DMODEL, DHEAD, NHEADS, 1);

    // 11. xh = xh/rs1 + depthwise conv(v)
    convadd2_k<<<(NTOK / 8) * DMODEL / 256, 256>>>(qkv, rker, xh, rs1);

    // 12. enc = xh @ w_out^T + b_out + dense  (fused epilogue)
    gemmH(NTOK, DMODEL, DMODEL, 1.f, xh, DMODEL, 0, w_out, DMODEL, 0,
          enc, DMODEL, 0, 1, dense, b_out);

    // 13. qeke = enc @ [wq|wk]  (single N=512 GEMM)
    gemmH(NTOK, 2 * WPD, DMODEL, 1.f, enc, DMODEL, 0, wqkT, DMODEL, 0,
          qeke, 2 * WPD, 0, 1);

    // 14. edge scores -> segment sum
    edge_k<<<(NEDGE + 7) / 8, 256>>>(qeke, arows, acols, avals, Araw);

    // 15. alpha = softmax(A_raw)
    softmax_all_k<<<1, 1024>>>(Araw, alpha, NTOK);

    // 16. value = dense @ wv_w^T
    gemmH(NTOK, DMODEL, DMODEL, 1.f, dense, DMODEL, 0, wv_w, DMODEL, 0,
          val, DMODEL, 0, 1);

    // 17. final gated blend + A_raw copy
    final_k<<<(int)(((long)NTOK * DMODEL + 255) / 256), 256>>>(val, wv_b, alpha, enc, Araw, out);
}